// round 11
// baseline (speedup 1.0000x reference)
#include <cuda_runtime.h>
#include <cuda_bf16.h>
#include <math_constants.h>
#include <cstdint>

#define BATCH 8
#define CH    192
#define HH    56
#define WW    56
#define NPIX  3136
#define KC    16
#define NBR   9
#define CO    384
#define NCAT  768
#define BN    (BATCH*NPIX)  // 25088
#define SMAX  384

// ---------------- scratch ----------------
__device__ __align__(128) float g_xa[BATCH*CH*NPIX];
__device__ __align__(128) __nv_bfloat16 g_xt_hi[BN*CH];
__device__ __align__(128) __nv_bfloat16 g_xt_lo[BN*CH];
__device__ __align__(128) float g_xf[BN*CH];            // fc1 out (UNSORTED rows)
__device__ __align__(128) __nv_bfloat16 g_xsh[BN*CH];   // sorted rows bf16
__device__ __align__(128) __nv_bfloat16 g_xe_hi[BN*CH];
__device__ __align__(128) __nv_bfloat16 g_xe_lo[BN*CH];
__device__ __align__(128) __nv_bfloat16 g_ABh[(size_t)BN*NCAT]; // [A | Bv] bf16 (sorted)
__device__ __align__(128) float g_S[(size_t)BATCH*KC*SMAX*SMAX];
__device__ __align__(128) __nv_bfloat16 g_hnh[BN*CO];   // aggregated, UNSORTED rows
__device__ int   g_order[BN];
__device__ int   g_ls[BN];
__device__ int   g_cstart[BATCH][KC+1];
__device__ int   g_nbr[BN*NBR];
__device__ __align__(128) float g_cen[BATCH*KC*CH];
__device__ __align__(128) float g_AcBc[BATCH*KC*NCAT];
__device__ __align__(128) float g_hc[BATCH*KC*CO];
__device__ __align__(128) float g_Wc2[CH*NCAT];
__device__ __align__(128) __nv_bfloat16 g_Wvt[NCAT*CH];
__device__ __align__(128) __nv_bfloat16 g_W2t[CH*CO];
__device__ __align__(128) __nv_bfloat16 g_W1t_hi[CH*CH];
__device__ __align__(128) __nv_bfloat16 g_W1t_lo[CH*CH];
__device__ __align__(128) float g_bias_cat[NCAT];
__device__ __align__(128) float g_bias_c2[NCAT];

__device__ __forceinline__ float gelu_f(float x) {
    float u = 0.7978845608028654f * (x + 0.044715f * x * x * x);
    float t;
    asm("tanh.approx.f32 %0, %1;" : "=f"(t) : "f"(u));
    return 0.5f * x * (1.0f + t);
}
// gelu is a valley function (decreasing then increasing, min near x=-0.75):
// max over a set = max(gelu(set-min), gelu(set-max)).
__device__ __forceinline__ float gelu_max2(float mn, float mx) {
    return fmaxf(gelu_f(mn), gelu_f(mx));
}
__device__ __forceinline__ void split_bf16(float v, __nv_bfloat16& hi, __nv_bfloat16& lo) {
    hi = __float2bfloat16(v);
    lo = __float2bfloat16(v - __bfloat162float(hi));
}
__device__ __forceinline__ void cp16(void* dst, const void* src) {
    uint32_t d = (uint32_t)__cvta_generic_to_shared(dst);
    asm volatile("cp.async.ca.shared.global [%0], [%1], 16;\n" :: "r"(d), "l"(src));
}
__device__ __forceinline__ uint32_t smaddr(const void* p) {
    return (uint32_t)__cvta_generic_to_shared(p);
}
#define CP_COMMIT() asm volatile("cp.async.commit_group;\n")
#define CP_WAIT1()  asm volatile("cp.async.wait_group 1;\n")
#define CP_WAIT0()  asm volatile("cp.async.wait_group 0;\n")

#define MMA_BF16(acc, a0, a1, a2, a3, b0, b1) \
    asm volatile( \
        "mma.sync.aligned.m16n8k16.row.col.f32.bf16.bf16.f32 " \
        "{%0,%1,%2,%3}, {%4,%5,%6,%7}, {%8,%9}, {%0,%1,%2,%3};\n" \
        : "+f"(acc[0]), "+f"(acc[1]), "+f"(acc[2]), "+f"(acc[3]) \
        : "r"(a0), "r"(a1), "r"(a2), "r"(a3), "r"(b0), "r"(b1))

#define LDSM_X4(d0, d1, d2, d3, a) \
    asm volatile("ldmatrix.sync.aligned.m8n8.x4.shared.b16 {%0,%1,%2,%3}, [%4];" \
        : "=r"(d0), "=r"(d1), "=r"(d2), "=r"(d3) : "r"(a))

// ---------------- merged sort (blocks 0..7) + weight prep (blocks 8..) ----------------
#define CHUNK 13
__global__ void k_sortprep(const int* __restrict__ labels,
                           const float* __restrict__ wv, const float* __restrict__ wc,
                           const float* __restrict__ w2, const float* __restrict__ w1,
                           const float* __restrict__ vb, const float* __restrict__ cbias) {
    if (blockIdx.x >= 8) {
        int i = (blockIdx.x - 8) * 256 + threadIdx.x;
        if (i < NCAT * CH) {
            int n = i / CH, k = i % CH;
            float v;
            if (n < CO) v = wv[k * CO + n] - wv[(CH + k) * CO + n];
            else        v = wv[(CH + k) * CO + (n - CO)];
            g_Wvt[n * CH + k] = __float2bfloat16(v);
            int k2 = i / NCAT, n2 = i % NCAT;
            float vc;
            if (n2 < CO) vc = wc[k2 * CO + n2] - wc[(CH + k2) * CO + n2];
            else         vc = wc[(CH + k2) * CO + (n2 - CO)];
            g_Wc2[i] = vc;
        }
        if (i < CH * CO) {
            int n = i / CO, k = i % CO;
            g_W2t[n * CO + k] = __float2bfloat16(w2[k * CH + n]);
        }
        if (i < CH * CH) {
            int n = i / CH, k = i % CH;
            __nv_bfloat16 hi, lo;
            split_bf16(w1[k * CH + n], hi, lo);
            g_W1t_hi[n * CH + k] = hi;
            g_W1t_lo[n * CH + k] = lo;
        }
        if (i < NCAT) {
            g_bias_cat[i] = (i < CO) ? vb[i] : 0.f;
            g_bias_c2[i]  = (i < CO) ? cbias[i] : 0.f;
        }
        return;
    }
    int b = blockIdx.x;
    const int* lab = labels + b * NPIX;
    __shared__ int slab[NPIX];
    __shared__ int cnt[KC][257];
    __shared__ int start[KC + 1];
    int t = threadIdx.x;
    for (int i = t; i < NPIX; i += 256) slab[i] = lab[i];
    __syncthreads();
    int lo = t * CHUNK;
    int hi = min(lo + CHUNK, NPIX);
    int local[KC];
#pragma unroll
    for (int k = 0; k < KC; k++) local[k] = 0;
    for (int i = lo; i < hi; i++) local[slab[i]]++;
#pragma unroll
    for (int k = 0; k < KC; k++) cnt[k][t + 1] = local[k];
    if (t < KC) cnt[t][0] = 0;
    __syncthreads();
    if (t < KC) {
        int s = 0;
        for (int j = 1; j <= 256; j++) { s += cnt[t][j]; cnt[t][j] = s; }
    }
    __syncthreads();
    if (t == 0) {
        int s = 0;
        for (int k = 0; k < KC; k++) { start[k] = s; s += cnt[k][256]; }
        start[KC] = s;
        for (int k = 0; k <= KC; k++) g_cstart[b][k] = start[k];
    }
    __syncthreads();
    int ofs[KC];
#pragma unroll
    for (int k = 0; k < KC; k++) ofs[k] = start[k] + cnt[k][t];
    for (int i = lo; i < hi; i++) {
        int l = slab[i];
        int p = ofs[l]++;
        g_order[b * NPIX + p] = i;
        g_ls[b * NPIX + p] = l;
    }
}

// ---------------- dwconv 7x7: smem halo tile, 4 outputs/thread ----------------
__global__ void k_dwconv(const float* __restrict__ x, const float* __restrict__ cw,
                         const float* __restrict__ cb) {
    int bc = blockIdx.y;
    int c  = bc % CH;
    int tile = blockIdx.x;
    int ty0 = (tile >> 1) * 32, tx0 = (tile & 1) * 32;
    __shared__ float sh[38][41];
    __shared__ float wsh[49];
    if (threadIdx.x < 49) wsh[threadIdx.x] = cw[c * 49 + threadIdx.x];
    const float* src = x + (size_t)bc * NPIX;
    for (int l = threadIdx.x; l < 38 * 38; l += 256) {
        int r = l / 38, cc = l % 38;
        int h = ty0 + r - 3, w = tx0 + cc - 3;
        sh[r][cc] = (h >= 0 && h < HH && w >= 0 && w < WW) ? src[h * WW + w] : 0.f;
    }
    __syncthreads();
    int ty = threadIdx.x >> 3;
    int xg = threadIdx.x & 7;
    int h = ty0 + ty;
    int wbase = tx0 + xg * 4;
    if (h < HH) {
        float acc[4] = {0.f, 0.f, 0.f, 0.f};
#pragma unroll
        for (int kh = 0; kh < 7; kh++) {
            float rr[10];
#pragma unroll
            for (int q = 0; q < 10; q++) rr[q] = sh[ty + kh][xg * 4 + q];
#pragma unroll
            for (int kw = 0; kw < 7; kw++) {
                float wv = wsh[kh * 7 + kw];
                acc[0] += rr[kw] * wv;     acc[1] += rr[kw + 1] * wv;
                acc[2] += rr[kw + 2] * wv; acc[3] += rr[kw + 3] * wv;
            }
        }
        float bb = cb[c];
#pragma unroll
        for (int o = 0; o < 4; o++) {
            int w = wbase + o;
            if (w < WW)
                g_xa[(size_t)bc * NPIX + h * WW + w] = acc[o] + bb + sh[ty + 3][xg * 4 + o + 3];
        }
    }
}

// transpose (B,C,N)->(B,N,C), split bf16
__global__ void k_transpose_cn(const float* __restrict__ in) {
    int b = blockIdx.z;
    int n0 = blockIdx.x * 32, c0 = blockIdx.y * 32;
    __shared__ float t[32][33];
    const float* ip = in + (size_t)b * CH * NPIX;
#pragma unroll
    for (int q = 0; q < 4; q++) {
        int cc = c0 + threadIdx.y + q * 8;
        t[threadIdx.y + q * 8][threadIdx.x] = ip[(size_t)cc * NPIX + n0 + threadIdx.x];
    }
    __syncthreads();
#pragma unroll
    for (int q = 0; q < 4; q++) {
        int nn = n0 + threadIdx.y + q * 8;
        size_t o = ((size_t)b * NPIX + nn) * CH + c0 + threadIdx.x;
        __nv_bfloat16 hi, lo;
        split_bf16(t[threadIdx.x][threadIdx.y + q * 8], hi, lo);
        g_xt_hi[o] = hi;
        g_xt_lo[o] = lo;
    }
}

// ---------------- fp32 SGEMM (centroid MLP only) ----------------
__global__ void k_gemm(const float* __restrict__ X, const float* __restrict__ W,
                       const float* __restrict__ bias, float* __restrict__ Y,
                       int M, int K, int Nn) {
    __shared__ float As[16][128];
    __shared__ float Bs[16][64];
    int bm = blockIdx.y * 128;
    int bn = blockIdx.x * 64;
    int tid = threadIdx.x;
    int tx = tid & 15;
    int ty = tid >> 4;
    float acc[8][4];
#pragma unroll
    for (int i = 0; i < 8; i++)
#pragma unroll
        for (int j = 0; j < 4; j++) acc[i][j] = 0.f;
    int lrow = tid >> 1;
    int lk8  = (tid & 1) * 8;
    int wkk  = tid >> 4;
    int wn4  = (tid & 15) * 4;
    const float* Xp = X + (size_t)(bm + lrow) * K + lk8;
    const float* Wp = W + (size_t)wkk * Nn + bn + wn4;
    for (int k0 = 0; k0 < K; k0 += 16) {
        float4 xa0 = *(const float4*)(Xp + k0);
        float4 xa1 = *(const float4*)(Xp + k0 + 4);
        As[lk8 + 0][lrow] = xa0.x; As[lk8 + 1][lrow] = xa0.y;
        As[lk8 + 2][lrow] = xa0.z; As[lk8 + 3][lrow] = xa0.w;
        As[lk8 + 4][lrow] = xa1.x; As[lk8 + 5][lrow] = xa1.y;
        As[lk8 + 6][lrow] = xa1.z; As[lk8 + 7][lrow] = xa1.w;
        *(float4*)&Bs[wkk][wn4] = *(const float4*)(Wp + (size_t)k0 * Nn);
        __syncthreads();
#pragma unroll
        for (int kk = 0; kk < 16; kk++) {
            float b0 = Bs[kk][tx * 4 + 0], b1 = Bs[kk][tx * 4 + 1];
            float b2 = Bs[kk][tx * 4 + 2], b3 = Bs[kk][tx * 4 + 3];
#pragma unroll
            for (int i = 0; i < 8; i++) {
                float a = As[kk][ty * 8 + i];
                acc[i][0] += a * b0; acc[i][1] += a * b1;
                acc[i][2] += a * b2; acc[i][3] += a * b3;
            }
        }
        __syncthreads();
    }
    float bb0 = 0.f, bb1 = 0.f, bb2 = 0.f, bb3 = 0.f;
    if (bias) {
        bb0 = bias[bn + tx * 4 + 0]; bb1 = bias[bn + tx * 4 + 1];
        bb2 = bias[bn + tx * 4 + 2]; bb3 = bias[bn + tx * 4 + 3];
    }
#pragma unroll
    for (int i = 0; i < 8; i++) {
        int row = bm + ty * 8 + i;
        float4 v = make_float4(acc[i][0] + bb0, acc[i][1] + bb1,
                               acc[i][2] + bb2, acc[i][3] + bb3);
        *(float4*)(Y + (size_t)row * Nn + bn + tx * 4) = v;
    }
}

// ---------------- double-buffered bf16 tensor GEMM (ldmatrix fragments) ----------------
// MODE 1: bf16 out (AB).  MODE 2: fc2 fused epilogue: transpose + shortcut -> y.
template<int NT, int MODE>
__global__ void __launch_bounds__(256) k_hgemm_db(
        const __nv_bfloat16* __restrict__ X, const __nv_bfloat16* __restrict__ Wt,
        const float* __restrict__ bias, float* __restrict__ Yf,
        __nv_bfloat16* __restrict__ Ybf, const float* __restrict__ shortcut,
        int M, int K, int Nn) {
    extern __shared__ char sm_[];
    constexpr int ASZ = 128 * 40 * 2;
    constexpr int BSZ = NT * 40 * 2;
    constexpr int STG = ASZ + BSZ;
    int bm = blockIdx.y * 128, bn = blockIdx.x * NT;
    int tid = threadIdx.x, warp = tid >> 5, lane = tid & 31;
    int wm = warp & 3, wn = warp >> 2;
    int g = lane >> 2, tg = lane & 3;
    constexpr int NI = NT / 16;
    int arow = ((lane & 15) >> 3) * 8 + (lane & 7);
    int acol = (lane >> 4) * 8;
    int brow = (lane >> 4) * 8 + (lane & 7);
    int bcol = ((lane >> 3) & 1) * 8;
    float acc[2][NI][4];
#pragma unroll
    for (int im = 0; im < 2; im++)
#pragma unroll
        for (int in = 0; in < NI; in++)
#pragma unroll
            for (int q = 0; q < 4; q++) acc[im][in][q] = 0.f;

    int KT = K / 32;
#pragma unroll 1
    for (int kt = -1; kt < KT; kt++) {
        int lt = kt + 1;
        if (lt < KT) {
            int s = lt & 1;
            __nv_bfloat16 (*As)[40] = (__nv_bfloat16(*)[40])(sm_ + s * STG);
            __nv_bfloat16 (*Bs)[40] = (__nv_bfloat16(*)[40])(sm_ + s * STG + ASZ);
            int k0 = lt * 32;
#pragma unroll
            for (int c = 0; c < 2; c++) {
                int ch = tid + c * 256;
                int row = ch >> 2, part = ch & 3;
                cp16(&As[row][part * 8], X + (size_t)(bm + row) * K + k0 + part * 8);
            }
#pragma unroll
            for (int c = 0; c < NT / 64; c++) {
                int ch = tid + c * 256;
                int row = ch >> 2, part = ch & 3;
                cp16(&Bs[row][part * 8], Wt + (size_t)(bn + row) * K + k0 + part * 8);
            }
            CP_COMMIT();
        }
        if (kt < 0) continue;
        if (kt + 1 < KT) CP_WAIT1(); else CP_WAIT0();
        __syncthreads();
        int s = kt & 1;
        __nv_bfloat16 (*As)[40] = (__nv_bfloat16(*)[40])(sm_ + s * STG);
        __nv_bfloat16 (*Bs)[40] = (__nv_bfloat16(*)[40])(sm_ + s * STG + ASZ);
#pragma unroll
        for (int kk = 0; kk < 32; kk += 16) {
            uint32_t a[2][4], bf[NI][2];
#pragma unroll
            for (int im = 0; im < 2; im++) {
                uint32_t ad = smaddr(&As[wm * 32 + im * 16 + arow][kk + acol]);
                LDSM_X4(a[im][0], a[im][1], a[im][2], a[im][3], ad);
            }
#pragma unroll
            for (int i2 = 0; i2 < NI / 2; i2++) {
                uint32_t bd = smaddr(&Bs[wn * (NT / 2) + i2 * 16 + brow][kk + bcol]);
                LDSM_X4(bf[2 * i2][0], bf[2 * i2][1], bf[2 * i2 + 1][0], bf[2 * i2 + 1][1], bd);
            }
#pragma unroll
            for (int im = 0; im < 2; im++)
#pragma unroll
                for (int in = 0; in < NI; in++)
                    MMA_BF16(acc[im][in], a[im][0], a[im][1], a[im][2], a[im][3],
                             bf[in][0], bf[in][1]);
        }
        __syncthreads();
    }
    if (MODE == 1) {
#pragma unroll
        for (int im = 0; im < 2; im++)
#pragma unroll
            for (int in = 0; in < NI; in++) {
                int row = bm + wm * 32 + im * 16 + g;
                int col = bn + wn * (NT / 2) + in * 8 + tg * 2;
                float b0 = bias[col], b1 = bias[col + 1];
                __nv_bfloat162 h0, h1;
                h0.x = __float2bfloat16(acc[im][in][0] + b0);
                h0.y = __float2bfloat16(acc[im][in][1] + b1);
                h1.x = __float2bfloat16(acc[im][in][2] + b0);
                h1.y = __float2bfloat16(acc[im][in][3] + b1);
                *(__nv_bfloat162*)&Ybf[(size_t)row * Nn + col] = h0;
                *(__nv_bfloat162*)&Ybf[(size_t)(row + 8) * Nn + col] = h1;
            }
    } else {
        float* smf = (float*)sm_;            // [NT][132]
#pragma unroll
        for (int im = 0; im < 2; im++)
#pragma unroll
            for (int in = 0; in < NI; in++) {
                int r = wm * 32 + im * 16 + g;
                int cc = wn * (NT / 2) + in * 8 + tg * 2;
                float b0 = bias[bn + cc], b1 = bias[bn + cc + 1];
                smf[cc * 132 + r]           = acc[im][in][0] + b0;
                smf[(cc + 1) * 132 + r]     = acc[im][in][1] + b1;
                smf[cc * 132 + r + 8]       = acc[im][in][2] + b0;
                smf[(cc + 1) * 132 + r + 8] = acc[im][in][3] + b1;
            }
        __syncthreads();
        for (int cc = warp; cc < NT; cc += 8) {
            float4 v = *(float4*)&smf[cc * 132 + lane * 4];
            int p = bm + lane * 4;
            int b = p / NPIX;
            int n = p - b * NPIX;
            size_t o = ((size_t)b * CH + bn + cc) * NPIX + n;
            float4 xv = *(const float4*)(shortcut + o);
            v.x += xv.x; v.y += xv.y; v.z += xv.z; v.w += xv.w;
            *(float4*)(Yf + o) = v;
        }
    }
}

// ---------------- double-buffered split-bf16 GEMM (fc1, ldmatrix fragments) ----------------
__global__ void __launch_bounds__(256) k_hgemm3_db(
        const __nv_bfloat16* __restrict__ Xhi, const __nv_bfloat16* __restrict__ Xlo,
        const __nv_bfloat16* __restrict__ Whi, const __nv_bfloat16* __restrict__ Wlo,
        const float* __restrict__ bias, float* __restrict__ Y,
        int M, int K, int Nn) {
    extern __shared__ char sm_[];
    constexpr int A1 = 128 * 40 * 2;
    constexpr int B1 = 64 * 40 * 2;
    constexpr int STG = 2 * A1 + 2 * B1;
    int bm = blockIdx.y * 128, bn = blockIdx.x * 64;
    int tid = threadIdx.x, warp = tid >> 5, lane = tid & 31;
    int wm = warp & 3, wn = warp >> 2;
    int g = lane >> 2, tg = lane & 3;
    int arow = ((lane & 15) >> 3) * 8 + (lane & 7);
    int acol = (lane >> 4) * 8;
    int brow = (lane >> 4) * 8 + (lane & 7);
    int bcol = ((lane >> 3) & 1) * 8;
    float acc[2][4][4];
#pragma unroll
    for (int im = 0; im < 2; im++)
#pragma unroll
        for (int in = 0; in < 4; in++)
#pragma unroll
            for (int q = 0; q < 4; q++) acc[im][in][q] = 0.f;

    int KT = K / 32;
#pragma unroll 1
    for (int kt = -1; kt < KT; kt++) {
        int lt = kt + 1;
        if (lt < KT) {
            int s = lt & 1;
            char* base = sm_ + s * STG;
            __nv_bfloat16 (*Ah)[40] = (__nv_bfloat16(*)[40])(base);
            __nv_bfloat16 (*Al)[40] = (__nv_bfloat16(*)[40])(base + A1);
            __nv_bfloat16 (*Bh)[40] = (__nv_bfloat16(*)[40])(base + 2 * A1);
            __nv_bfloat16 (*Bl)[40] = (__nv_bfloat16(*)[40])(base + 2 * A1 + B1);
            int k0 = lt * 32;
#pragma unroll
            for (int c = 0; c < 2; c++) {
                int ch = tid + c * 256;
                int row = ch >> 2, part = ch & 3;
                size_t ofs = (size_t)(bm + row) * K + k0 + part * 8;
                cp16(&Ah[row][part * 8], Xhi + ofs);
                cp16(&Al[row][part * 8], Xlo + ofs);
            }
            {
                int row = tid >> 2, part = tid & 3;
                size_t ofs = (size_t)(bn + row) * K + k0 + part * 8;
                cp16(&Bh[row][part * 8], Whi + ofs);
                cp16(&Bl[row][part * 8], Wlo + ofs);
            }
            CP_COMMIT();
        }
        if (kt < 0) continue;
        if (kt + 1 < KT) CP_WAIT1(); else CP_WAIT0();
        __syncthreads();
        int s = kt & 1;
        char* base = sm_ + s * STG;
        __nv_bfloat16 (*Ah)[40] = (__nv_bfloat16(*)[40])(base);
        __nv_bfloat16 (*Al)[40] = (__nv_bfloat16(*)[40])(base + A1);
        __nv_bfloat16 (*Bh)[40] = (__nv_bfloat16(*)[40])(base + 2 * A1);
        __nv_bfloat16 (*Bl)[40] = (__nv_bfloat16(*)[40])(base + 2 * A1 + B1);
#pragma unroll
        for (int kk = 0; kk < 32; kk += 16) {
            uint32_t ah[2][4], al[2][4], bh[4][2], bl[4][2];
#pragma unroll
            for (int im = 0; im < 2; im++) {
                uint32_t adh = smaddr(&Ah[wm * 32 + im * 16 + arow][kk + acol]);
                LDSM_X4(ah[im][0], ah[im][1], ah[im][2], ah[im][3], adh);
                uint32_t adl = smaddr(&Al[wm * 32 + im * 16 + arow][kk + acol]);
                LDSM_X4(al[im][0], al[im][1], al[im][2], al[im][3], adl);
            }
#pragma unroll
            for (int i2 = 0; i2 < 2; i2++) {
                uint32_t bdh = smaddr(&Bh[wn * 32 + i2 * 16 + brow][kk + bcol]);
                LDSM_X4(bh[2 * i2][0], bh[2 * i2][1], bh[2 * i2 + 1][0], bh[2 * i2 + 1][1], bdh);
                uint32_t bdl = smaddr(&Bl[wn * 32 + i2 * 16 + brow][kk + bcol]);
                LDSM_X4(bl[2 * i2][0], bl[2 * i2][1], bl[2 * i2 + 1][0], bl[2 * i2 + 1][1], bdl);
            }
#pragma unroll
            for (int im = 0; im < 2; im++)
#pragma unroll
                for (int in = 0; in < 4; in++) {
                    MMA_BF16(acc[im][in], ah[im][0], ah[im][1], ah[im][2], ah[im][3],
                             bh[in][0], bh[in][1]);
                    MMA_BF16(acc[im][in], ah[im][0], ah[im][1], ah[im][2], ah[im][3],
                             bl[in][0], bl[in][1]);
                    MMA_BF16(acc[im][in], al[im][0], al[im][1], al[im][2], al[im][3],
                             bh[in][0], bh[in][1]);
                }
        }
        __syncthreads();
    }
#pragma unroll
    for (int im = 0; im < 2; im++)
#pragma unroll
        for (int in = 0; in < 4; in++) {
            int row = bm + wm * 32 + im * 16 + g;
            int col = bn + wn * 32 + in * 8 + tg * 2;
            float b0 = bias[col], b1 = bias[col + 1];
            *(float2*)&Y[(size_t)row * Nn + col] =
                make_float2(acc[im][in][0] + b0, acc[im][in][1] + b1);
            *(float2*)&Y[(size_t)(row + 8) * Nn + col] =
                make_float2(acc[im][in][2] + b0, acc[im][in][3] + b1);
        }
}

// ---------------- gather + normalize + splits (one pass; no fp32 sorted copy) ----------------
__global__ void k_gather_norm() {
    int warp = threadIdx.x >> 5, lane = threadIdx.x & 31;
    int p = blockIdx.x * 8 + warp;
    if (p >= BN) return;
    int b = p / NPIX;
    int src = g_order[p];
    const float* in = g_xf + ((size_t)b * NPIX + src) * CH;
    float v[6];
    float ss = 0.f;
#pragma unroll
    for (int q = 0; q < 6; q++) { v[q] = in[lane + q * 32]; ss += v[q] * v[q]; }
#pragma unroll
    for (int off = 16; off; off >>= 1) ss += __shfl_xor_sync(0xffffffffu, ss, off);
    float inv = 1.f / fmaxf(sqrtf(ss), 1e-12f);
    size_t base = (size_t)p * CH;
#pragma unroll
    for (int q = 0; q < 6; q++) {
        int c = lane + q * 32;
        g_xsh[base + c] = __float2bfloat16(v[q]);
        __nv_bfloat16 hi, lo;
        split_bf16(v[q] * inv, hi, lo);
        g_xe_hi[base + c] = hi;
        g_xe_lo[base + c] = lo;
    }
}

// ---------------- Gram (split bf16, symmetric pairs, ldmatrix, double-buffered) ----------------
__global__ void __launch_bounds__(256) k_gram() {
    int cl = blockIdx.z;
    int b = cl / KC, k = cl % KC;
    int s0 = g_cstart[b][k], e0 = g_cstart[b][k + 1];
    int n = min(e0 - s0, SMAX);
    int pi = blockIdx.x;
    const int TI[6] = {0, 0, 0, 1, 1, 2};
    const int TJ[6] = {0, 1, 2, 1, 2, 2};
    int ti = TI[pi], tj = TJ[pi];
    if (ti * 128 >= n || tj * 128 >= n) return;
    int base = b * NPIX + s0;

    extern __shared__ char sm_[];
    constexpr int A1 = 128 * 40 * 2;
    constexpr int STG = 4 * A1;
    int tid = threadIdx.x;
    int warp = tid >> 5, lane = tid & 31;
    int wm = warp & 3, wn = warp >> 2;
    int g = lane >> 2, tg = lane & 3;
    int arow = ((lane & 15) >> 3) * 8 + (lane & 7);
    int acol = (lane >> 4) * 8;
    int brow = (lane >> 4) * 8 + (lane & 7);
    int bcol = ((lane >> 3) & 1) * 8;
    float acc[2][8][4];
#pragma unroll
    for (int im = 0; im < 2; im++)
#pragma unroll
        for (int in = 0; in < 8; in++)
#pragma unroll
            for (int q = 0; q < 4; q++) acc[im][in][q] = 0.f;

    int KT = CH / 32;
#pragma unroll 1
    for (int kt = -1; kt < KT; kt++) {
        int lt = kt + 1;
        if (lt < KT) {
            int s = lt & 1;
            char* bb = sm_ + s * STG;
            __nv_bfloat16 (*Ah)[40] = (__nv_bfloat16(*)[40])(bb);
            __nv_bfloat16 (*Al)[40] = (__nv_bfloat16(*)[40])(bb + A1);
            __nv_bfloat16 (*Bh)[40] = (__nv_bfloat16(*)[40])(bb + 2 * A1);
            __nv_bfloat16 (*Bl)[40] = (__nv_bfloat16(*)[40])(bb + 3 * A1);
            int k0 = lt * 32;
#pragma unroll
            for (int c = 0; c < 2; c++) {
                int ch = tid + c * 256;
                int row = ch >> 2, part = ch & 3;
                int ra = min(base + ti * 128 + row, BN - 1);
                int rb = min(base + tj * 128 + row, BN - 1);
                size_t oa = (size_t)ra * CH + k0 + part * 8;
                size_t ob = (size_t)rb * CH + k0 + part * 8;
                cp16(&Ah[row][part * 8], g_xe_hi + oa);
                cp16(&Al[row][part * 8], g_xe_lo + oa);
                cp16(&Bh[row][part * 8], g_xe_hi + ob);
                cp16(&Bl[row][part * 8], g_xe_lo + ob);
            }
            CP_COMMIT();
        }
        if (kt < 0) continue;
        if (kt + 1 < KT) CP_WAIT1(); else CP_WAIT0();
        __syncthreads();
        int s = kt & 1;
        char* bb = sm_ + s * STG;
        __nv_bfloat16 (*Ah)[40] = (__nv_bfloat16(*)[40])(bb);
        __nv_bfloat16 (*Al)[40] = (__nv_bfloat16(*)[40])(bb + A1);
        __nv_bfloat16 (*Bh)[40] = (__nv_bfloat16(*)[40])(bb + 2 * A1);
        __nv_bfloat16 (*Bl)[40] = (__nv_bfloat16(*)[40])(bb + 3 * A1);
#pragma unroll
        for (int kk = 0; kk < 32; kk += 16) {
            uint32_t ah[2][4], al[2][4], bh[8][2], bl[8][2];
#pragma unroll
            for (int im = 0; im < 2; im++) {
                uint32_t adh = smaddr(&Ah[wm * 32 + im * 16 + arow][kk + acol]);
                LDSM_X4(ah[im][0], ah[im][1], ah[im][2], ah[im][3], adh);
                uint32_t adl = smaddr(&Al[wm * 32 + im * 16 + arow][kk + acol]);
                LDSM_X4(al[im][0], al[im][1], al[im][2], al[im][3], adl);
            }
#pragma unroll
            for (int i2 = 0; i2 < 4; i2++) {
                uint32_t bdh = smaddr(&Bh[wn * 64 + i2 * 16 + brow][kk + bcol]);
                LDSM_X4(bh[2 * i2][0], bh[2 * i2][1], bh[2 * i2 + 1][0], bh[2 * i2 + 1][1], bdh);
                uint32_t bdl = smaddr(&Bl[wn * 64 + i2 * 16 + brow][kk + bcol]);
                LDSM_X4(bl[2 * i2][0], bl[2 * i2][1], bl[2 * i2 + 1][0], bl[2 * i2 + 1][1], bdl);
            }
#pragma unroll
            for (int im = 0; im < 2; im++)
#pragma unroll
                for (int in = 0; in < 8; in++) {
                    MMA_BF16(acc[im][in], ah[im][0], ah[im][1], ah[im][2], ah[im][3],
                             bh[in][0], bh[in][1]);
                    MMA_BF16(acc[im][in], ah[im][0], ah[im][1], ah[im][2], ah[im][3],
                             bl[in][0], bl[in][1]);
                    MMA_BF16(acc[im][in], al[im][0], al[im][1], al[im][2], al[im][3],
                             bh[in][0], bh[in][1]);
                }
        }
        __syncthreads();
    }
    float* Sp = g_S + (size_t)cl * SMAX * SMAX;
    float* smf = (float*)sm_;
#pragma unroll
    for (int im = 0; im < 2; im++)
#pragma unroll
        for (int in = 0; in < 8; in++) {
            int i0 = ti * 128 + wm * 32 + im * 16 + g;
            int j  = tj * 128 + wn * 64 + in * 8 + tg * 2;
            *(float2*)&Sp[(size_t)i0 * SMAX + j] = make_float2(acc[im][in][0], acc[im][in][1]);
            *(float2*)&Sp[(size_t)(i0 + 8) * SMAX + j] = make_float2(acc[im][in][2], acc[im][in][3]);
            if (ti != tj) {
                int il = wm * 32 + im * 16 + g;
                int jl = wn * 64 + in * 8 + tg * 2;
                smf[jl * 129 + il]           = acc[im][in][0];
                smf[(jl + 1) * 129 + il]     = acc[im][in][1];
                smf[jl * 129 + il + 8]       = acc[im][in][2];
                smf[(jl + 1) * 129 + il + 8] = acc[im][in][3];
            }
        }
    if (ti != tj) {
        __syncthreads();
        for (int jj = warp; jj < 128; jj += 8) {
            float v0 = smf[jj * 129 + lane * 4 + 0];
            float v1 = smf[jj * 129 + lane * 4 + 1];
            float v2 = smf[jj * 129 + lane * 4 + 2];
            float v3 = smf[jj * 129 + lane * 4 + 3];
            *(float4*)&Sp[(size_t)(tj * 128 + jj) * SMAX + ti * 128 + lane * 4] =
                make_float4(v0, v1, v2, v3);
        }
    }
}

// ---------------- top-NBR selection ----------------
__global__ void k_sel() {
    int cl = blockIdx.x;
    int b = cl / KC, k = cl % KC;
    int s = g_cstart[b][k], e = g_cstart[b][k + 1];
    int n = min(e - s, SMAX);
    int base = b * NPIX + s;
    int warp = threadIdx.x >> 5, lane = threadIdx.x & 31;
    int cnt = n < NBR ? n : NBR;
    const float* Sp = g_S + (size_t)cl * SMAX * SMAX;

    for (int i = warp; i < n; i += 8) {
        const float* row = Sp + (size_t)i * SMAX;
        float v[12];
#pragma unroll
        for (int q = 0; q < 12; q++) {
            int j = q * 32 + lane;
            v[q] = (j < n) ? row[j] : -CUDART_INF_F;
        }
        int lastbj = 0;
        for (int r = 0; r < cnt; r++) {
            float best = -CUDART_INF_F;
            int bj = SMAX * 32;
#pragma unroll
            for (int q = 0; q < 12; q++) {
                if (v[q] > best) { best = v[q]; bj = q * 32 + lane; }
            }
#pragma unroll
            for (int off = 16; off; off >>= 1) {
                float ov = __shfl_down_sync(0xffffffffu, best, off);
                int   oj = __shfl_down_sync(0xffffffffu, bj, off);
                if (ov > best || (ov == best && oj < bj)) { best = ov; bj = oj; }
            }
            bj = __shfl_sync(0xffffffffu, bj, 0);
            if (lane == (bj & 31)) v[bj >> 5] = -CUDART_INF_F;
            if (lane == 0) g_nbr[(size_t)(base + i) * NBR + r] = base + bj;
            lastbj = bj;
        }
        if (lane == 0)
            for (int r = cnt; r < NBR; r++)
                g_nbr[(size_t)(base + i) * NBR + r] = base + lastbj;
    }
}

// centroid from bf16 sorted rows (fp32 accumulate)
__global__ void k_centroid() {
    int b = blockIdx.x / KC, k = blockIdx.x % KC;
    int s = g_cstart[b][k], e = g_cstart[b][k + 1];
    int c = threadIdx.x;
    float sum = 0.f;
    for (int p = s; p < e; p++)
        sum += __bfloat162float(g_xsh[((size_t)b * NPIX + p) * CH + c]);
    float cntf = (float)max(e - s, 1);
    g_cen[((size_t)b * KC + k) * CH + c] = sum / cntf;
}

__global__ void k_cmax() {
    int idx = blockIdx.x * blockDim.x + threadIdx.x;
    if (idx >= BATCH * KC * CO) return;
    int c = idx % CO;
    int bk = idx / CO;
    int b = bk / KC;
    float a = g_AcBc[(size_t)bk * NCAT + c];
    float mn = CUDART_INF_F, mx = -CUDART_INF_F;
#pragma unroll
    for (int j = 0; j < KC; j++) {
        float xv = a + g_AcBc[(size_t)(b * KC + j) * NCAT + CO + c];
        mn = fminf(mn, xv);
        mx = fmaxf(mx, xv);
    }
    g_hc[idx] = gelu_max2(mn, mx);
}

// ---------------- aggregate: valley-extremes gelu-max over 9 neighbors ----------------
__global__ void k_aggregate() {
    int p = blockIdx.x;
    int b = p / NPIX;
    int lsk = g_ls[p];
    int dst = b * NPIX + g_order[p];
    __shared__ int nbrs[NBR];
    if (threadIdx.x < NBR) nbrs[threadIdx.x] = g_nbr[(size_t)p * NBR + threadIdx.x];
    __syncthreads();
    int c = threadIdx.x * 2;
    __nv_bfloat162 av = *(const __nv_bfloat162*)&g_ABh[(size_t)p * NCAT + c];
    float a0 = __bfloat162float(av.x), a1 = __bfloat162float(av.y);
    float2 hc2 = *(const float2*)&g_hc[((size_t)b * KC + lsk) * CO + c];
    float mn0 = CUDART_INF_F, mx0 = -CUDART_INF_F;
    float mn1 = CUDART_INF_F, mx1 = -CUDART_INF_F;
    int nb[NBR];
#pragma unroll
    for (int r = 0; r < NBR; r++) nb[r] = nbrs[r];
#pragma unroll
    for (int r = 0; r < NBR; r++) {
        __nv_bfloat162 bv = *(const __nv_bfloat162*)&g_ABh[(size_t)nb[r] * NCAT + CO + c];
        float x0 = __bfloat162float(bv.x);
        float x1 = __bfloat162float(bv.y);
        mn0 = fminf(mn0, x0); mx0 = fmaxf(mx0, x0);
        mn1 = fminf(mn1, x1); mx1 = fmaxf(mx1, x1);
    }
    float m0 = gelu_max2(a0 + mn0, a0 + mx0);
    float m1 = gelu_max2(a1 + mn1, a1 + mx1);
    __nv_bfloat162 out;
    out.x = __float2bfloat16(m0 + hc2.x);
    out.y = __float2bfloat16(m1 + hc2.y);
    *(__nv_bfloat162*)&g_hnh[(size_t)dst * CO + c] = out;
}

// ---------------- launch (serial, single stream) ----------------
extern "C" void kernel_launch(void* const* d_in, const int* in_sizes, int n_in,
                              void* d_out, int out_size) {
    const float* x      = (const float*)d_in[0];
    const int*   labels = (const int*)  d_in[1];
    const float* cpe_w  = (const float*)d_in[2];
    const float* cpe_b  = (const float*)d_in[3];
    const float* fc1_w  = (const float*)d_in[4];
    const float* fc1_b  = (const float*)d_in[5];
    const float* nn_v_w = (const float*)d_in[6];
    const float* nn_v_b = (const float*)d_in[7];
    const float* nn_c_w = (const float*)d_in[8];
    const float* nn_c_b = (const float*)d_in[9];
    const float* fc2_w  = (const float*)d_in[10];
    const float* fc2_b  = (const float*)d_in[11];
    float* y = (float*)d_out;

    float *p_xa, *p_xf, *p_cen, *p_AcBc, *p_Wc2, *p_bcat, *p_bc2;
    __nv_bfloat16 *p_xth, *p_xtl, *p_xsh, *p_hnh, *p_Wvt, *p_W2t, *p_W1h, *p_W1l, *p_ABh;
    cudaGetSymbolAddress((void**)&p_xa,   g_xa);
    cudaGetSymbolAddress((void**)&p_xf,   g_xf);
    cudaGetSymbolAddress((void**)&p_cen,  g_cen);
    cudaGetSymbolAddress((void**)&p_AcBc, g_AcBc);
    cudaGetSymbolAddress((void**)&p_Wc2,  g_Wc2);
    cudaGetSymbolAddress((void**)&p_bcat, g_bias_cat);
    cudaGetSymbolAddress((void**)&p_bc2,  g_bias_c2);
    cudaGetSymbolAddress((void**)&p_xth,  g_xt_hi);
    cudaGetSymbolAddress((void**)&p_xtl,  g_xt_lo);
    cudaGetSymbolAddress((void**)&p_xsh,  g_xsh);
    cudaGetSymbolAddress((void**)&p_hnh,  g_hnh);
    cudaGetSymbolAddress((void**)&p_Wvt,  g_Wvt);
    cudaGetSymbolAddress((void**)&p_W2t,  g_W2t);
    cudaGetSymbolAddress((void**)&p_W1h,  g_W1t_hi);
    cudaGetSymbolAddress((void**)&p_W1l,  g_W1t_lo);
    cudaGetSymbolAddress((void**)&p_ABh,  g_ABh);

    cudaFuncSetAttribute(k_hgemm3_db, cudaFuncAttributeMaxDynamicSharedMemorySize, 61440);
    cudaFuncSetAttribute(k_gram,      cudaFuncAttributeMaxDynamicSharedMemorySize, 81920);
    cudaFuncSetAttribute(k_hgemm_db<128,1>, cudaFuncAttributeMaxDynamicSharedMemorySize, 40960);
    cudaFuncSetAttribute(k_hgemm_db<64,2>,  cudaFuncAttributeMaxDynamicSharedMemorySize, 34048);

    k_sortprep<<<8 + (NCAT * CH + 255) / 256, 256>>>(labels, nn_v_w, nn_c_w, fc2_w, fc1_w, nn_v_b, nn_c_b);
    k_dwconv<<<dim3(4, BATCH * CH), 256>>>(x, cpe_w, cpe_b);
    k_transpose_cn<<<dim3(NPIX / 32, CH / 32, BATCH), dim3(32, 8)>>>(p_xa);

    // fc1 split-bf16 (contiguous rows, unsorted out)
    k_hgemm3_db<<<dim3(CH / 64, BN / 128), 256, 61440>>>(p_xth, p_xtl, p_W1h, p_W1l, fc1_b, p_xf, BN, CH, CH);
    // gather into sorted order + norm + splits (one pass)
    k_gather_norm<<<BN / 8, 256>>>();

    k_gram<<<dim3(6, 1, BATCH * KC), 256, 81920>>>();
    k_sel<<<BATCH * KC, 256>>>();

    // [A|Bv]: (25088,192)x(192,768) -> bf16
    k_hgemm_db<128,1><<<dim3(NCAT / 128, BN / 128), 256, 40960>>>(p_xsh, p_Wvt, p_bcat, nullptr, p_ABh, nullptr, BN, CH, NCAT);

    k_centroid<<<BATCH * KC, CH>>>();
    k_gemm<<<dim3(NCAT / 64, 1), 256>>>(p_cen, p_Wc2, p_bc2, p_AcBc, BATCH * KC, CH, NCAT);
    k_cmax<<<(BATCH * KC * CO + 255) / 256, 256>>>();

    k_aggregate<<<BN, CO / 2>>>();

    // fc2 fused: (25088,384)x(384,192) -> transpose + shortcut -> y
    k_hgemm_db<64,2><<<dim3(CH / 64, BN / 128), 256, 34048>>>(p_hnh, p_W2t, fc2_b, y, nullptr, x, BN, CO, CH);
}

// round 12
// speedup vs baseline: 1.5072x; 1.5072x over previous
#include <cuda_runtime.h>
#include <cuda_bf16.h>
#include <math_constants.h>
#include <cstdint>

#define BATCH 8
#define CH    192
#define HH    56
#define WW    56
#define NPIX  3136
#define KC    16
#define NBR   9
#define CO    384
#define NCAT  768
#define BN    (BATCH*NPIX)  // 25088
#define SMAX  384

// ---------------- scratch ----------------
__device__ __align__(128) float g_xa[BATCH*CH*NPIX];
__device__ __align__(128) __nv_bfloat16 g_xt_hi[BN*CH];
__device__ __align__(128) __nv_bfloat16 g_xt_lo[BN*CH];
__device__ __align__(128) float g_xf[BN*CH];            // fc1 out (UNSORTED rows)
__device__ __align__(128) __nv_bfloat16 g_xsh[BN*CH];   // sorted rows bf16
__device__ __align__(128) __nv_bfloat16 g_xe_hi[BN*CH];
__device__ __align__(128) __nv_bfloat16 g_xe_lo[BN*CH];
__device__ __align__(128) __nv_bfloat16 g_ABh[(size_t)BN*NCAT]; // [A | Bv] bf16 (sorted)
__device__ __align__(128) float g_S[(size_t)BATCH*KC*SMAX*SMAX];
__device__ __align__(128) __nv_bfloat16 g_hnh[BN*CO];   // aggregated, UNSORTED rows
__device__ int   g_order[BN];
__device__ int   g_ls[BN];
__device__ int   g_cstart[BATCH][KC+1];
__device__ int   g_nbr[BN*NBR];
__device__ __align__(128) float g_cen[BATCH*KC*CH];
__device__ __align__(128) float g_AcBc[BATCH*KC*NCAT];
__device__ __align__(128) float g_hc[BATCH*KC*CO];
__device__ __align__(128) float g_Wc2[CH*NCAT];
__device__ __align__(128) __nv_bfloat16 g_Wvt[NCAT*CH];
__device__ __align__(128) __nv_bfloat16 g_W2t[CH*CO];
__device__ __align__(128) __nv_bfloat16 g_W1t_hi[CH*CH];
__device__ __align__(128) __nv_bfloat16 g_W1t_lo[CH*CH];
__device__ __align__(128) float g_bias_cat[NCAT];
__device__ __align__(128) float g_bias_c2[NCAT];

__device__ __forceinline__ float gelu_f(float x) {
    float u = 0.7978845608028654f * (x + 0.044715f * x * x * x);
    float t;
    asm("tanh.approx.f32 %0, %1;" : "=f"(t) : "f"(u));
    return 0.5f * x * (1.0f + t);
}
// gelu is a valley function (decreasing then increasing, min near x=-0.75):
// max over a set = max(gelu(set-min), gelu(set-max)).
__device__ __forceinline__ float gelu_max2(float mn, float mx) {
    return fmaxf(gelu_f(mn), gelu_f(mx));
}
__device__ __forceinline__ void split_bf16(float v, __nv_bfloat16& hi, __nv_bfloat16& lo) {
    hi = __float2bfloat16(v);
    lo = __float2bfloat16(v - __bfloat162float(hi));
}
__device__ __forceinline__ void cp16(void* dst, const void* src) {
    uint32_t d = (uint32_t)__cvta_generic_to_shared(dst);
    asm volatile("cp.async.ca.shared.global [%0], [%1], 16;\n" :: "r"(d), "l"(src));
}
__device__ __forceinline__ uint32_t smaddr(const void* p) {
    return (uint32_t)__cvta_generic_to_shared(p);
}
#define CP_COMMIT() asm volatile("cp.async.commit_group;\n")
#define CP_WAIT1()  asm volatile("cp.async.wait_group 1;\n")
#define CP_WAIT0()  asm volatile("cp.async.wait_group 0;\n")

#define MMA_BF16(acc, a0, a1, a2, a3, b0, b1) \
    asm volatile( \
        "mma.sync.aligned.m16n8k16.row.col.f32.bf16.bf16.f32 " \
        "{%0,%1,%2,%3}, {%4,%5,%6,%7}, {%8,%9}, {%0,%1,%2,%3};\n" \
        : "+f"(acc[0]), "+f"(acc[1]), "+f"(acc[2]), "+f"(acc[3]) \
        : "r"(a0), "r"(a1), "r"(a2), "r"(a3), "r"(b0), "r"(b1))

#define LDSM_X4(d0, d1, d2, d3, a) \
    asm volatile("ldmatrix.sync.aligned.m8n8.x4.shared.b16 {%0,%1,%2,%3}, [%4];" \
        : "=r"(d0), "=r"(d1), "=r"(d2), "=r"(d3) : "r"(a))

// ---------------- merged sort (blocks 0..7) + weight prep (blocks 8..) ----------------
#define CHUNK 13
__global__ void k_sortprep(const int* __restrict__ labels,
                           const float* __restrict__ wv, const float* __restrict__ wc,
                           const float* __restrict__ w2, const float* __restrict__ w1,
                           const float* __restrict__ vb, const float* __restrict__ cbias) {
    if (blockIdx.x >= 8) {
        int i = (blockIdx.x - 8) * 256 + threadIdx.x;
        if (i < NCAT * CH) {
            int n = i / CH, k = i % CH;
            float v;
            if (n < CO) v = wv[k * CO + n] - wv[(CH + k) * CO + n];
            else        v = wv[(CH + k) * CO + (n - CO)];
            g_Wvt[n * CH + k] = __float2bfloat16(v);
            int k2 = i / NCAT, n2 = i % NCAT;
            float vc;
            if (n2 < CO) vc = wc[k2 * CO + n2] - wc[(CH + k2) * CO + n2];
            else         vc = wc[(CH + k2) * CO + (n2 - CO)];
            g_Wc2[i] = vc;
        }
        if (i < CH * CO) {
            int n = i / CO, k = i % CO;
            g_W2t[n * CO + k] = __float2bfloat16(w2[k * CH + n]);
        }
        if (i < CH * CH) {
            int n = i / CH, k = i % CH;
            __nv_bfloat16 hi, lo;
            split_bf16(w1[k * CH + n], hi, lo);
            g_W1t_hi[n * CH + k] = hi;
            g_W1t_lo[n * CH + k] = lo;
        }
        if (i < NCAT) {
            g_bias_cat[i] = (i < CO) ? vb[i] : 0.f;
            g_bias_c2[i]  = (i < CO) ? cbias[i] : 0.f;
        }
        return;
    }
    int b = blockIdx.x;
    const int* lab = labels + b * NPIX;
    __shared__ int slab[NPIX];
    __shared__ int cnt[KC][257];
    __shared__ int start[KC + 1];
    int t = threadIdx.x;
    for (int i = t; i < NPIX; i += 256) slab[i] = lab[i];
    __syncthreads();
    int lo = t * CHUNK;
    int hi = min(lo + CHUNK, NPIX);
    int local[KC];
#pragma unroll
    for (int k = 0; k < KC; k++) local[k] = 0;
    for (int i = lo; i < hi; i++) local[slab[i]]++;
#pragma unroll
    for (int k = 0; k < KC; k++) cnt[k][t + 1] = local[k];
    if (t < KC) cnt[t][0] = 0;
    __syncthreads();
    if (t < KC) {
        int s = 0;
        for (int j = 1; j <= 256; j++) { s += cnt[t][j]; cnt[t][j] = s; }
    }
    __syncthreads();
    if (t == 0) {
        int s = 0;
        for (int k = 0; k < KC; k++) { start[k] = s; s += cnt[k][256]; }
        start[KC] = s;
        for (int k = 0; k <= KC; k++) g_cstart[b][k] = start[k];
    }
    __syncthreads();
    int ofs[KC];
#pragma unroll
    for (int k = 0; k < KC; k++) ofs[k] = start[k] + cnt[k][t];
    for (int i = lo; i < hi; i++) {
        int l = slab[i];
        int p = ofs[l]++;
        g_order[b * NPIX + p] = i;
        g_ls[b * NPIX + p] = l;
    }
}

// ---------------- dwconv 7x7: smem halo tile, 4 outputs/thread ----------------
__global__ void k_dwconv(const float* __restrict__ x, const float* __restrict__ cw,
                         const float* __restrict__ cb) {
    int bc = blockIdx.y;
    int c  = bc % CH;
    int tile = blockIdx.x;
    int ty0 = (tile >> 1) * 32, tx0 = (tile & 1) * 32;
    __shared__ float sh[38][41];
    __shared__ float wsh[49];
    if (threadIdx.x < 49) wsh[threadIdx.x] = cw[c * 49 + threadIdx.x];
    const float* src = x + (size_t)bc * NPIX;
    for (int l = threadIdx.x; l < 38 * 38; l += 256) {
        int r = l / 38, cc = l % 38;
        int h = ty0 + r - 3, w = tx0 + cc - 3;
        sh[r][cc] = (h >= 0 && h < HH && w >= 0 && w < WW) ? src[h * WW + w] : 0.f;
    }
    __syncthreads();
    int ty = threadIdx.x >> 3;
    int xg = threadIdx.x & 7;
    int h = ty0 + ty;
    int wbase = tx0 + xg * 4;
    if (h < HH) {
        float acc[4] = {0.f, 0.f, 0.f, 0.f};
#pragma unroll
        for (int kh = 0; kh < 7; kh++) {
            float rr[10];
#pragma unroll
            for (int q = 0; q < 10; q++) rr[q] = sh[ty + kh][xg * 4 + q];
#pragma unroll
            for (int kw = 0; kw < 7; kw++) {
                float wv = wsh[kh * 7 + kw];
                acc[0] += rr[kw] * wv;     acc[1] += rr[kw + 1] * wv;
                acc[2] += rr[kw + 2] * wv; acc[3] += rr[kw + 3] * wv;
            }
        }
        float bb = cb[c];
#pragma unroll
        for (int o = 0; o < 4; o++) {
            int w = wbase + o;
            if (w < WW)
                g_xa[(size_t)bc * NPIX + h * WW + w] = acc[o] + bb + sh[ty + 3][xg * 4 + o + 3];
        }
    }
}

// transpose (B,C,N)->(B,N,C), split bf16
__global__ void k_transpose_cn(const float* __restrict__ in) {
    int b = blockIdx.z;
    int n0 = blockIdx.x * 32, c0 = blockIdx.y * 32;
    __shared__ float t[32][33];
    const float* ip = in + (size_t)b * CH * NPIX;
#pragma unroll
    for (int q = 0; q < 4; q++) {
        int cc = c0 + threadIdx.y + q * 8;
        t[threadIdx.y + q * 8][threadIdx.x] = ip[(size_t)cc * NPIX + n0 + threadIdx.x];
    }
    __syncthreads();
#pragma unroll
    for (int q = 0; q < 4; q++) {
        int nn = n0 + threadIdx.y + q * 8;
        size_t o = ((size_t)b * NPIX + nn) * CH + c0 + threadIdx.x;
        __nv_bfloat16 hi, lo;
        split_bf16(t[threadIdx.x][threadIdx.y + q * 8], hi, lo);
        g_xt_hi[o] = hi;
        g_xt_lo[o] = lo;
    }
}

// ---------------- fp32 SGEMM (centroid MLP only) ----------------
__global__ void k_gemm(const float* __restrict__ X, const float* __restrict__ W,
                       const float* __restrict__ bias, float* __restrict__ Y,
                       int M, int K, int Nn) {
    __shared__ float As[16][128];
    __shared__ float Bs[16][64];
    int bm = blockIdx.y * 128;
    int bn = blockIdx.x * 64;
    int tid = threadIdx.x;
    int tx = tid & 15;
    int ty = tid >> 4;
    float acc[8][4];
#pragma unroll
    for (int i = 0; i < 8; i++)
#pragma unroll
        for (int j = 0; j < 4; j++) acc[i][j] = 0.f;
    int lrow = tid >> 1;
    int lk8  = (tid & 1) * 8;
    int wkk  = tid >> 4;
    int wn4  = (tid & 15) * 4;
    const float* Xp = X + (size_t)(bm + lrow) * K + lk8;
    const float* Wp = W + (size_t)wkk * Nn + bn + wn4;
    for (int k0 = 0; k0 < K; k0 += 16) {
        float4 xa0 = *(const float4*)(Xp + k0);
        float4 xa1 = *(const float4*)(Xp + k0 + 4);
        As[lk8 + 0][lrow] = xa0.x; As[lk8 + 1][lrow] = xa0.y;
        As[lk8 + 2][lrow] = xa0.z; As[lk8 + 3][lrow] = xa0.w;
        As[lk8 + 4][lrow] = xa1.x; As[lk8 + 5][lrow] = xa1.y;
        As[lk8 + 6][lrow] = xa1.z; As[lk8 + 7][lrow] = xa1.w;
        *(float4*)&Bs[wkk][wn4] = *(const float4*)(Wp + (size_t)k0 * Nn);
        __syncthreads();
#pragma unroll
        for (int kk = 0; kk < 16; kk++) {
            float b0 = Bs[kk][tx * 4 + 0], b1 = Bs[kk][tx * 4 + 1];
            float b2 = Bs[kk][tx * 4 + 2], b3 = Bs[kk][tx * 4 + 3];
#pragma unroll
            for (int i = 0; i < 8; i++) {
                float a = As[kk][ty * 8 + i];
                acc[i][0] += a * b0; acc[i][1] += a * b1;
                acc[i][2] += a * b2; acc[i][3] += a * b3;
            }
        }
        __syncthreads();
    }
    float bb0 = 0.f, bb1 = 0.f, bb2 = 0.f, bb3 = 0.f;
    if (bias) {
        bb0 = bias[bn + tx * 4 + 0]; bb1 = bias[bn + tx * 4 + 1];
        bb2 = bias[bn + tx * 4 + 2]; bb3 = bias[bn + tx * 4 + 3];
    }
#pragma unroll
    for (int i = 0; i < 8; i++) {
        int row = bm + ty * 8 + i;
        float4 v = make_float4(acc[i][0] + bb0, acc[i][1] + bb1,
                               acc[i][2] + bb2, acc[i][3] + bb3);
        *(float4*)(Y + (size_t)row * Nn + bn + tx * 4) = v;
    }
}

// ---------------- double-buffered bf16 tensor GEMM (ldmatrix fragments) ----------------
// MODE 1: bf16 out (AB).  MODE 2: fc2 fused epilogue: transpose + shortcut -> y.
template<int NT, int MODE>
__global__ void __launch_bounds__(256) k_hgemm_db(
        const __nv_bfloat16* __restrict__ X, const __nv_bfloat16* __restrict__ Wt,
        const float* __restrict__ bias, float* __restrict__ Yf,
        __nv_bfloat16* __restrict__ Ybf, const float* __restrict__ shortcut,
        int M, int K, int Nn) {
    extern __shared__ char sm_[];
    constexpr int ASZ = 128 * 40 * 2;
    constexpr int BSZ = NT * 40 * 2;
    constexpr int STG = ASZ + BSZ;
    int bm = blockIdx.y * 128, bn = blockIdx.x * NT;
    int tid = threadIdx.x, warp = tid >> 5, lane = tid & 31;
    int wm = warp & 3, wn = warp >> 2;
    int g = lane >> 2, tg = lane & 3;
    constexpr int NI = NT / 16;
    int arow = ((lane & 15) >> 3) * 8 + (lane & 7);
    int acol = (lane >> 4) * 8;
    int brow = (lane >> 4) * 8 + (lane & 7);
    int bcol = ((lane >> 3) & 1) * 8;
    float acc[2][NI][4];
#pragma unroll
    for (int im = 0; im < 2; im++)
#pragma unroll
        for (int in = 0; in < NI; in++)
#pragma unroll
            for (int q = 0; q < 4; q++) acc[im][in][q] = 0.f;

    int KT = K / 32;
#pragma unroll 1
    for (int kt = -1; kt < KT; kt++) {
        int lt = kt + 1;
        if (lt < KT) {
            int s = lt & 1;
            __nv_bfloat16 (*As)[40] = (__nv_bfloat16(*)[40])(sm_ + s * STG);
            __nv_bfloat16 (*Bs)[40] = (__nv_bfloat16(*)[40])(sm_ + s * STG + ASZ);
            int k0 = lt * 32;
#pragma unroll
            for (int c = 0; c < 2; c++) {
                int ch = tid + c * 256;
                int row = ch >> 2, part = ch & 3;
                cp16(&As[row][part * 8], X + (size_t)(bm + row) * K + k0 + part * 8);
            }
#pragma unroll
            for (int c = 0; c < NT / 64; c++) {
                int ch = tid + c * 256;
                int row = ch >> 2, part = ch & 3;
                cp16(&Bs[row][part * 8], Wt + (size_t)(bn + row) * K + k0 + part * 8);
            }
            CP_COMMIT();
        }
        if (kt < 0) continue;
        if (kt + 1 < KT) CP_WAIT1(); else CP_WAIT0();
        __syncthreads();
        int s = kt & 1;
        __nv_bfloat16 (*As)[40] = (__nv_bfloat16(*)[40])(sm_ + s * STG);
        __nv_bfloat16 (*Bs)[40] = (__nv_bfloat16(*)[40])(sm_ + s * STG + ASZ);
#pragma unroll
        for (int kk = 0; kk < 32; kk += 16) {
            uint32_t a[2][4], bf[NI][2];
#pragma unroll
            for (int im = 0; im < 2; im++) {
                uint32_t ad = smaddr(&As[wm * 32 + im * 16 + arow][kk + acol]);
                LDSM_X4(a[im][0], a[im][1], a[im][2], a[im][3], ad);
            }
#pragma unroll
            for (int i2 = 0; i2 < NI / 2; i2++) {
                uint32_t bd = smaddr(&Bs[wn * (NT / 2) + i2 * 16 + brow][kk + bcol]);
                LDSM_X4(bf[2 * i2][0], bf[2 * i2][1], bf[2 * i2 + 1][0], bf[2 * i2 + 1][1], bd);
            }
#pragma unroll
            for (int im = 0; im < 2; im++)
#pragma unroll
                for (int in = 0; in < NI; in++)
                    MMA_BF16(acc[im][in], a[im][0], a[im][1], a[im][2], a[im][3],
                             bf[in][0], bf[in][1]);
        }
        __syncthreads();
    }
    if (MODE == 1) {
#pragma unroll
        for (int im = 0; im < 2; im++)
#pragma unroll
            for (int in = 0; in < NI; in++) {
                int row = bm + wm * 32 + im * 16 + g;
                int col = bn + wn * (NT / 2) + in * 8 + tg * 2;
                float b0 = bias[col], b1 = bias[col + 1];
                __nv_bfloat162 h0, h1;
                h0.x = __float2bfloat16(acc[im][in][0] + b0);
                h0.y = __float2bfloat16(acc[im][in][1] + b1);
                h1.x = __float2bfloat16(acc[im][in][2] + b0);
                h1.y = __float2bfloat16(acc[im][in][3] + b1);
                *(__nv_bfloat162*)&Ybf[(size_t)row * Nn + col] = h0;
                *(__nv_bfloat162*)&Ybf[(size_t)(row + 8) * Nn + col] = h1;
            }
    } else {
        float* smf = (float*)sm_;            // [NT][132]
#pragma unroll
        for (int im = 0; im < 2; im++)
#pragma unroll
            for (int in = 0; in < NI; in++) {
                int r = wm * 32 + im * 16 + g;
                int cc = wn * (NT / 2) + in * 8 + tg * 2;
                float b0 = bias[bn + cc], b1 = bias[bn + cc + 1];
                smf[cc * 132 + r]           = acc[im][in][0] + b0;
                smf[(cc + 1) * 132 + r]     = acc[im][in][1] + b1;
                smf[cc * 132 + r + 8]       = acc[im][in][2] + b0;
                smf[(cc + 1) * 132 + r + 8] = acc[im][in][3] + b1;
            }
        __syncthreads();
        for (int cc = warp; cc < NT; cc += 8) {
            float4 v = *(float4*)&smf[cc * 132 + lane * 4];
            int p = bm + lane * 4;
            int b = p / NPIX;
            int n = p - b * NPIX;
            size_t o = ((size_t)b * CH + bn + cc) * NPIX + n;
            float4 xv = *(const float4*)(shortcut + o);
            v.x += xv.x; v.y += xv.y; v.z += xv.z; v.w += xv.w;
            *(float4*)(Yf + o) = v;
        }
    }
}

// ---------------- double-buffered split-bf16 GEMM (fc1, ldmatrix fragments) ----------------
__global__ void __launch_bounds__(256) k_hgemm3_db(
        const __nv_bfloat16* __restrict__ Xhi, const __nv_bfloat16* __restrict__ Xlo,
        const __nv_bfloat16* __restrict__ Whi, const __nv_bfloat16* __restrict__ Wlo,
        const float* __restrict__ bias, float* __restrict__ Y,
        int M, int K, int Nn) {
    extern __shared__ char sm_[];
    constexpr int A1 = 128 * 40 * 2;
    constexpr int B1 = 64 * 40 * 2;
    constexpr int STG = 2 * A1 + 2 * B1;
    int bm = blockIdx.y * 128, bn = blockIdx.x * 64;
    int tid = threadIdx.x, warp = tid >> 5, lane = tid & 31;
    int wm = warp & 3, wn = warp >> 2;
    int g = lane >> 2, tg = lane & 3;
    int arow = ((lane & 15) >> 3) * 8 + (lane & 7);
    int acol = (lane >> 4) * 8;
    int brow = (lane >> 4) * 8 + (lane & 7);
    int bcol = ((lane >> 3) & 1) * 8;
    float acc[2][4][4];
#pragma unroll
    for (int im = 0; im < 2; im++)
#pragma unroll
        for (int in = 0; in < 4; in++)
#pragma unroll
            for (int q = 0; q < 4; q++) acc[im][in][q] = 0.f;

    int KT = K / 32;
#pragma unroll 1
    for (int kt = -1; kt < KT; kt++) {
        int lt = kt + 1;
        if (lt < KT) {
            int s = lt & 1;
            char* base = sm_ + s * STG;
            __nv_bfloat16 (*Ah)[40] = (__nv_bfloat16(*)[40])(base);
            __nv_bfloat16 (*Al)[40] = (__nv_bfloat16(*)[40])(base + A1);
            __nv_bfloat16 (*Bh)[40] = (__nv_bfloat16(*)[40])(base + 2 * A1);
            __nv_bfloat16 (*Bl)[40] = (__nv_bfloat16(*)[40])(base + 2 * A1 + B1);
            int k0 = lt * 32;
#pragma unroll
            for (int c = 0; c < 2; c++) {
                int ch = tid + c * 256;
                int row = ch >> 2, part = ch & 3;
                size_t ofs = (size_t)(bm + row) * K + k0 + part * 8;
                cp16(&Ah[row][part * 8], Xhi + ofs);
                cp16(&Al[row][part * 8], Xlo + ofs);
            }
            {
                int row = tid >> 2, part = tid & 3;
                size_t ofs = (size_t)(bn + row) * K + k0 + part * 8;
                cp16(&Bh[row][part * 8], Whi + ofs);
                cp16(&Bl[row][part * 8], Wlo + ofs);
            }
            CP_COMMIT();
        }
        if (kt < 0) continue;
        if (kt + 1 < KT) CP_WAIT1(); else CP_WAIT0();
        __syncthreads();
        int s = kt & 1;
        char* base = sm_ + s * STG;
        __nv_bfloat16 (*Ah)[40] = (__nv_bfloat16(*)[40])(base);
        __nv_bfloat16 (*Al)[40] = (__nv_bfloat16(*)[40])(base + A1);
        __nv_bfloat16 (*Bh)[40] = (__nv_bfloat16(*)[40])(base + 2 * A1);
        __nv_bfloat16 (*Bl)[40] = (__nv_bfloat16(*)[40])(base + 2 * A1 + B1);
#pragma unroll
        for (int kk = 0; kk < 32; kk += 16) {
            uint32_t ah[2][4], al[2][4], bh[4][2], bl[4][2];
#pragma unroll
            for (int im = 0; im < 2; im++) {
                uint32_t adh = smaddr(&Ah[wm * 32 + im * 16 + arow][kk + acol]);
                LDSM_X4(ah[im][0], ah[im][1], ah[im][2], ah[im][3], adh);
                uint32_t adl = smaddr(&Al[wm * 32 + im * 16 + arow][kk + acol]);
                LDSM_X4(al[im][0], al[im][1], al[im][2], al[im][3], adl);
            }
#pragma unroll
            for (int i2 = 0; i2 < 2; i2++) {
                uint32_t bdh = smaddr(&Bh[wn * 32 + i2 * 16 + brow][kk + bcol]);
                LDSM_X4(bh[2 * i2][0], bh[2 * i2][1], bh[2 * i2 + 1][0], bh[2 * i2 + 1][1], bdh);
                uint32_t bdl = smaddr(&Bl[wn * 32 + i2 * 16 + brow][kk + bcol]);
                LDSM_X4(bl[2 * i2][0], bl[2 * i2][1], bl[2 * i2 + 1][0], bl[2 * i2 + 1][1], bdl);
            }
#pragma unroll
            for (int im = 0; im < 2; im++)
#pragma unroll
                for (int in = 0; in < 4; in++) {
                    MMA_BF16(acc[im][in], ah[im][0], ah[im][1], ah[im][2], ah[im][3],
                             bh[in][0], bh[in][1]);
                    MMA_BF16(acc[im][in], ah[im][0], ah[im][1], ah[im][2], ah[im][3],
                             bl[in][0], bl[in][1]);
                    MMA_BF16(acc[im][in], al[im][0], al[im][1], al[im][2], al[im][3],
                             bh[in][0], bh[in][1]);
                }
        }
        __syncthreads();
    }
#pragma unroll
    for (int im = 0; im < 2; im++)
#pragma unroll
        for (int in = 0; in < 4; in++) {
            int row = bm + wm * 32 + im * 16 + g;
            int col = bn + wn * 32 + in * 8 + tg * 2;
            float b0 = bias[col], b1 = bias[col + 1];
            *(float2*)&Y[(size_t)row * Nn + col] =
                make_float2(acc[im][in][0] + b0, acc[im][in][1] + b1);
            *(float2*)&Y[(size_t)(row + 8) * Nn + col] =
                make_float2(acc[im][in][2] + b0, acc[im][in][3] + b1);
        }
}

// ---------------- gather + normalize + splits (one pass; no fp32 sorted copy) ----------------
__global__ void k_gather_norm() {
    int warp = threadIdx.x >> 5, lane = threadIdx.x & 31;
    int p = blockIdx.x * 8 + warp;
    if (p >= BN) return;
    int b = p / NPIX;
    int src = g_order[p];
    const float* in = g_xf + ((size_t)b * NPIX + src) * CH;
    float v[6];
    float ss = 0.f;
#pragma unroll
    for (int q = 0; q < 6; q++) { v[q] = in[lane + q * 32]; ss += v[q] * v[q]; }
#pragma unroll
    for (int off = 16; off; off >>= 1) ss += __shfl_xor_sync(0xffffffffu, ss, off);
    float inv = 1.f / fmaxf(sqrtf(ss), 1e-12f);
    size_t base = (size_t)p * CH;
#pragma unroll
    for (int q = 0; q < 6; q++) {
        int c = lane + q * 32;
        g_xsh[base + c] = __float2bfloat16(v[q]);
        __nv_bfloat16 hi, lo;
        split_bf16(v[q] * inv, hi, lo);
        g_xe_hi[base + c] = hi;
        g_xe_lo[base + c] = lo;
    }
}

// ---------------- Gram (split bf16, symmetric pairs, ldmatrix, double-buffered) ----------------
__global__ void __launch_bounds__(256) k_gram() {
    int cl = blockIdx.z;
    int b = cl / KC, k = cl % KC;
    int s0 = g_cstart[b][k], e0 = g_cstart[b][k + 1];
    int n = min(e0 - s0, SMAX);
    int pi = blockIdx.x;
    const int TI[6] = {0, 0, 0, 1, 1, 2};
    const int TJ[6] = {0, 1, 2, 1, 2, 2};
    int ti = TI[pi], tj = TJ[pi];
    if (ti * 128 >= n || tj * 128 >= n) return;
    int base = b * NPIX + s0;

    extern __shared__ char sm_[];
    constexpr int A1 = 128 * 40 * 2;
    constexpr int STG = 4 * A1;
    int tid = threadIdx.x;
    int warp = tid >> 5, lane = tid & 31;
    int wm = warp & 3, wn = warp >> 2;
    int g = lane >> 2, tg = lane & 3;
    int arow = ((lane & 15) >> 3) * 8 + (lane & 7);
    int acol = (lane >> 4) * 8;
    int brow = (lane >> 4) * 8 + (lane & 7);
    int bcol = ((lane >> 3) & 1) * 8;
    float acc[2][8][4];
#pragma unroll
    for (int im = 0; im < 2; im++)
#pragma unroll
        for (int in = 0; in < 8; in++)
#pragma unroll
            for (int q = 0; q < 4; q++) acc[im][in][q] = 0.f;

    int KT = CH / 32;
#pragma unroll 1
    for (int kt = -1; kt < KT; kt++) {
        int lt = kt + 1;
        if (lt < KT) {
            int s = lt & 1;
            char* bb = sm_ + s * STG;
            __nv_bfloat16 (*Ah)[40] = (__nv_bfloat16(*)[40])(bb);
            __nv_bfloat16 (*Al)[40] = (__nv_bfloat16(*)[40])(bb + A1);
            __nv_bfloat16 (*Bh)[40] = (__nv_bfloat16(*)[40])(bb + 2 * A1);
            __nv_bfloat16 (*Bl)[40] = (__nv_bfloat16(*)[40])(bb + 3 * A1);
            int k0 = lt * 32;
#pragma unroll
            for (int c = 0; c < 2; c++) {
                int ch = tid + c * 256;
                int row = ch >> 2, part = ch & 3;
                int ra = min(base + ti * 128 + row, BN - 1);
                int rb = min(base + tj * 128 + row, BN - 1);
                size_t oa = (size_t)ra * CH + k0 + part * 8;
                size_t ob = (size_t)rb * CH + k0 + part * 8;
                cp16(&Ah[row][part * 8], g_xe_hi + oa);
                cp16(&Al[row][part * 8], g_xe_lo + oa);
                cp16(&Bh[row][part * 8], g_xe_hi + ob);
                cp16(&Bl[row][part * 8], g_xe_lo + ob);
            }
            CP_COMMIT();
        }
        if (kt < 0) continue;
        if (kt + 1 < KT) CP_WAIT1(); else CP_WAIT0();
        __syncthreads();
        int s = kt & 1;
        char* bb = sm_ + s * STG;
        __nv_bfloat16 (*Ah)[40] = (__nv_bfloat16(*)[40])(bb);
        __nv_bfloat16 (*Al)[40] = (__nv_bfloat16(*)[40])(bb + A1);
        __nv_bfloat16 (*Bh)[40] = (__nv_bfloat16(*)[40])(bb + 2 * A1);
        __nv_bfloat16 (*Bl)[40] = (__nv_bfloat16(*)[40])(bb + 3 * A1);
#pragma unroll
        for (int kk = 0; kk < 32; kk += 16) {
            uint32_t ah[2][4], al[2][4], bh[8][2], bl[8][2];
#pragma unroll
            for (int im = 0; im < 2; im++) {
                uint32_t adh = smaddr(&Ah[wm * 32 + im * 16 + arow][kk + acol]);
                LDSM_X4(ah[im][0], ah[im][1], ah[im][2], ah[im][3], adh);
                uint32_t adl = smaddr(&Al[wm * 32 + im * 16 + arow][kk + acol]);
                LDSM_X4(al[im][0], al[im][1], al[im][2], al[im][3], adl);
            }
#pragma unroll
            for (int i2 = 0; i2 < 4; i2++) {
                uint32_t bdh = smaddr(&Bh[wn * 64 + i2 * 16 + brow][kk + bcol]);
                LDSM_X4(bh[2 * i2][0], bh[2 * i2][1], bh[2 * i2 + 1][0], bh[2 * i2 + 1][1], bdh);
                uint32_t bdl = smaddr(&Bl[wn * 64 + i2 * 16 + brow][kk + bcol]);
                LDSM_X4(bl[2 * i2][0], bl[2 * i2][1], bl[2 * i2 + 1][0], bl[2 * i2 + 1][1], bdl);
            }
#pragma unroll
            for (int im = 0; im < 2; im++)
#pragma unroll
                for (int in = 0; in < 8; in++) {
                    MMA_BF16(acc[im][in], ah[im][0], ah[im][1], ah[im][2], ah[im][3],
                             bh[in][0], bh[in][1]);
                    MMA_BF16(acc[im][in], ah[im][0], ah[im][1], ah[im][2], ah[im][3],
                             bl[in][0], bl[in][1]);
                    MMA_BF16(acc[im][in], al[im][0], al[im][1], al[im][2], al[im][3],
                             bh[in][0], bh[in][1]);
                }
        }
        __syncthreads();
    }
    float* Sp = g_S + (size_t)cl * SMAX * SMAX;
    float* smf = (float*)sm_;
#pragma unroll
    for (int im = 0; im < 2; im++)
#pragma unroll
        for (int in = 0; in < 8; in++) {
            int i0 = ti * 128 + wm * 32 + im * 16 + g;
            int j  = tj * 128 + wn * 64 + in * 8 + tg * 2;
            *(float2*)&Sp[(size_t)i0 * SMAX + j] = make_float2(acc[im][in][0], acc[im][in][1]);
            *(float2*)&Sp[(size_t)(i0 + 8) * SMAX + j] = make_float2(acc[im][in][2], acc[im][in][3]);
            if (ti != tj) {
                int il = wm * 32 + im * 16 + g;
                int jl = wn * 64 + in * 8 + tg * 2;
                smf[jl * 129 + il]           = acc[im][in][0];
                smf[(jl + 1) * 129 + il]     = acc[im][in][1];
                smf[jl * 129 + il + 8]       = acc[im][in][2];
                smf[(jl + 1) * 129 + il + 8] = acc[im][in][3];
            }
        }
    if (ti != tj) {
        __syncthreads();
        for (int jj = warp; jj < 128; jj += 8) {
            float v0 = smf[jj * 129 + lane * 4 + 0];
            float v1 = smf[jj * 129 + lane * 4 + 1];
            float v2 = smf[jj * 129 + lane * 4 + 2];
            float v3 = smf[jj * 129 + lane * 4 + 3];
            *(float4*)&Sp[(size_t)(tj * 128 + jj) * SMAX + ti * 128 + lane * 4] =
                make_float4(v0, v1, v2, v3);
        }
    }
}

// ---------------- top-NBR selection ----------------
__global__ void k_sel() {
    int cl = blockIdx.x;
    int b = cl / KC, k = cl % KC;
    int s = g_cstart[b][k], e = g_cstart[b][k + 1];
    int n = min(e - s, SMAX);
    int base = b * NPIX + s;
    int warp = threadIdx.x >> 5, lane = threadIdx.x & 31;
    int cnt = n < NBR ? n : NBR;
    const float* Sp = g_S + (size_t)cl * SMAX * SMAX;

    for (int i = warp; i < n; i += 8) {
        const float* row = Sp + (size_t)i * SMAX;
        float v[12];
#pragma unroll
        for (int q = 0; q < 12; q++) {
            int j = q * 32 + lane;
            v[q] = (j < n) ? row[j] : -CUDART_INF_F;
        }
        int lastbj = 0;
        for (int r = 0; r < cnt; r++) {
            float best = -CUDART_INF_F;
            int bj = SMAX * 32;
#pragma unroll
            for (int q = 0; q < 12; q++) {
                if (v[q] > best) { best = v[q]; bj = q * 32 + lane; }
            }
#pragma unroll
            for (int off = 16; off; off >>= 1) {
                float ov = __shfl_down_sync(0xffffffffu, best, off);
                int   oj = __shfl_down_sync(0xffffffffu, bj, off);
                if (ov > best || (ov == best && oj < bj)) { best = ov; bj = oj; }
            }
            bj = __shfl_sync(0xffffffffu, bj, 0);
            if (lane == (bj & 31)) v[bj >> 5] = -CUDART_INF_F;
            if (lane == 0) g_nbr[(size_t)(base + i) * NBR + r] = base + bj;
            lastbj = bj;
        }
        if (lane == 0)
            for (int r = cnt; r < NBR; r++)
                g_nbr[(size_t)(base + i) * NBR + r] = base + lastbj;
    }
}

// centroid from bf16 sorted rows (fp32 accumulate)
__global__ void k_centroid() {
    int b = blockIdx.x / KC, k = blockIdx.x % KC;
    int s = g_cstart[b][k], e = g_cstart[b][k + 1];
    int c = threadIdx.x;
    float sum = 0.f;
    for (int p = s; p < e; p++)
        sum += __bfloat162float(g_xsh[((size_t)b * NPIX + p) * CH + c]);
    float cntf = (float)max(e - s, 1);
    g_cen[((size_t)b * KC + k) * CH + c] = sum / cntf;
}

__global__ void k_cmax() {
    int idx = blockIdx.x * blockDim.x + threadIdx.x;
    if (idx >= BATCH * KC * CO) return;
    int c = idx % CO;
    int bk = idx / CO;
    int b = bk / KC;
    float a = g_AcBc[(size_t)bk * NCAT + c];
    float mn = CUDART_INF_F, mx = -CUDART_INF_F;
#pragma unroll
    for (int j = 0; j < KC; j++) {
        float xv = a + g_AcBc[(size_t)(b * KC + j) * NCAT + CO + c];
        mn = fminf(mn, xv);
        mx = fmaxf(mx, xv);
    }
    g_hc[idx] = gelu_max2(mn, mx);
}

// ---------------- aggregate: valley-extremes gelu-max over 9 neighbors ----------------
__global__ void k_aggregate() {
    int p = blockIdx.x;
    int b = p / NPIX;
    int lsk = g_ls[p];
    int dst = b * NPIX + g_order[p];
    __shared__ int nbrs[NBR];
    if (threadIdx.x < NBR) nbrs[threadIdx.x] = g_nbr[(size_t)p * NBR + threadIdx.x];
    __syncthreads();
    int c = threadIdx.x * 2;
    __nv_bfloat162 av = *(const __nv_bfloat162*)&g_ABh[(size_t)p * NCAT + c];
    float a0 = __bfloat162float(av.x), a1 = __bfloat162float(av.y);
    float2 hc2 = *(const float2*)&g_hc[((size_t)b * KC + lsk) * CO + c];
    float mn0 = CUDART_INF_F, mx0 = -CUDART_INF_F;
    float mn1 = CUDART_INF_F, mx1 = -CUDART_INF_F;
    int nb[NBR];
#pragma unroll
    for (int r = 0; r < NBR; r++) nb[r] = nbrs[r];
#pragma unroll
    for (int r = 0; r < NBR; r++) {
        __nv_bfloat162 bv = *(const __nv_bfloat162*)&g_ABh[(size_t)nb[r] * NCAT + CO + c];
        float x0 = __bfloat162float(bv.x);
        float x1 = __bfloat162float(bv.y);
        mn0 = fminf(mn0, x0); mx0 = fmaxf(mx0, x0);
        mn1 = fminf(mn1, x1); mx1 = fmaxf(mx1, x1);
    }
    float m0 = gelu_max2(a0 + mn0, a0 + mx0);
    float m1 = gelu_max2(a1 + mn1, a1 + mx1);
    __nv_bfloat162 out;
    out.x = __float2bfloat16(m0 + hc2.x);
    out.y = __float2bfloat16(m1 + hc2.y);
    *(__nv_bfloat162*)&g_hnh[(size_t)dst * CO + c] = out;
}

// ---------------- launch (serial, single stream) ----------------
extern "C" void kernel_launch(void* const* d_in, const int* in_sizes, int n_in,
                              void* d_out, int out_size) {
    const float* x      = (const float*)d_in[0];
    const int*   labels = (const int*)  d_in[1];
    const float* cpe_w  = (const float*)d_in[2];
    const float* cpe_b  = (const float*)d_in[3];
    const float* fc1_w  = (const float*)d_in[4];
    const float* fc1_b  = (const float*)d_in[5];
    const float* nn_v_w = (const float*)d_in[6];
    const float* nn_v_b = (const float*)d_in[7];
    const float* nn_c_w = (const float*)d_in[8];
    const float* nn_c_b = (const float*)d_in[9];
    const float* fc2_w  = (const float*)d_in[10];
    const float* fc2_b  = (const float*)d_in[11];
    float* y = (float*)d_out;

    float *p_xa, *p_xf, *p_cen, *p_AcBc, *p_Wc2, *p_bcat, *p_bc2;
    __nv_bfloat16 *p_xth, *p_xtl, *p_xsh, *p_hnh, *p_Wvt, *p_W2t, *p_W1h, *p_W1l, *p_ABh;
    cudaGetSymbolAddress((void**)&p_xa,   g_xa);
    cudaGetSymbolAddress((void**)&p_xf,   g_xf);
    cudaGetSymbolAddress((void**)&p_cen,  g_cen);
    cudaGetSymbolAddress((void**)&p_AcBc, g_AcBc);
    cudaGetSymbolAddress((void**)&p_Wc2,  g_Wc2);
    cudaGetSymbolAddress((void**)&p_bcat, g_bias_cat);
    cudaGetSymbolAddress((void**)&p_bc2,  g_bias_c2);
    cudaGetSymbolAddress((void**)&p_xth,  g_xt_hi);
    cudaGetSymbolAddress((void**)&p_xtl,  g_xt_lo);
    cudaGetSymbolAddress((void**)&p_xsh,  g_xsh);
    cudaGetSymbolAddress((void**)&p_hnh,  g_hnh);
    cudaGetSymbolAddress((void**)&p_Wvt,  g_Wvt);
    cudaGetSymbolAddress((void**)&p_W2t,  g_W2t);
    cudaGetSymbolAddress((void**)&p_W1h,  g_W1t_hi);
    cudaGetSymbolAddress((void**)&p_W1l,  g_W1t_lo);
    cudaGetSymbolAddress((void**)&p_ABh,  g_ABh);

    cudaFuncSetAttribute(k_hgemm3_db, cudaFuncAttributeMaxDynamicSharedMemorySize, 61440);
    cudaFuncSetAttribute(k_gram,      cudaFuncAttributeMaxDynamicSharedMemorySize, 81920);
    cudaFuncSetAttribute(k_hgemm_db<128,1>, cudaFuncAttributeMaxDynamicSharedMemorySize, 40960);
    cudaFuncSetAttribute(k_hgemm_db<64,2>,  cudaFuncAttributeMaxDynamicSharedMemorySize, 34048);

    k_sortprep<<<8 + (NCAT * CH + 255) / 256, 256>>>(labels, nn_v_w, nn_c_w, fc2_w, fc1_w, nn_v_b, nn_c_b);
    k_dwconv<<<dim3(4, BATCH * CH), 256>>>(x, cpe_w, cpe_b);
    k_transpose_cn<<<dim3(NPIX / 32, CH / 32, BATCH), dim3(32, 8)>>>(p_xa);

    // fc1 split-bf16 (contiguous rows, unsorted out)
    k_hgemm3_db<<<dim3(CH / 64, BN / 128), 256, 61440>>>(p_xth, p_xtl, p_W1h, p_W1l, fc1_b, p_xf, BN, CH, CH);
    // gather into sorted order + norm + splits (one pass)
    k_gather_norm<<<BN / 8, 256>>>();

    k_gram<<<dim3(6, 1, BATCH * KC), 256, 81920>>>();
    k_sel<<<BATCH * KC, 256>>>();

    // [A|Bv]: (25088,192)x(192,768) -> bf16
    k_hgemm_db<128,1><<<dim3(NCAT / 128, BN / 128), 256, 40960>>>(p_xsh, p_Wvt, p_bcat, nullptr, p_ABh, nullptr, BN, CH, NCAT);

    k_centroid<<<BATCH * KC, CH>>>();
    k_gemm<<<dim3(NCAT / 64, 1), 256>>>(p_cen, p_Wc2, p_bc2, p_AcBc, BATCH * KC, CH, NCAT);
    k_cmax<<<(BATCH * KC * CO + 255) / 256, 256>>>();

    k_aggregate<<<BN, CO / 2>>>();

    // fc2 fused: (25088,384)x(384,192) -> transpose + shortcut -> y
    k_hgemm_db<64,2><<<dim3(CH / 64, BN / 128), 256, 34048>>>(p_hnh, p_W2t, fc2_b, y, nullptr, x, BN, CO, CH);
}

// round 13
// speedup vs baseline: 1.5549x; 1.0317x over previous
#include <cuda_runtime.h>
#include <cuda_bf16.h>
#include <math_constants.h>
#include <cstdint>

#define BATCH 8
#define CH    192
#define HH    56
#define WW    56
#define NPIX  3136
#define KC    16
#define NBR   9
#define CO    384
#define NCAT  768
#define BN    (BATCH*NPIX)  // 25088
#define SMAX  384

// ---------------- scratch ----------------
__device__ __align__(128) float g_xa[BATCH*CH*NPIX];
__device__ __align__(128) __nv_bfloat16 g_xt_hi[BN*CH];
__device__ __align__(128) __nv_bfloat16 g_xt_lo[BN*CH];
__device__ __align__(128) float g_xf[BN*CH];            // fc1 out (UNSORTED rows)
__device__ __align__(128) __nv_bfloat16 g_xsh[BN*CH];   // sorted rows bf16
__device__ __align__(128) __nv_bfloat16 g_xe_hi[BN*CH]; // normalized sorted rows bf16
__device__ __align__(128) __nv_bfloat16 g_ABh[(size_t)BN*NCAT]; // [A | Bv] bf16 (sorted)
__device__ __align__(128) float g_S[(size_t)BATCH*KC*SMAX*SMAX];
__device__ __align__(128) __nv_bfloat16 g_hnh[BN*CO];   // aggregated, UNSORTED rows
__device__ int   g_order[BN];
__device__ int   g_ls[BN];
__device__ int   g_cstart[BATCH][KC+1];
__device__ int   g_nbr[BN*NBR];
__device__ __align__(128) float g_AcBc[BATCH*KC*NCAT];
__device__ __align__(128) float g_hc[BATCH*KC*CO];
__device__ __align__(128) float g_Wc2[CH*NCAT];
__device__ __align__(128) __nv_bfloat16 g_Wvt[NCAT*CH];
__device__ __align__(128) __nv_bfloat16 g_W2t[CH*CO];
__device__ __align__(128) __nv_bfloat16 g_W1t_hi[CH*CH];
__device__ __align__(128) __nv_bfloat16 g_W1t_lo[CH*CH];
__device__ __align__(128) float g_bias_cat[NCAT];
__device__ __align__(128) float g_bias_c2[NCAT];

__device__ __forceinline__ float gelu_f(float x) {
    float u = 0.7978845608028654f * (x + 0.044715f * x * x * x);
    float t;
    asm("tanh.approx.f32 %0, %1;" : "=f"(t) : "f"(u));
    return 0.5f * x * (1.0f + t);
}
__device__ __forceinline__ float gelu_max2(float mn, float mx) {
    return fmaxf(gelu_f(mn), gelu_f(mx));
}
__device__ __forceinline__ void split_bf16(float v, __nv_bfloat16& hi, __nv_bfloat16& lo) {
    hi = __float2bfloat16(v);
    lo = __float2bfloat16(v - __bfloat162float(hi));
}
__device__ __forceinline__ void cp16(void* dst, const void* src) {
    uint32_t d = (uint32_t)__cvta_generic_to_shared(dst);
    asm volatile("cp.async.ca.shared.global [%0], [%1], 16;\n" :: "r"(d), "l"(src));
}
__device__ __forceinline__ uint32_t smaddr(const void* p) {
    return (uint32_t)__cvta_generic_to_shared(p);
}
#define CP_COMMIT() asm volatile("cp.async.commit_group;\n")
#define CP_WAIT1()  asm volatile("cp.async.wait_group 1;\n")
#define CP_WAIT0()  asm volatile("cp.async.wait_group 0;\n")

#define MMA_BF16(acc, a0, a1, a2, a3, b0, b1) \
    asm volatile( \
        "mma.sync.aligned.m16n8k16.row.col.f32.bf16.bf16.f32 " \
        "{%0,%1,%2,%3}, {%4,%5,%6,%7}, {%8,%9}, {%0,%1,%2,%3};\n" \
        : "+f"(acc[0]), "+f"(acc[1]), "+f"(acc[2]), "+f"(acc[3]) \
        : "r"(a0), "r"(a1), "r"(a2), "r"(a3), "r"(b0), "r"(b1))

#define LDSM_X4(d0, d1, d2, d3, a) \
    asm volatile("ldmatrix.sync.aligned.m8n8.x4.shared.b16 {%0,%1,%2,%3}, [%4];" \
        : "=r"(d0), "=r"(d1), "=r"(d2), "=r"(d3) : "r"(a))

// ---------------- merged sort (blocks 0..7) + weight prep (blocks 8..) ----------------
#define CHUNK 13
__global__ void k_sortprep(const int* __restrict__ labels,
                           const float* __restrict__ wv, const float* __restrict__ wc,
                           const float* __restrict__ w2, const float* __restrict__ w1,
                           const float* __restrict__ vb, const float* __restrict__ cbias) {
    if (blockIdx.x >= 8) {
        int i = (blockIdx.x - 8) * 256 + threadIdx.x;
        if (i < NCAT * CH) {
            int n = i / CH, k = i % CH;
            float v;
            if (n < CO) v = wv[k * CO + n] - wv[(CH + k) * CO + n];
            else        v = wv[(CH + k) * CO + (n - CO)];
            g_Wvt[n * CH + k] = __float2bfloat16(v);
            int k2 = i / NCAT, n2 = i % NCAT;
            float vc;
            if (n2 < CO) vc = wc[k2 * CO + n2] - wc[(CH + k2) * CO + n2];
            else         vc = wc[(CH + k2) * CO + (n2 - CO)];
            g_Wc2[i] = vc;
        }
        if (i < CH * CO) {
            int n = i / CO, k = i % CO;
            g_W2t[n * CO + k] = __float2bfloat16(w2[k * CH + n]);
        }
        if (i < CH * CH) {
            int n = i / CH, k = i % CH;
            __nv_bfloat16 hi, lo;
            split_bf16(w1[k * CH + n], hi, lo);
            g_W1t_hi[n * CH + k] = hi;
            g_W1t_lo[n * CH + k] = lo;
        }
        if (i < NCAT) {
            g_bias_cat[i] = (i < CO) ? vb[i] : 0.f;
            g_bias_c2[i]  = (i < CO) ? cbias[i] : 0.f;
        }
        return;
    }
    int b = blockIdx.x;
    const int* lab = labels + b * NPIX;
    __shared__ int slab[NPIX];
    __shared__ int cnt[KC][257];
    __shared__ int start[KC + 1];
    int t = threadIdx.x;
    for (int i = t; i < NPIX; i += 256) slab[i] = lab[i];
    __syncthreads();
    int lo = t * CHUNK;
    int hi = min(lo + CHUNK, NPIX);
    int local[KC];
#pragma unroll
    for (int k = 0; k < KC; k++) local[k] = 0;
    for (int i = lo; i < hi; i++) local[slab[i]]++;
#pragma unroll
    for (int k = 0; k < KC; k++) cnt[k][t + 1] = local[k];
    if (t < KC) cnt[t][0] = 0;
    __syncthreads();
    if (t < KC) {
        int s = 0;
        for (int j = 1; j <= 256; j++) { s += cnt[t][j]; cnt[t][j] = s; }
    }
    __syncthreads();
    if (t == 0) {
        int s = 0;
        for (int k = 0; k < KC; k++) { start[k] = s; s += cnt[k][256]; }
        start[KC] = s;
        for (int k = 0; k <= KC; k++) g_cstart[b][k] = start[k];
    }
    __syncthreads();
    int ofs[KC];
#pragma unroll
    for (int k = 0; k < KC; k++) ofs[k] = start[k] + cnt[k][t];
    for (int i = lo; i < hi; i++) {
        int l = slab[i];
        int p = ofs[l]++;
        g_order[b * NPIX + p] = i;
        g_ls[b * NPIX + p] = l;
    }
}

// ---------------- dwconv 7x7: smem halo tile, 4 outputs/thread ----------------
__global__ void k_dwconv(const float* __restrict__ x, const float* __restrict__ cw,
                         const float* __restrict__ cb) {
    int bc = blockIdx.y;
    int c  = bc % CH;
    int tile = blockIdx.x;
    int ty0 = (tile >> 1) * 32, tx0 = (tile & 1) * 32;
    __shared__ float sh[38][41];
    __shared__ float wsh[49];
    if (threadIdx.x < 49) wsh[threadIdx.x] = cw[c * 49 + threadIdx.x];
    const float* src = x + (size_t)bc * NPIX;
    for (int l = threadIdx.x; l < 38 * 38; l += 256) {
        int r = l / 38, cc = l % 38;
        int h = ty0 + r - 3, w = tx0 + cc - 3;
        sh[r][cc] = (h >= 0 && h < HH && w >= 0 && w < WW) ? src[h * WW + w] : 0.f;
    }
    __syncthreads();
    int ty = threadIdx.x >> 3;
    int xg = threadIdx.x & 7;
    int h = ty0 + ty;
    int wbase = tx0 + xg * 4;
    if (h < HH) {
        float acc[4] = {0.f, 0.f, 0.f, 0.f};
#pragma unroll
        for (int kh = 0; kh < 7; kh++) {
            float rr[10];
#pragma unroll
            for (int q = 0; q < 10; q++) rr[q] = sh[ty + kh][xg * 4 + q];
#pragma unroll
            for (int kw = 0; kw < 7; kw++) {
                float wv = wsh[kh * 7 + kw];
                acc[0] += rr[kw] * wv;     acc[1] += rr[kw + 1] * wv;
                acc[2] += rr[kw + 2] * wv; acc[3] += rr[kw + 3] * wv;
            }
        }
        float bb = cb[c];
#pragma unroll
        for (int o = 0; o < 4; o++) {
            int w = wbase + o;
            if (w < WW)
                g_xa[(size_t)bc * NPIX + h * WW + w] = acc[o] + bb + sh[ty + 3][xg * 4 + o + 3];
        }
    }
}

// transpose (B,C,N)->(B,N,C), split bf16
__global__ void k_transpose_cn(const float* __restrict__ in) {
    int b = blockIdx.z;
    int n0 = blockIdx.x * 32, c0 = blockIdx.y * 32;
    __shared__ float t[32][33];
    const float* ip = in + (size_t)b * CH * NPIX;
#pragma unroll
    for (int q = 0; q < 4; q++) {
        int cc = c0 + threadIdx.y + q * 8;
        t[threadIdx.y + q * 8][threadIdx.x] = ip[(size_t)cc * NPIX + n0 + threadIdx.x];
    }
    __syncthreads();
#pragma unroll
    for (int q = 0; q < 4; q++) {
        int nn = n0 + threadIdx.y + q * 8;
        size_t o = ((size_t)b * NPIX + nn) * CH + c0 + threadIdx.x;
        __nv_bfloat16 hi, lo;
        split_bf16(t[threadIdx.x][threadIdx.y + q * 8], hi, lo);
        g_xt_hi[o] = hi;
        g_xt_lo[o] = lo;
    }
}

// ---------------- double-buffered bf16 tensor GEMM (ldmatrix fragments) ----------------
// MODE 1: bf16 out (AB).  MODE 2: fc2 fused epilogue: transpose + shortcut -> y.
template<int NT, int MODE>
__global__ void __launch_bounds__(256) k_hgemm_db(
        const __nv_bfloat16* __restrict__ X, const __nv_bfloat16* __restrict__ Wt,
        const float* __restrict__ bias, float* __restrict__ Yf,
        __nv_bfloat16* __restrict__ Ybf, const float* __restrict__ shortcut,
        int M, int K, int Nn) {
    extern __shared__ char sm_[];
    constexpr int ASZ = 128 * 40 * 2;
    constexpr int BSZ = NT * 40 * 2;
    constexpr int STG = ASZ + BSZ;
    int bm = blockIdx.y * 128, bn = blockIdx.x * NT;
    int tid = threadIdx.x, warp = tid >> 5, lane = tid & 31;
    int wm = warp & 3, wn = warp >> 2;
    int g = lane >> 2, tg = lane & 3;
    constexpr int NI = NT / 16;
    int arow = ((lane & 15) >> 3) * 8 + (lane & 7);
    int acol = (lane >> 4) * 8;
    int brow = (lane >> 4) * 8 + (lane & 7);
    int bcol = ((lane >> 3) & 1) * 8;
    float acc[2][NI][4];
#pragma unroll
    for (int im = 0; im < 2; im++)
#pragma unroll
        for (int in = 0; in < NI; in++)
#pragma unroll
            for (int q = 0; q < 4; q++) acc[im][in][q] = 0.f;

    int KT = K / 32;
#pragma unroll 1
    for (int kt = -1; kt < KT; kt++) {
        int lt = kt + 1;
        if (lt < KT) {
            int s = lt & 1;
            __nv_bfloat16 (*As)[40] = (__nv_bfloat16(*)[40])(sm_ + s * STG);
            __nv_bfloat16 (*Bs)[40] = (__nv_bfloat16(*)[40])(sm_ + s * STG + ASZ);
            int k0 = lt * 32;
#pragma unroll
            for (int c = 0; c < 2; c++) {
                int ch = tid + c * 256;
                int row = ch >> 2, part = ch & 3;
                cp16(&As[row][part * 8], X + (size_t)(bm + row) * K + k0 + part * 8);
            }
#pragma unroll
            for (int c = 0; c < NT / 64; c++) {
                int ch = tid + c * 256;
                int row = ch >> 2, part = ch & 3;
                cp16(&Bs[row][part * 8], Wt + (size_t)(bn + row) * K + k0 + part * 8);
            }
            CP_COMMIT();
        }
        if (kt < 0) continue;
        if (kt + 1 < KT) CP_WAIT1(); else CP_WAIT0();
        __syncthreads();
        int s = kt & 1;
        __nv_bfloat16 (*As)[40] = (__nv_bfloat16(*)[40])(sm_ + s * STG);
        __nv_bfloat16 (*Bs)[40] = (__nv_bfloat16(*)[40])(sm_ + s * STG + ASZ);
#pragma unroll
        for (int kk = 0; kk < 32; kk += 16) {
            uint32_t a[2][4], bf[NI][2];
#pragma unroll
            for (int im = 0; im < 2; im++) {
                uint32_t ad = smaddr(&As[wm * 32 + im * 16 + arow][kk + acol]);
                LDSM_X4(a[im][0], a[im][1], a[im][2], a[im][3], ad);
            }
#pragma unroll
            for (int i2 = 0; i2 < NI / 2; i2++) {
                uint32_t bd = smaddr(&Bs[wn * (NT / 2) + i2 * 16 + brow][kk + bcol]);
                LDSM_X4(bf[2 * i2][0], bf[2 * i2][1], bf[2 * i2 + 1][0], bf[2 * i2 + 1][1], bd);
            }
#pragma unroll
            for (int im = 0; im < 2; im++)
#pragma unroll
                for (int in = 0; in < NI; in++)
                    MMA_BF16(acc[im][in], a[im][0], a[im][1], a[im][2], a[im][3],
                             bf[in][0], bf[in][1]);
        }
        __syncthreads();
    }
    if (MODE == 1) {
#pragma unroll
        for (int im = 0; im < 2; im++)
#pragma unroll
            for (int in = 0; in < NI; in++) {
                int row = bm + wm * 32 + im * 16 + g;
                int col = bn + wn * (NT / 2) + in * 8 + tg * 2;
                float b0 = bias[col], b1 = bias[col + 1];
                __nv_bfloat162 h0, h1;
                h0.x = __float2bfloat16(acc[im][in][0] + b0);
                h0.y = __float2bfloat16(acc[im][in][1] + b1);
                h1.x = __float2bfloat16(acc[im][in][2] + b0);
                h1.y = __float2bfloat16(acc[im][in][3] + b1);
                *(__nv_bfloat162*)&Ybf[(size_t)row * Nn + col] = h0;
                *(__nv_bfloat162*)&Ybf[(size_t)(row + 8) * Nn + col] = h1;
            }
    } else {
        float* smf = (float*)sm_;            // [NT][132]
#pragma unroll
        for (int im = 0; im < 2; im++)
#pragma unroll
            for (int in = 0; in < NI; in++) {
                int r = wm * 32 + im * 16 + g;
                int cc = wn * (NT / 2) + in * 8 + tg * 2;
                float b0 = bias[bn + cc], b1 = bias[bn + cc + 1];
                smf[cc * 132 + r]           = acc[im][in][0] + b0;
                smf[(cc + 1) * 132 + r]     = acc[im][in][1] + b1;
                smf[cc * 132 + r + 8]       = acc[im][in][2] + b0;
                smf[(cc + 1) * 132 + r + 8] = acc[im][in][3] + b1;
            }
        __syncthreads();
        for (int cc = warp; cc < NT; cc += 8) {
            float4 v = *(float4*)&smf[cc * 132 + lane * 4];
            int p = bm + lane * 4;
            int b = p / NPIX;
            int n = p - b * NPIX;
            size_t o = ((size_t)b * CH + bn + cc) * NPIX + n;
            float4 xv = *(const float4*)(shortcut + o);
            v.x += xv.x; v.y += xv.y; v.z += xv.z; v.w += xv.w;
            *(float4*)(Yf + o) = v;
        }
    }
}

// ---------------- double-buffered split-bf16 GEMM (fc1, ldmatrix fragments) ----------------
__global__ void __launch_bounds__(256) k_hgemm3_db(
        const __nv_bfloat16* __restrict__ Xhi, const __nv_bfloat16* __restrict__ Xlo,
        const __nv_bfloat16* __restrict__ Whi, const __nv_bfloat16* __restrict__ Wlo,
        const float* __restrict__ bias, float* __restrict__ Y,
        int M, int K, int Nn) {
    extern __shared__ char sm_[];
    constexpr int A1 = 128 * 40 * 2;
    constexpr int B1 = 64 * 40 * 2;
    constexpr int STG = 2 * A1 + 2 * B1;
    int bm = blockIdx.y * 128, bn = blockIdx.x * 64;
    int tid = threadIdx.x, warp = tid >> 5, lane = tid & 31;
    int wm = warp & 3, wn = warp >> 2;
    int g = lane >> 2, tg = lane & 3;
    int arow = ((lane & 15) >> 3) * 8 + (lane & 7);
    int acol = (lane >> 4) * 8;
    int brow = (lane >> 4) * 8 + (lane & 7);
    int bcol = ((lane >> 3) & 1) * 8;
    float acc[2][4][4];
#pragma unroll
    for (int im = 0; im < 2; im++)
#pragma unroll
        for (int in = 0; in < 4; in++)
#pragma unroll
            for (int q = 0; q < 4; q++) acc[im][in][q] = 0.f;

    int KT = K / 32;
#pragma unroll 1
    for (int kt = -1; kt < KT; kt++) {
        int lt = kt + 1;
        if (lt < KT) {
            int s = lt & 1;
            char* base = sm_ + s * STG;
            __nv_bfloat16 (*Ah)[40] = (__nv_bfloat16(*)[40])(base);
            __nv_bfloat16 (*Al)[40] = (__nv_bfloat16(*)[40])(base + A1);
            __nv_bfloat16 (*Bh)[40] = (__nv_bfloat16(*)[40])(base + 2 * A1);
            __nv_bfloat16 (*Bl)[40] = (__nv_bfloat16(*)[40])(base + 2 * A1 + B1);
            int k0 = lt * 32;
#pragma unroll
            for (int c = 0; c < 2; c++) {
                int ch = tid + c * 256;
                int row = ch >> 2, part = ch & 3;
                size_t ofs = (size_t)(bm + row) * K + k0 + part * 8;
                cp16(&Ah[row][part * 8], Xhi + ofs);
                cp16(&Al[row][part * 8], Xlo + ofs);
            }
            {
                int row = tid >> 2, part = tid & 3;
                size_t ofs = (size_t)(bn + row) * K + k0 + part * 8;
                cp16(&Bh[row][part * 8], Whi + ofs);
                cp16(&Bl[row][part * 8], Wlo + ofs);
            }
            CP_COMMIT();
        }
        if (kt < 0) continue;
        if (kt + 1 < KT) CP_WAIT1(); else CP_WAIT0();
        __syncthreads();
        int s = kt & 1;
        char* base = sm_ + s * STG;
        __nv_bfloat16 (*Ah)[40] = (__nv_bfloat16(*)[40])(base);
        __nv_bfloat16 (*Al)[40] = (__nv_bfloat16(*)[40])(base + A1);
        __nv_bfloat16 (*Bh)[40] = (__nv_bfloat16(*)[40])(base + 2 * A1);
        __nv_bfloat16 (*Bl)[40] = (__nv_bfloat16(*)[40])(base + 2 * A1 + B1);
#pragma unroll
        for (int kk = 0; kk < 32; kk += 16) {
            uint32_t ah[2][4], al[2][4], bh[4][2], bl[4][2];
#pragma unroll
            for (int im = 0; im < 2; im++) {
                uint32_t adh = smaddr(&Ah[wm * 32 + im * 16 + arow][kk + acol]);
                LDSM_X4(ah[im][0], ah[im][1], ah[im][2], ah[im][3], adh);
                uint32_t adl = smaddr(&Al[wm * 32 + im * 16 + arow][kk + acol]);
                LDSM_X4(al[im][0], al[im][1], al[im][2], al[im][3], adl);
            }
#pragma unroll
            for (int i2 = 0; i2 < 2; i2++) {
                uint32_t bdh = smaddr(&Bh[wn * 32 + i2 * 16 + brow][kk + bcol]);
                LDSM_X4(bh[2 * i2][0], bh[2 * i2][1], bh[2 * i2 + 1][0], bh[2 * i2 + 1][1], bdh);
                uint32_t bdl = smaddr(&Bl[wn * 32 + i2 * 16 + brow][kk + bcol]);
                LDSM_X4(bl[2 * i2][0], bl[2 * i2][1], bl[2 * i2 + 1][0], bl[2 * i2 + 1][1], bdl);
            }
#pragma unroll
            for (int im = 0; im < 2; im++)
#pragma unroll
                for (int in = 0; in < 4; in++) {
                    MMA_BF16(acc[im][in], ah[im][0], ah[im][1], ah[im][2], ah[im][3],
                             bh[in][0], bh[in][1]);
                    MMA_BF16(acc[im][in], ah[im][0], ah[im][1], ah[im][2], ah[im][3],
                             bl[in][0], bl[in][1]);
                    MMA_BF16(acc[im][in], al[im][0], al[im][1], al[im][2], al[im][3],
                             bh[in][0], bh[in][1]);
                }
        }
        __syncthreads();
    }
#pragma unroll
    for (int im = 0; im < 2; im++)
#pragma unroll
        for (int in = 0; in < 4; in++) {
            int row = bm + wm * 32 + im * 16 + g;
            int col = bn + wn * 32 + in * 8 + tg * 2;
            float b0 = bias[col], b1 = bias[col + 1];
            *(float2*)&Y[(size_t)row * Nn + col] =
                make_float2(acc[im][in][0] + b0, acc[im][in][1] + b1);
            *(float2*)&Y[(size_t)(row + 8) * Nn + col] =
                make_float2(acc[im][in][2] + b0, acc[im][in][3] + b1);
        }
}

// ---------------- gather + normalize (bf16 hi only) ----------------
__global__ void k_gather_norm() {
    int warp = threadIdx.x >> 5, lane = threadIdx.x & 31;
    int p = blockIdx.x * 8 + warp;
    if (p >= BN) return;
    int b = p / NPIX;
    int src = g_order[p];
    const float* in = g_xf + ((size_t)b * NPIX + src) * CH;
    float v[6];
    float ss = 0.f;
#pragma unroll
    for (int q = 0; q < 6; q++) { v[q] = in[lane + q * 32]; ss += v[q] * v[q]; }
#pragma unroll
    for (int off = 16; off; off >>= 1) ss += __shfl_xor_sync(0xffffffffu, ss, off);
    float inv = 1.f / fmaxf(sqrtf(ss), 1e-12f);
    size_t base = (size_t)p * CH;
#pragma unroll
    for (int q = 0; q < 6; q++) {
        int c = lane + q * 32;
        g_xsh[base + c] = __float2bfloat16(v[q]);
        g_xe_hi[base + c] = __float2bfloat16(v[q] * inv);
    }
}

// ---------------- Gram (single bf16 MMA, symmetric pairs, ldmatrix, double-buffered) ----------------
__global__ void __launch_bounds__(256) k_gram() {
    int cl = blockIdx.z;
    int b = cl / KC, k = cl % KC;
    int s0 = g_cstart[b][k], e0 = g_cstart[b][k + 1];
    int n = min(e0 - s0, SMAX);
    int pi = blockIdx.x;
    const int TI[6] = {0, 0, 0, 1, 1, 2};
    const int TJ[6] = {0, 1, 2, 1, 2, 2};
    int ti = TI[pi], tj = TJ[pi];
    if (ti * 128 >= n || tj * 128 >= n) return;
    int base = b * NPIX + s0;

    extern __shared__ char sm_[];
    constexpr int A1 = 128 * 40 * 2;
    constexpr int STG = 2 * A1;                 // Ah + Bh only
    int tid = threadIdx.x;
    int warp = tid >> 5, lane = tid & 31;
    int wm = warp & 3, wn = warp >> 2;
    int g = lane >> 2, tg = lane & 3;
    int arow = ((lane & 15) >> 3) * 8 + (lane & 7);
    int acol = (lane >> 4) * 8;
    int brow = (lane >> 4) * 8 + (lane & 7);
    int bcol = ((lane >> 3) & 1) * 8;
    float acc[2][8][4];
#pragma unroll
    for (int im = 0; im < 2; im++)
#pragma unroll
        for (int in = 0; in < 8; in++)
#pragma unroll
            for (int q = 0; q < 4; q++) acc[im][in][q] = 0.f;

    int KT = CH / 32;
#pragma unroll 1
    for (int kt = -1; kt < KT; kt++) {
        int lt = kt + 1;
        if (lt < KT) {
            int s = lt & 1;
            char* bb = sm_ + s * STG;
            __nv_bfloat16 (*Ah)[40] = (__nv_bfloat16(*)[40])(bb);
            __nv_bfloat16 (*Bh)[40] = (__nv_bfloat16(*)[40])(bb + A1);
            int k0 = lt * 32;
#pragma unroll
            for (int c = 0; c < 2; c++) {
                int ch = tid + c * 256;
                int row = ch >> 2, part = ch & 3;
                int ra = min(base + ti * 128 + row, BN - 1);
                int rb = min(base + tj * 128 + row, BN - 1);
                cp16(&Ah[row][part * 8], g_xe_hi + (size_t)ra * CH + k0 + part * 8);
                cp16(&Bh[row][part * 8], g_xe_hi + (size_t)rb * CH + k0 + part * 8);
            }
            CP_COMMIT();
        }
        if (kt < 0) continue;
        if (kt + 1 < KT) CP_WAIT1(); else CP_WAIT0();
        __syncthreads();
        int s = kt & 1;
        char* bb = sm_ + s * STG;
        __nv_bfloat16 (*Ah)[40] = (__nv_bfloat16(*)[40])(bb);
        __nv_bfloat16 (*Bh)[40] = (__nv_bfloat16(*)[40])(bb + A1);
#pragma unroll
        for (int kk = 0; kk < 32; kk += 16) {
            uint32_t ah[2][4], bh[8][2];
#pragma unroll
            for (int im = 0; im < 2; im++) {
                uint32_t adh = smaddr(&Ah[wm * 32 + im * 16 + arow][kk + acol]);
                LDSM_X4(ah[im][0], ah[im][1], ah[im][2], ah[im][3], adh);
            }
#pragma unroll
            for (int i2 = 0; i2 < 4; i2++) {
                uint32_t bdh = smaddr(&Bh[wn * 64 + i2 * 16 + brow][kk + bcol]);
                LDSM_X4(bh[2 * i2][0], bh[2 * i2][1], bh[2 * i2 + 1][0], bh[2 * i2 + 1][1], bdh);
            }
#pragma unroll
            for (int im = 0; im < 2; im++)
#pragma unroll
                for (int in = 0; in < 8; in++)
                    MMA_BF16(acc[im][in], ah[im][0], ah[im][1], ah[im][2], ah[im][3],
                             bh[in][0], bh[in][1]);
        }
        __syncthreads();
    }
    float* Sp = g_S + (size_t)cl * SMAX * SMAX;
    float* smf = (float*)sm_;
#pragma unroll
    for (int im = 0; im < 2; im++)
#pragma unroll
        for (int in = 0; in < 8; in++) {
            int i0 = ti * 128 + wm * 32 + im * 16 + g;
            int j  = tj * 128 + wn * 64 + in * 8 + tg * 2;
            *(float2*)&Sp[(size_t)i0 * SMAX + j] = make_float2(acc[im][in][0], acc[im][in][1]);
            *(float2*)&Sp[(size_t)(i0 + 8) * SMAX + j] = make_float2(acc[im][in][2], acc[im][in][3]);
            if (ti != tj) {
                int il = wm * 32 + im * 16 + g;
                int jl = wn * 64 + in * 8 + tg * 2;
                smf[jl * 129 + il]           = acc[im][in][0];
                smf[(jl + 1) * 129 + il]     = acc[im][in][1];
                smf[jl * 129 + il + 8]       = acc[im][in][2];
                smf[(jl + 1) * 129 + il + 8] = acc[im][in][3];
            }
        }
    if (ti != tj) {
        __syncthreads();
        for (int jj = warp; jj < 128; jj += 8) {
            float v0 = smf[jj * 129 + lane * 4 + 0];
            float v1 = smf[jj * 129 + lane * 4 + 1];
            float v2 = smf[jj * 129 + lane * 4 + 2];
            float v3 = smf[jj * 129 + lane * 4 + 3];
            *(float4*)&Sp[(size_t)(tj * 128 + jj) * SMAX + ti * 128 + lane * 4] =
                make_float4(v0, v1, v2, v3);
        }
    }
}

// ---------------- top-NBR selection ----------------
__global__ void k_sel() {
    int cl = blockIdx.x;
    int b = cl / KC, k = cl % KC;
    int s = g_cstart[b][k], e = g_cstart[b][k + 1];
    int n = min(e - s, SMAX);
    int base = b * NPIX + s;
    int warp = threadIdx.x >> 5, lane = threadIdx.x & 31;
    int cnt = n < NBR ? n : NBR;
    const float* Sp = g_S + (size_t)cl * SMAX * SMAX;

    for (int i = warp; i < n; i += 8) {
        const float* row = Sp + (size_t)i * SMAX;
        float v[12];
#pragma unroll
        for (int q = 0; q < 12; q++) {
            int j = q * 32 + lane;
            v[q] = (j < n) ? row[j] : -CUDART_INF_F;
        }
        int lastbj = 0;
        for (int r = 0; r < cnt; r++) {
            float best = -CUDART_INF_F;
            int bj = SMAX * 32;
#pragma unroll
            for (int q = 0; q < 12; q++) {
                if (v[q] > best) { best = v[q]; bj = q * 32 + lane; }
            }
#pragma unroll
            for (int off = 16; off; off >>= 1) {
                float ov = __shfl_down_sync(0xffffffffu, best, off);
                int   oj = __shfl_down_sync(0xffffffffu, bj, off);
                if (ov > best || (ov == best && oj < bj)) { best = ov; bj = oj; }
            }
            bj = __shfl_sync(0xffffffffu, bj, 0);
            if (lane == (bj & 31)) v[bj >> 5] = -CUDART_INF_F;
            if (lane == 0) g_nbr[(size_t)(base + i) * NBR + r] = base + bj;
            lastbj = bj;
        }
        if (lane == 0)
            for (int r = cnt; r < NBR; r++)
                g_nbr[(size_t)(base + i) * NBR + r] = base + lastbj;
    }
}

// ---------------- fused centroid + cluster MLP: one block per (b,k) ----------------
__global__ void __launch_bounds__(256) k_cenmlp() {
    int bk = blockIdx.x;
    int b = bk / KC, k = bk % KC;
    int s = g_cstart[b][k], e = g_cstart[b][k + 1];
    __shared__ float cen[CH];
    int t = threadIdx.x;
    if (t < CH) {
        float sum = 0.f;
        for (int p = s; p < e; p++)
            sum += __bfloat162float(g_xsh[((size_t)b * NPIX + p) * CH + t]);
        cen[t] = sum / (float)max(e - s, 1);
    }
    __syncthreads();
    // each thread computes 3 outputs of NCAT=768
    for (int o = t; o < NCAT; o += 256) {
        float acc = g_bias_c2[o];
        for (int kk = 0; kk < CH; kk++)
            acc += cen[kk] * g_Wc2[kk * NCAT + o];
        g_AcBc[(size_t)bk * NCAT + o] = acc;
    }
}

__global__ void k_cmax() {
    int idx = blockIdx.x * blockDim.x + threadIdx.x;
    if (idx >= BATCH * KC * CO) return;
    int c = idx % CO;
    int bk = idx / CO;
    int b = bk / KC;
    float a = g_AcBc[(size_t)bk * NCAT + c];
    float mn = CUDART_INF_F, mx = -CUDART_INF_F;
#pragma unroll
    for (int j = 0; j < KC; j++) {
        float xv = a + g_AcBc[(size_t)(b * KC + j) * NCAT + CO + c];
        mn = fminf(mn, xv);
        mx = fmaxf(mx, xv);
    }
    g_hc[idx] = gelu_max2(mn, mx);
}

// ---------------- aggregate: valley-extremes gelu-max over 9 neighbors ----------------
__global__ void k_aggregate() {
    int p = blockIdx.x;
    int b = p / NPIX;
    int lsk = g_ls[p];
    int dst = b * NPIX + g_order[p];
    __shared__ int nbrs[NBR];
    if (threadIdx.x < NBR) nbrs[threadIdx.x] = g_nbr[(size_t)p * NBR + threadIdx.x];
    __syncthreads();
    int c = threadIdx.x * 2;
    __nv_bfloat162 av = *(const __nv_bfloat162*)&g_ABh[(size_t)p * NCAT + c];
    float a0 = __bfloat162float(av.x), a1 = __bfloat162float(av.y);
    float2 hc2 = *(const float2*)&g_hc[((size_t)b * KC + lsk) * CO + c];
    float mn0 = CUDART_INF_F, mx0 = -CUDART_INF_F;
    float mn1 = CUDART_INF_F, mx1 = -CUDART_INF_F;
    int nb[NBR];
#pragma unroll
    for (int r = 0; r < NBR; r++) nb[r] = nbrs[r];
#pragma unroll
    for (int r = 0; r < NBR; r++) {
        __nv_bfloat162 bv = *(const __nv_bfloat162*)&g_ABh[(size_t)nb[r] * NCAT + CO + c];
        float x0 = __bfloat162float(bv.x);
        float x1 = __bfloat162float(bv.y);
        mn0 = fminf(mn0, x0); mx0 = fmaxf(mx0, x0);
        mn1 = fminf(mn1, x1); mx1 = fmaxf(mx1, x1);
    }
    float m0 = gelu_max2(a0 + mn0, a0 + mx0);
    float m1 = gelu_max2(a1 + mn1, a1 + mx1);
    __nv_bfloat162 out;
    out.x = __float2bfloat16(m0 + hc2.x);
    out.y = __float2bfloat16(m1 + hc2.y);
    *(__nv_bfloat162*)&g_hnh[(size_t)dst * CO + c] = out;
}

// ---------------- launch (serial, single stream) ----------------
extern "C" void kernel_launch(void* const* d_in, const int* in_sizes, int n_in,
                              void* d_out, int out_size) {
    const float* x      = (const float*)d_in[0];
    const int*   labels = (const int*)  d_in[1];
    const float* cpe_w  = (const float*)d_in[2];
    const float* cpe_b  = (const float*)d_in[3];
    const float* fc1_w  = (const float*)d_in[4];
    const float* fc1_b  = (const float*)d_in[5];
    const float* nn_v_w = (const float*)d_in[6];
    const float* nn_v_b = (const float*)d_in[7];
    const float* nn_c_w = (const float*)d_in[8];
    const float* nn_c_b = (const float*)d_in[9];
    const float* fc2_w  = (const float*)d_in[10];
    const float* fc2_b  = (const float*)d_in[11];
    float* y = (float*)d_out;

    float *p_xa, *p_xf;
    __nv_bfloat16 *p_xth, *p_xtl, *p_xsh, *p_hnh, *p_Wvt, *p_W2t, *p_W1h, *p_W1l, *p_ABh;
    float *p_bcat;
    cudaGetSymbolAddress((void**)&p_xa,   g_xa);
    cudaGetSymbolAddress((void**)&p_xf,   g_xf);
    cudaGetSymbolAddress((void**)&p_bcat, g_bias_cat);
    cudaGetSymbolAddress((void**)&p_xth,  g_xt_hi);
    cudaGetSymbolAddress((void**)&p_xtl,  g_xt_lo);
    cudaGetSymbolAddress((void**)&p_xsh,  g_xsh);
    cudaGetSymbolAddress((void**)&p_hnh,  g_hnh);
    cudaGetSymbolAddress((void**)&p_Wvt,  g_Wvt);
    cudaGetSymbolAddress((void**)&p_W2t,  g_W2t);
    cudaGetSymbolAddress((void**)&p_W1h,  g_W1t_hi);
    cudaGetSymbolAddress((void**)&p_W1l,  g_W1t_lo);
    cudaGetSymbolAddress((void**)&p_ABh,  g_ABh);

    cudaFuncSetAttribute(k_hgemm3_db, cudaFuncAttributeMaxDynamicSharedMemorySize, 61440);
    cudaFuncSetAttribute(k_gram,      cudaFuncAttributeMaxDynamicSharedMemorySize, 66048);
    cudaFuncSetAttribute(k_hgemm_db<128,1>, cudaFuncAttributeMaxDynamicSharedMemorySize, 40960);
    cudaFuncSetAttribute(k_hgemm_db<64,2>,  cudaFuncAttributeMaxDynamicSharedMemorySize, 34048);

    k_sortprep<<<8 + (NCAT * CH + 255) / 256, 256>>>(labels, nn_v_w, nn_c_w, fc2_w, fc1_w, nn_v_b, nn_c_b);
    k_dwconv<<<dim3(4, BATCH * CH), 256>>>(x, cpe_w, cpe_b);
    k_transpose_cn<<<dim3(NPIX / 32, CH / 32, BATCH), dim3(32, 8)>>>(p_xa);

    // fc1 split-bf16 (contiguous rows, unsorted out)
    k_hgemm3_db<<<dim3(CH / 64, BN / 128), 256, 61440>>>(p_xth, p_xtl, p_W1h, p_W1l, fc1_b, p_xf, BN, CH, CH);
    // gather into sorted order + norm (one pass)
    k_gather_norm<<<BN / 8, 256>>>();

    // gram smem: max(2 stages * 2*A1 = 40960, epilogue 128*129*4 = 66048)
    k_gram<<<dim3(6, 1, BATCH * KC), 256, 66048>>>();
    k_sel<<<BATCH * KC, 256>>>();

    // [A|Bv]: (25088,192)x(192,768) -> bf16
    k_hgemm_db<128,1><<<dim3(NCAT / 128, BN / 128), 256, 40960>>>(p_xsh, p_Wvt, p_bcat, nullptr, p_ABh, nullptr, BN, CH, NCAT);

    k_cenmlp<<<BATCH * KC, 256>>>();
    k_cmax<<<(BATCH * KC * CO + 255) / 256, 256>>>();

    k_aggregate<<<BN, CO / 2>>>();

    // fc2 fused: (25088,384)x(384,192) -> transpose + shortcut -> y
    k_hgemm_db<64,2><<<dim3(CH / 64, BN / 128), 256, 34048>>>(p_hnh, p_W2t, fc2_b, y, nullptr, x, BN, CO, CH);
}

// round 14
// speedup vs baseline: 1.6155x; 1.0390x over previous
#include <cuda_runtime.h>
#include <cuda_bf16.h>
#include <math_constants.h>
#include <cstdint>

#define BATCH 8
#define CH    192
#define HH    56
#define WW    56
#define NPIX  3136
#define KC    16
#define NBR   9
#define CO    384
#define NCAT  768
#define BN    (BATCH*NPIX)  // 25088
#define SMAX  384

// ---------------- scratch ----------------
__device__ __align__(128) float g_xa[BATCH*CH*NPIX];
__device__ __align__(128) __nv_bfloat16 g_xt_hi[BN*CH];
__device__ __align__(128) __nv_bfloat16 g_xt_lo[BN*CH];
__device__ __align__(128) float g_xf[BN*CH];            // fc1 out (UNSORTED rows)
__device__ __align__(128) __nv_bfloat16 g_xsh[BN*CH];   // sorted rows bf16
__device__ __align__(128) __nv_bfloat16 g_xe_hi[BN*CH]; // normalized sorted rows bf16
__device__ __align__(128) __nv_bfloat16 g_ABh[(size_t)BN*NCAT]; // [A | Bv] bf16 (sorted)
__device__ __align__(128) float g_S[(size_t)BATCH*KC*SMAX*SMAX];
__device__ __align__(128) __nv_bfloat16 g_hnh[BN*CO];   // aggregated, UNSORTED rows
__device__ int   g_order[BN];
__device__ int   g_ls[BN];
__device__ int   g_cstart[BATCH][KC+1];
__device__ int   g_nbr[BN*NBR];
__device__ __align__(128) float g_AcBc[BATCH*KC*NCAT];
__device__ __align__(128) float g_hc[BATCH*KC*CO];
__device__ __align__(128) float g_Wc2[CH*NCAT];
__device__ __align__(128) __nv_bfloat16 g_Wvt[NCAT*CH];
__device__ __align__(128) __nv_bfloat16 g_W2t[CH*CO];
__device__ __align__(128) __nv_bfloat16 g_W1t_hi[CH*CH];
__device__ __align__(128) __nv_bfloat16 g_W1t_lo[CH*CH];
__device__ __align__(128) float g_bias_cat[NCAT];
__device__ __align__(128) float g_bias_c2[NCAT];

__device__ __forceinline__ float gelu_f(float x) {
    float u = 0.7978845608028654f * (x + 0.044715f * x * x * x);
    float t;
    asm("tanh.approx.f32 %0, %1;" : "=f"(t) : "f"(u));
    return 0.5f * x * (1.0f + t);
}
__device__ __forceinline__ float gelu_max2(float mn, float mx) {
    return fmaxf(gelu_f(mn), gelu_f(mx));
}
__device__ __forceinline__ void split_bf16(float v, __nv_bfloat16& hi, __nv_bfloat16& lo) {
    hi = __float2bfloat16(v);
    lo = __float2bfloat16(v - __bfloat162float(hi));
}
__device__ __forceinline__ void cp16(void* dst, const void* src) {
    uint32_t d = (uint32_t)__cvta_generic_to_shared(dst);
    asm volatile("cp.async.ca.shared.global [%0], [%1], 16;\n" :: "r"(d), "l"(src));
}
__device__ __forceinline__ uint32_t smaddr(const void* p) {
    return (uint32_t)__cvta_generic_to_shared(p);
}
#define CP_COMMIT() asm volatile("cp.async.commit_group;\n")
#define CP_WAIT1()  asm volatile("cp.async.wait_group 1;\n")
#define CP_WAIT0()  asm volatile("cp.async.wait_group 0;\n")

#define MMA_BF16(acc, a0, a1, a2, a3, b0, b1) \
    asm volatile( \
        "mma.sync.aligned.m16n8k16.row.col.f32.bf16.bf16.f32 " \
        "{%0,%1,%2,%3}, {%4,%5,%6,%7}, {%8,%9}, {%0,%1,%2,%3};\n" \
        : "+f"(acc[0]), "+f"(acc[1]), "+f"(acc[2]), "+f"(acc[3]) \
        : "r"(a0), "r"(a1), "r"(a2), "r"(a3), "r"(b0), "r"(b1))

#define LDSM_X4(d0, d1, d2, d3, a) \
    asm volatile("ldmatrix.sync.aligned.m8n8.x4.shared.b16 {%0,%1,%2,%3}, [%4];" \
        : "=r"(d0), "=r"(d1), "=r"(d2), "=r"(d3) : "r"(a))

// ---------------- merged sort (blocks 0..7) + weight prep (blocks 8..) ----------------
#define CHUNK 13
__global__ void k_sortprep(const int* __restrict__ labels,
                           const float* __restrict__ wv, const float* __restrict__ wc,
                           const float* __restrict__ w2, const float* __restrict__ w1,
                           const float* __restrict__ vb, const float* __restrict__ cbias) {
    if (blockIdx.x >= 8) {
        int i = (blockIdx.x - 8) * 256 + threadIdx.x;
        if (i < NCAT * CH) {
            int n = i / CH, k = i % CH;
            float v;
            if (n < CO) v = wv[k * CO + n] - wv[(CH + k) * CO + n];
            else        v = wv[(CH + k) * CO + (n - CO)];
            g_Wvt[n * CH + k] = __float2bfloat16(v);
            int k2 = i / NCAT, n2 = i % NCAT;
            float vc;
            if (n2 < CO) vc = wc[k2 * CO + n2] - wc[(CH + k2) * CO + n2];
            else         vc = wc[(CH + k2) * CO + (n2 - CO)];
            g_Wc2[i] = vc;
        }
        if (i < CH * CO) {
            int n = i / CO, k = i % CO;
            g_W2t[n * CO + k] = __float2bfloat16(w2[k * CH + n]);
        }
        if (i < CH * CH) {
            int n = i / CH, k = i % CH;
            __nv_bfloat16 hi, lo;
            split_bf16(w1[k * CH + n], hi, lo);
            g_W1t_hi[n * CH + k] = hi;
            g_W1t_lo[n * CH + k] = lo;
        }
        if (i < NCAT) {
            g_bias_cat[i] = (i < CO) ? vb[i] : 0.f;
            g_bias_c2[i]  = (i < CO) ? cbias[i] : 0.f;
        }
        return;
    }
    int b = blockIdx.x;
    const int* lab = labels + b * NPIX;
    __shared__ int slab[NPIX];
    __shared__ int cnt[KC][257];
    __shared__ int start[KC + 1];
    int t = threadIdx.x;
    for (int i = t; i < NPIX; i += 256) slab[i] = lab[i];
    __syncthreads();
    int lo = t * CHUNK;
    int hi = min(lo + CHUNK, NPIX);
    int local[KC];
#pragma unroll
    for (int k = 0; k < KC; k++) local[k] = 0;
    for (int i = lo; i < hi; i++) local[slab[i]]++;
#pragma unroll
    for (int k = 0; k < KC; k++) cnt[k][t + 1] = local[k];
    if (t < KC) cnt[t][0] = 0;
    __syncthreads();
    if (t < KC) {
        int s = 0;
        for (int j = 1; j <= 256; j++) { s += cnt[t][j]; cnt[t][j] = s; }
    }
    __syncthreads();
    if (t == 0) {
        int s = 0;
        for (int k = 0; k < KC; k++) { start[k] = s; s += cnt[k][256]; }
        start[KC] = s;
        for (int k = 0; k <= KC; k++) g_cstart[b][k] = start[k];
    }
    __syncthreads();
    int ofs[KC];
#pragma unroll
    for (int k = 0; k < KC; k++) ofs[k] = start[k] + cnt[k][t];
    for (int i = lo; i < hi; i++) {
        int l = slab[i];
        int p = ofs[l]++;
        g_order[b * NPIX + p] = i;
        g_ls[b * NPIX + p] = l;
    }
}

// ---------------- dwconv 7x7: smem halo tile, 4 outputs/thread ----------------
__global__ void k_dwconv(const float* __restrict__ x, const float* __restrict__ cw,
                         const float* __restrict__ cb) {
    int bc = blockIdx.y;
    int c  = bc % CH;
    int tile = blockIdx.x;
    int ty0 = (tile >> 1) * 32, tx0 = (tile & 1) * 32;
    __shared__ float sh[38][41];
    __shared__ float wsh[49];
    if (threadIdx.x < 49) wsh[threadIdx.x] = cw[c * 49 + threadIdx.x];
    const float* src = x + (size_t)bc * NPIX;
    for (int l = threadIdx.x; l < 38 * 38; l += 256) {
        int r = l / 38, cc = l % 38;
        int h = ty0 + r - 3, w = tx0 + cc - 3;
        sh[r][cc] = (h >= 0 && h < HH && w >= 0 && w < WW) ? src[h * WW + w] : 0.f;
    }
    __syncthreads();
    int ty = threadIdx.x >> 3;
    int xg = threadIdx.x & 7;
    int h = ty0 + ty;
    int wbase = tx0 + xg * 4;
    if (h < HH) {
        float acc[4] = {0.f, 0.f, 0.f, 0.f};
#pragma unroll
        for (int kh = 0; kh < 7; kh++) {
            float rr[10];
#pragma unroll
            for (int q = 0; q < 10; q++) rr[q] = sh[ty + kh][xg * 4 + q];
#pragma unroll
            for (int kw = 0; kw < 7; kw++) {
                float wv = wsh[kh * 7 + kw];
                acc[0] += rr[kw] * wv;     acc[1] += rr[kw + 1] * wv;
                acc[2] += rr[kw + 2] * wv; acc[3] += rr[kw + 3] * wv;
            }
        }
        float bb = cb[c];
#pragma unroll
        for (int o = 0; o < 4; o++) {
            int w = wbase + o;
            if (w < WW)
                g_xa[(size_t)bc * NPIX + h * WW + w] = acc[o] + bb + sh[ty + 3][xg * 4 + o + 3];
        }
    }
}

// transpose (B,C,N)->(B,N,C), split bf16
__global__ void k_transpose_cn(const float* __restrict__ in) {
    int b = blockIdx.z;
    int n0 = blockIdx.x * 32, c0 = blockIdx.y * 32;
    __shared__ float t[32][33];
    const float* ip = in + (size_t)b * CH * NPIX;
#pragma unroll
    for (int q = 0; q < 4; q++) {
        int cc = c0 + threadIdx.y + q * 8;
        t[threadIdx.y + q * 8][threadIdx.x] = ip[(size_t)cc * NPIX + n0 + threadIdx.x];
    }
    __syncthreads();
#pragma unroll
    for (int q = 0; q < 4; q++) {
        int nn = n0 + threadIdx.y + q * 8;
        size_t o = ((size_t)b * NPIX + nn) * CH + c0 + threadIdx.x;
        __nv_bfloat16 hi, lo;
        split_bf16(t[threadIdx.x][threadIdx.y + q * 8], hi, lo);
        g_xt_hi[o] = hi;
        g_xt_lo[o] = lo;
    }
}

// ---------------- double-buffered bf16 tensor GEMM (ldmatrix fragments) ----------------
// MODE 1: bf16 out (AB).  MODE 2: fc2 fused epilogue: transpose + shortcut -> y.
template<int NT, int MODE>
__global__ void __launch_bounds__(256) k_hgemm_db(
        const __nv_bfloat16* __restrict__ X, const __nv_bfloat16* __restrict__ Wt,
        const float* __restrict__ bias, float* __restrict__ Yf,
        __nv_bfloat16* __restrict__ Ybf, const float* __restrict__ shortcut,
        int M, int K, int Nn) {
    extern __shared__ char sm_[];
    constexpr int ASZ = 128 * 40 * 2;
    constexpr int BSZ = NT * 40 * 2;
    constexpr int STG = ASZ + BSZ;
    int bm = blockIdx.y * 128, bn = blockIdx.x * NT;
    int tid = threadIdx.x, warp = tid >> 5, lane = tid & 31;
    int wm = warp & 3, wn = warp >> 2;
    int g = lane >> 2, tg = lane & 3;
    constexpr int NI = NT / 16;
    int arow = ((lane & 15) >> 3) * 8 + (lane & 7);
    int acol = (lane >> 4) * 8;
    int brow = (lane >> 4) * 8 + (lane & 7);
    int bcol = ((lane >> 3) & 1) * 8;
    float acc[2][NI][4];
#pragma unroll
    for (int im = 0; im < 2; im++)
#pragma unroll
        for (int in = 0; in < NI; in++)
#pragma unroll
            for (int q = 0; q < 4; q++) acc[im][in][q] = 0.f;

    int KT = K / 32;
#pragma unroll 1
    for (int kt = -1; kt < KT; kt++) {
        int lt = kt + 1;
        if (lt < KT) {
            int s = lt & 1;
            __nv_bfloat16 (*As)[40] = (__nv_bfloat16(*)[40])(sm_ + s * STG);
            __nv_bfloat16 (*Bs)[40] = (__nv_bfloat16(*)[40])(sm_ + s * STG + ASZ);
            int k0 = lt * 32;
#pragma unroll
            for (int c = 0; c < 2; c++) {
                int ch = tid + c * 256;
                int row = ch >> 2, part = ch & 3;
                cp16(&As[row][part * 8], X + (size_t)(bm + row) * K + k0 + part * 8);
            }
#pragma unroll
            for (int c = 0; c < NT / 64; c++) {
                int ch = tid + c * 256;
                int row = ch >> 2, part = ch & 3;
                cp16(&Bs[row][part * 8], Wt + (size_t)(bn + row) * K + k0 + part * 8);
            }
            CP_COMMIT();
        }
        if (kt < 0) continue;
        if (kt + 1 < KT) CP_WAIT1(); else CP_WAIT0();
        __syncthreads();
        int s = kt & 1;
        __nv_bfloat16 (*As)[40] = (__nv_bfloat16(*)[40])(sm_ + s * STG);
        __nv_bfloat16 (*Bs)[40] = (__nv_bfloat16(*)[40])(sm_ + s * STG + ASZ);
#pragma unroll
        for (int kk = 0; kk < 32; kk += 16) {
            uint32_t a[2][4], bf[NI][2];
#pragma unroll
            for (int im = 0; im < 2; im++) {
                uint32_t ad = smaddr(&As[wm * 32 + im * 16 + arow][kk + acol]);
                LDSM_X4(a[im][0], a[im][1], a[im][2], a[im][3], ad);
            }
#pragma unroll
            for (int i2 = 0; i2 < NI / 2; i2++) {
                uint32_t bd = smaddr(&Bs[wn * (NT / 2) + i2 * 16 + brow][kk + bcol]);
                LDSM_X4(bf[2 * i2][0], bf[2 * i2][1], bf[2 * i2 + 1][0], bf[2 * i2 + 1][1], bd);
            }
#pragma unroll
            for (int im = 0; im < 2; im++)
#pragma unroll
                for (int in = 0; in < NI; in++)
                    MMA_BF16(acc[im][in], a[im][0], a[im][1], a[im][2], a[im][3],
                             bf[in][0], bf[in][1]);
        }
        __syncthreads();
    }
    if (MODE == 1) {
#pragma unroll
        for (int im = 0; im < 2; im++)
#pragma unroll
            for (int in = 0; in < NI; in++) {
                int row = bm + wm * 32 + im * 16 + g;
                int col = bn + wn * (NT / 2) + in * 8 + tg * 2;
                float b0 = bias[col], b1 = bias[col + 1];
                __nv_bfloat162 h0, h1;
                h0.x = __float2bfloat16(acc[im][in][0] + b0);
                h0.y = __float2bfloat16(acc[im][in][1] + b1);
                h1.x = __float2bfloat16(acc[im][in][2] + b0);
                h1.y = __float2bfloat16(acc[im][in][3] + b1);
                *(__nv_bfloat162*)&Ybf[(size_t)row * Nn + col] = h0;
                *(__nv_bfloat162*)&Ybf[(size_t)(row + 8) * Nn + col] = h1;
            }
    } else {
        float* smf = (float*)sm_;            // [NT][132]
#pragma unroll
        for (int im = 0; im < 2; im++)
#pragma unroll
            for (int in = 0; in < NI; in++) {
                int r = wm * 32 + im * 16 + g;
                int cc = wn * (NT / 2) + in * 8 + tg * 2;
                float b0 = bias[bn + cc], b1 = bias[bn + cc + 1];
                smf[cc * 132 + r]           = acc[im][in][0] + b0;
                smf[(cc + 1) * 132 + r]     = acc[im][in][1] + b1;
                smf[cc * 132 + r + 8]       = acc[im][in][2] + b0;
                smf[(cc + 1) * 132 + r + 8] = acc[im][in][3] + b1;
            }
        __syncthreads();
        for (int cc = warp; cc < NT; cc += 8) {
            float4 v = *(float4*)&smf[cc * 132 + lane * 4];
            int p = bm + lane * 4;
            int b = p / NPIX;
            int n = p - b * NPIX;
            size_t o = ((size_t)b * CH + bn + cc) * NPIX + n;
            float4 xv = *(const float4*)(shortcut + o);
            v.x += xv.x; v.y += xv.y; v.z += xv.z; v.w += xv.w;
            *(float4*)(Yf + o) = v;
        }
    }
}

// ---------------- double-buffered split-bf16 GEMM (fc1, ldmatrix fragments) ----------------
__global__ void __launch_bounds__(256) k_hgemm3_db(
        const __nv_bfloat16* __restrict__ Xhi, const __nv_bfloat16* __restrict__ Xlo,
        const __nv_bfloat16* __restrict__ Whi, const __nv_bfloat16* __restrict__ Wlo,
        const float* __restrict__ bias, float* __restrict__ Y,
        int M, int K, int Nn) {
    extern __shared__ char sm_[];
    constexpr int A1 = 128 * 40 * 2;
    constexpr int B1 = 64 * 40 * 2;
    constexpr int STG = 2 * A1 + 2 * B1;
    int bm = blockIdx.y * 128, bn = blockIdx.x * 64;
    int tid = threadIdx.x, warp = tid >> 5, lane = tid & 31;
    int wm = warp & 3, wn = warp >> 2;
    int g = lane >> 2, tg = lane & 3;
    int arow = ((lane & 15) >> 3) * 8 + (lane & 7);
    int acol = (lane >> 4) * 8;
    int brow = (lane >> 4) * 8 + (lane & 7);
    int bcol = ((lane >> 3) & 1) * 8;
    float acc[2][4][4];
#pragma unroll
    for (int im = 0; im < 2; im++)
#pragma unroll
        for (int in = 0; in < 4; in++)
#pragma unroll
            for (int q = 0; q < 4; q++) acc[im][in][q] = 0.f;

    int KT = K / 32;
#pragma unroll 1
    for (int kt = -1; kt < KT; kt++) {
        int lt = kt + 1;
        if (lt < KT) {
            int s = lt & 1;
            char* base = sm_ + s * STG;
            __nv_bfloat16 (*Ah)[40] = (__nv_bfloat16(*)[40])(base);
            __nv_bfloat16 (*Al)[40] = (__nv_bfloat16(*)[40])(base + A1);
            __nv_bfloat16 (*Bh)[40] = (__nv_bfloat16(*)[40])(base + 2 * A1);
            __nv_bfloat16 (*Bl)[40] = (__nv_bfloat16(*)[40])(base + 2 * A1 + B1);
            int k0 = lt * 32;
#pragma unroll
            for (int c = 0; c < 2; c++) {
                int ch = tid + c * 256;
                int row = ch >> 2, part = ch & 3;
                size_t ofs = (size_t)(bm + row) * K + k0 + part * 8;
                cp16(&Ah[row][part * 8], Xhi + ofs);
                cp16(&Al[row][part * 8], Xlo + ofs);
            }
            {
                int row = tid >> 2, part = tid & 3;
                size_t ofs = (size_t)(bn + row) * K + k0 + part * 8;
                cp16(&Bh[row][part * 8], Whi + ofs);
                cp16(&Bl[row][part * 8], Wlo + ofs);
            }
            CP_COMMIT();
        }
        if (kt < 0) continue;
        if (kt + 1 < KT) CP_WAIT1(); else CP_WAIT0();
        __syncthreads();
        int s = kt & 1;
        char* base = sm_ + s * STG;
        __nv_bfloat16 (*Ah)[40] = (__nv_bfloat16(*)[40])(base);
        __nv_bfloat16 (*Al)[40] = (__nv_bfloat16(*)[40])(base + A1);
        __nv_bfloat16 (*Bh)[40] = (__nv_bfloat16(*)[40])(base + 2 * A1);
        __nv_bfloat16 (*Bl)[40] = (__nv_bfloat16(*)[40])(base + 2 * A1 + B1);
#pragma unroll
        for (int kk = 0; kk < 32; kk += 16) {
            uint32_t ah[2][4], al[2][4], bh[4][2], bl[4][2];
#pragma unroll
            for (int im = 0; im < 2; im++) {
                uint32_t adh = smaddr(&Ah[wm * 32 + im * 16 + arow][kk + acol]);
                LDSM_X4(ah[im][0], ah[im][1], ah[im][2], ah[im][3], adh);
                uint32_t adl = smaddr(&Al[wm * 32 + im * 16 + arow][kk + acol]);
                LDSM_X4(al[im][0], al[im][1], al[im][2], al[im][3], adl);
            }
#pragma unroll
            for (int i2 = 0; i2 < 2; i2++) {
                uint32_t bdh = smaddr(&Bh[wn * 32 + i2 * 16 + brow][kk + bcol]);
                LDSM_X4(bh[2 * i2][0], bh[2 * i2][1], bh[2 * i2 + 1][0], bh[2 * i2 + 1][1], bdh);
                uint32_t bdl = smaddr(&Bl[wn * 32 + i2 * 16 + brow][kk + bcol]);
                LDSM_X4(bl[2 * i2][0], bl[2 * i2][1], bl[2 * i2 + 1][0], bl[2 * i2 + 1][1], bdl);
            }
#pragma unroll
            for (int im = 0; im < 2; im++)
#pragma unroll
                for (int in = 0; in < 4; in++) {
                    MMA_BF16(acc[im][in], ah[im][0], ah[im][1], ah[im][2], ah[im][3],
                             bh[in][0], bh[in][1]);
                    MMA_BF16(acc[im][in], ah[im][0], ah[im][1], ah[im][2], ah[im][3],
                             bl[in][0], bl[in][1]);
                    MMA_BF16(acc[im][in], al[im][0], al[im][1], al[im][2], al[im][3],
                             bh[in][0], bh[in][1]);
                }
        }
        __syncthreads();
    }
#pragma unroll
    for (int im = 0; im < 2; im++)
#pragma unroll
        for (int in = 0; in < 4; in++) {
            int row = bm + wm * 32 + im * 16 + g;
            int col = bn + wn * 32 + in * 8 + tg * 2;
            float b0 = bias[col], b1 = bias[col + 1];
            *(float2*)&Y[(size_t)row * Nn + col] =
                make_float2(acc[im][in][0] + b0, acc[im][in][1] + b1);
            *(float2*)&Y[(size_t)(row + 8) * Nn + col] =
                make_float2(acc[im][in][2] + b0, acc[im][in][3] + b1);
        }
}

// ---------------- gather + normalize (bf16 hi only) ----------------
__global__ void k_gather_norm() {
    int warp = threadIdx.x >> 5, lane = threadIdx.x & 31;
    int p = blockIdx.x * 8 + warp;
    if (p >= BN) return;
    int b = p / NPIX;
    int src = g_order[p];
    const float* in = g_xf + ((size_t)b * NPIX + src) * CH;
    float v[6];
    float ss = 0.f;
#pragma unroll
    for (int q = 0; q < 6; q++) { v[q] = in[lane + q * 32]; ss += v[q] * v[q]; }
#pragma unroll
    for (int off = 16; off; off >>= 1) ss += __shfl_xor_sync(0xffffffffu, ss, off);
    float inv = 1.f / fmaxf(sqrtf(ss), 1e-12f);
    size_t base = (size_t)p * CH;
#pragma unroll
    for (int q = 0; q < 6; q++) {
        int c = lane + q * 32;
        g_xsh[base + c] = __float2bfloat16(v[q]);
        g_xe_hi[base + c] = __float2bfloat16(v[q] * inv);
    }
}

// ---------------- gram body (single bf16 MMA, symmetric pairs, ldmatrix) ----------------
__device__ __forceinline__ void gram_body(int pi, int cl, char* sm_) {
    int b = cl / KC, k = cl % KC;
    int s0 = g_cstart[b][k], e0 = g_cstart[b][k + 1];
    int n = min(e0 - s0, SMAX);
    const int TI[6] = {0, 0, 0, 1, 1, 2};
    const int TJ[6] = {0, 1, 2, 1, 2, 2};
    int ti = TI[pi], tj = TJ[pi];
    if (ti * 128 >= n || tj * 128 >= n) return;
    int base = b * NPIX + s0;

    constexpr int A1 = 128 * 40 * 2;
    constexpr int STG = 2 * A1;
    int tid = threadIdx.x;
    int warp = tid >> 5, lane = tid & 31;
    int wm = warp & 3, wn = warp >> 2;
    int g = lane >> 2, tg = lane & 3;
    int arow = ((lane & 15) >> 3) * 8 + (lane & 7);
    int acol = (lane >> 4) * 8;
    int brow = (lane >> 4) * 8 + (lane & 7);
    int bcol = ((lane >> 3) & 1) * 8;
    float acc[2][8][4];
#pragma unroll
    for (int im = 0; im < 2; im++)
#pragma unroll
        for (int in = 0; in < 8; in++)
#pragma unroll
            for (int q = 0; q < 4; q++) acc[im][in][q] = 0.f;

    int KT = CH / 32;
#pragma unroll 1
    for (int kt = -1; kt < KT; kt++) {
        int lt = kt + 1;
        if (lt < KT) {
            int s = lt & 1;
            char* bb = sm_ + s * STG;
            __nv_bfloat16 (*Ah)[40] = (__nv_bfloat16(*)[40])(bb);
            __nv_bfloat16 (*Bh)[40] = (__nv_bfloat16(*)[40])(bb + A1);
            int k0 = lt * 32;
#pragma unroll
            for (int c = 0; c < 2; c++) {
                int ch = tid + c * 256;
                int row = ch >> 2, part = ch & 3;
                int ra = min(base + ti * 128 + row, BN - 1);
                int rb = min(base + tj * 128 + row, BN - 1);
                cp16(&Ah[row][part * 8], g_xe_hi + (size_t)ra * CH + k0 + part * 8);
                cp16(&Bh[row][part * 8], g_xe_hi + (size_t)rb * CH + k0 + part * 8);
            }
            CP_COMMIT();
        }
        if (kt < 0) continue;
        if (kt + 1 < KT) CP_WAIT1(); else CP_WAIT0();
        __syncthreads();
        int s = kt & 1;
        char* bb = sm_ + s * STG;
        __nv_bfloat16 (*Ah)[40] = (__nv_bfloat16(*)[40])(bb);
        __nv_bfloat16 (*Bh)[40] = (__nv_bfloat16(*)[40])(bb + A1);
#pragma unroll
        for (int kk = 0; kk < 32; kk += 16) {
            uint32_t ah[2][4], bh[8][2];
#pragma unroll
            for (int im = 0; im < 2; im++) {
                uint32_t adh = smaddr(&Ah[wm * 32 + im * 16 + arow][kk + acol]);
                LDSM_X4(ah[im][0], ah[im][1], ah[im][2], ah[im][3], adh);
            }
#pragma unroll
            for (int i2 = 0; i2 < 4; i2++) {
                uint32_t bdh = smaddr(&Bh[wn * 64 + i2 * 16 + brow][kk + bcol]);
                LDSM_X4(bh[2 * i2][0], bh[2 * i2][1], bh[2 * i2 + 1][0], bh[2 * i2 + 1][1], bdh);
            }
#pragma unroll
            for (int im = 0; im < 2; im++)
#pragma unroll
                for (int in = 0; in < 8; in++)
                    MMA_BF16(acc[im][in], ah[im][0], ah[im][1], ah[im][2], ah[im][3],
                             bh[in][0], bh[in][1]);
        }
        __syncthreads();
    }
    float* Sp = g_S + (size_t)cl * SMAX * SMAX;
    float* smf = (float*)sm_;
#pragma unroll
    for (int im = 0; im < 2; im++)
#pragma unroll
        for (int in = 0; in < 8; in++) {
            int i0 = ti * 128 + wm * 32 + im * 16 + g;
            int j  = tj * 128 + wn * 64 + in * 8 + tg * 2;
            *(float2*)&Sp[(size_t)i0 * SMAX + j] = make_float2(acc[im][in][0], acc[im][in][1]);
            *(float2*)&Sp[(size_t)(i0 + 8) * SMAX + j] = make_float2(acc[im][in][2], acc[im][in][3]);
            if (ti != tj) {
                int il = wm * 32 + im * 16 + g;
                int jl = wn * 64 + in * 8 + tg * 2;
                smf[jl * 129 + il]           = acc[im][in][0];
                smf[(jl + 1) * 129 + il]     = acc[im][in][1];
                smf[jl * 129 + il + 8]       = acc[im][in][2];
                smf[(jl + 1) * 129 + il + 8] = acc[im][in][3];
            }
        }
    if (ti != tj) {
        __syncthreads();
        for (int jj = warp; jj < 128; jj += 8) {
            float v0 = smf[jj * 129 + lane * 4 + 0];
            float v1 = smf[jj * 129 + lane * 4 + 1];
            float v2 = smf[jj * 129 + lane * 4 + 2];
            float v3 = smf[jj * 129 + lane * 4 + 3];
            *(float4*)&Sp[(size_t)(tj * 128 + jj) * SMAX + ti * 128 + lane * 4] =
                make_float4(v0, v1, v2, v3);
        }
    }
}

// ---------------- AB body (128-wide bf16 GEMM, identical math to k_hgemm_db<128,1>) ----------------
__device__ __forceinline__ void ab_body(int bxi, int byi,
        const __nv_bfloat16* __restrict__ X, const __nv_bfloat16* __restrict__ Wt,
        const float* __restrict__ bias, __nv_bfloat16* __restrict__ Ybf, char* sm_) {
    constexpr int NT = 128;
    constexpr int ASZ = 128 * 40 * 2;
    constexpr int BSZ = NT * 40 * 2;
    constexpr int STG = ASZ + BSZ;
    constexpr int K = CH, Nn = NCAT;
    int bm = byi * 128, bn = bxi * NT;
    int tid = threadIdx.x, warp = tid >> 5, lane = tid & 31;
    int wm = warp & 3, wn = warp >> 2;
    int g = lane >> 2, tg = lane & 3;
    constexpr int NI = NT / 16;
    int arow = ((lane & 15) >> 3) * 8 + (lane & 7);
    int acol = (lane >> 4) * 8;
    int brow = (lane >> 4) * 8 + (lane & 7);
    int bcol = ((lane >> 3) & 1) * 8;
    float acc[2][NI][4];
#pragma unroll
    for (int im = 0; im < 2; im++)
#pragma unroll
        for (int in = 0; in < NI; in++)
#pragma unroll
            for (int q = 0; q < 4; q++) acc[im][in][q] = 0.f;

    int KT = K / 32;
#pragma unroll 1
    for (int kt = -1; kt < KT; kt++) {
        int lt = kt + 1;
        if (lt < KT) {
            int s = lt & 1;
            __nv_bfloat16 (*As)[40] = (__nv_bfloat16(*)[40])(sm_ + s * STG);
            __nv_bfloat16 (*Bs)[40] = (__nv_bfloat16(*)[40])(sm_ + s * STG + ASZ);
            int k0 = lt * 32;
#pragma unroll
            for (int c = 0; c < 2; c++) {
                int ch = tid + c * 256;
                int row = ch >> 2, part = ch & 3;
                cp16(&As[row][part * 8], X + (size_t)(bm + row) * K + k0 + part * 8);
            }
#pragma unroll
            for (int c = 0; c < NT / 64; c++) {
                int ch = tid + c * 256;
                int row = ch >> 2, part = ch & 3;
                cp16(&Bs[row][part * 8], Wt + (size_t)(bn + row) * K + k0 + part * 8);
            }
            CP_COMMIT();
        }
        if (kt < 0) continue;
        if (kt + 1 < KT) CP_WAIT1(); else CP_WAIT0();
        __syncthreads();
        int s = kt & 1;
        __nv_bfloat16 (*As)[40] = (__nv_bfloat16(*)[40])(sm_ + s * STG);
        __nv_bfloat16 (*Bs)[40] = (__nv_bfloat16(*)[40])(sm_ + s * STG + ASZ);
#pragma unroll
        for (int kk = 0; kk < 32; kk += 16) {
            uint32_t a[2][4], bf[NI][2];
#pragma unroll
            for (int im = 0; im < 2; im++) {
                uint32_t ad = smaddr(&As[wm * 32 + im * 16 + arow][kk + acol]);
                LDSM_X4(a[im][0], a[im][1], a[im][2], a[im][3], ad);
            }
#pragma unroll
            for (int i2 = 0; i2 < NI / 2; i2++) {
                uint32_t bd = smaddr(&Bs[wn * (NT / 2) + i2 * 16 + brow][kk + bcol]);
                LDSM_X4(bf[2 * i2][0], bf[2 * i2][1], bf[2 * i2 + 1][0], bf[2 * i2 + 1][1], bd);
            }
#pragma unroll
            for (int im = 0; im < 2; im++)
#pragma unroll
                for (int in = 0; in < NI; in++)
                    MMA_BF16(acc[im][in], a[im][0], a[im][1], a[im][2], a[im][3],
                             bf[in][0], bf[in][1]);
        }
        __syncthreads();
    }
#pragma unroll
    for (int im = 0; im < 2; im++)
#pragma unroll
        for (int in = 0; in < NI; in++) {
            int row = bm + wm * 32 + im * 16 + g;
            int col = bn + wn * (NT / 2) + in * 8 + tg * 2;
            float b0 = bias[col], b1 = bias[col + 1];
            __nv_bfloat162 h0, h1;
            h0.x = __float2bfloat16(acc[im][in][0] + b0);
            h0.y = __float2bfloat16(acc[im][in][1] + b1);
            h1.x = __float2bfloat16(acc[im][in][2] + b0);
            h1.y = __float2bfloat16(acc[im][in][3] + b1);
            *(__nv_bfloat162*)&Ybf[(size_t)row * Nn + col] = h0;
            *(__nv_bfloat162*)&Ybf[(size_t)(row + 8) * Nn + col] = h1;
        }
}

// ---------------- merged gram + AB dispatch (independent work, one launch) ----------------
#define GRAM_BLOCKS (6 * BATCH * KC)          // 768
#define AB_BLOCKS   ((NCAT / 128) * (BN / 128)) // 1176
__global__ void __launch_bounds__(256) k_gram_ab(
        const __nv_bfloat16* __restrict__ X, const __nv_bfloat16* __restrict__ Wt,
        const float* __restrict__ bias, __nv_bfloat16* __restrict__ Ybf) {
    extern __shared__ char sm_[];
    int bid = blockIdx.x;
    if (bid < GRAM_BLOCKS) {
        gram_body(bid % 6, bid / 6, sm_);
    } else {
        int t = bid - GRAM_BLOCKS;
        ab_body(t % (NCAT / 128), t / (NCAT / 128), X, Wt, bias, Ybf, sm_);
    }
}

// ---------------- top-NBR selection ----------------
__global__ void k_sel() {
    int cl = blockIdx.x;
    int b = cl / KC, k = cl % KC;
    int s = g_cstart[b][k], e = g_cstart[b][k + 1];
    int n = min(e - s, SMAX);
    int base = b * NPIX + s;
    int warp = threadIdx.x >> 5, lane = threadIdx.x & 31;
    int cnt = n < NBR ? n : NBR;
    const float* Sp = g_S + (size_t)cl * SMAX * SMAX;

    for (int i = warp; i < n; i += 8) {
        const float* row = Sp + (size_t)i * SMAX;
        float v[12];
#pragma unroll
        for (int q = 0; q < 12; q++) {
            int j = q * 32 + lane;
            v[q] = (j < n) ? row[j] : -CUDART_INF_F;
        }
        int lastbj = 0;
        for (int r = 0; r < cnt; r++) {
            float best = -CUDART_INF_F;
            int bj = SMAX * 32;
#pragma unroll
            for (int q = 0; q < 12; q++) {
                if (v[q] > best) { best = v[q]; bj = q * 32 + lane; }
            }
#pragma unroll
            for (int off = 16; off; off >>= 1) {
                float ov = __shfl_down_sync(0xffffffffu, best, off);
                int   oj = __shfl_down_sync(0xffffffffu, bj, off);
                if (ov > best || (ov == best && oj < bj)) { best = ov; bj = oj; }
            }
            bj = __shfl_sync(0xffffffffu, bj, 0);
            if (lane == (bj & 31)) v[bj >> 5] = -CUDART_INF_F;
            if (lane == 0) g_nbr[(size_t)(base + i) * NBR + r] = base + bj;
            lastbj = bj;
        }
        if (lane == 0)
            for (int r = cnt; r < NBR; r++)
                g_nbr[(size_t)(base + i) * NBR + r] = base + lastbj;
    }
}

// ---------------- fused centroid + cluster MLP: one block per (b,k) ----------------
__global__ void __launch_bounds__(256) k_cenmlp() {
    int bk = blockIdx.x;
    int b = bk / KC, k = bk % KC;
    int s = g_cstart[b][k], e = g_cstart[b][k + 1];
    __shared__ float cen[CH];
    int t = threadIdx.x;
    if (t < CH) {
        float sum = 0.f;
        for (int p = s; p < e; p++)
            sum += __bfloat162float(g_xsh[((size_t)b * NPIX + p) * CH + t]);
        cen[t] = sum / (float)max(e - s, 1);
    }
    __syncthreads();
    for (int o = t; o < NCAT; o += 256) {
        float acc = g_bias_c2[o];
        for (int kk = 0; kk < CH; kk++)
            acc += cen[kk] * g_Wc2[kk * NCAT + o];
        g_AcBc[(size_t)bk * NCAT + o] = acc;
    }
}

__global__ void k_cmax() {
    int idx = blockIdx.x * blockDim.x + threadIdx.x;
    if (idx >= BATCH * KC * CO) return;
    int c = idx % CO;
    int bk = idx / CO;
    int b = bk / KC;
    float a = g_AcBc[(size_t)bk * NCAT + c];
    float mn = CUDART_INF_F, mx = -CUDART_INF_F;
#pragma unroll
    for (int j = 0; j < KC; j++) {
        float xv = a + g_AcBc[(size_t)(b * KC + j) * NCAT + CO + c];
        mn = fminf(mn, xv);
        mx = fmaxf(mx, xv);
    }
    g_hc[idx] = gelu_max2(mn, mx);
}

// ---------------- aggregate: valley-extremes gelu-max over 9 neighbors ----------------
__global__ void k_aggregate() {
    int p = blockIdx.x;
    int b = p / NPIX;
    int lsk = g_ls[p];
    int dst = b * NPIX + g_order[p];
    __shared__ int nbrs[NBR];
    if (threadIdx.x < NBR) nbrs[threadIdx.x] = g_nbr[(size_t)p * NBR + threadIdx.x];
    __syncthreads();
    int c = threadIdx.x * 2;
    __nv_bfloat162 av = *(const __nv_bfloat162*)&g_ABh[(size_t)p * NCAT + c];
    float a0 = __bfloat162float(av.x), a1 = __bfloat162float(av.y);
    float2 hc2 = *(const float2*)&g_hc[((size_t)b * KC + lsk) * CO + c];
    float mn0 = CUDART_INF_F, mx0 = -CUDART_INF_F;
    float mn1 = CUDART_INF_F, mx1 = -CUDART_INF_F;
    int nb[NBR];
#pragma unroll
    for (int r = 0; r < NBR; r++) nb[r] = nbrs[r];
#pragma unroll
    for (int r = 0; r < NBR; r++) {
        __nv_bfloat162 bv = *(const __nv_bfloat162*)&g_ABh[(size_t)nb[r] * NCAT + CO + c];
        float x0 = __bfloat162float(bv.x);
        float x1 = __bfloat162float(bv.y);
        mn0 = fminf(mn0, x0); mx0 = fmaxf(mx0, x0);
        mn1 = fminf(mn1, x1); mx1 = fmaxf(mx1, x1);
    }
    float m0 = gelu_max2(a0 + mn0, a0 + mx0);
    float m1 = gelu_max2(a1 + mn1, a1 + mx1);
    __nv_bfloat162 out;
    out.x = __float2bfloat16(m0 + hc2.x);
    out.y = __float2bfloat16(m1 + hc2.y);
    *(__nv_bfloat162*)&g_hnh[(size_t)dst * CO + c] = out;
}

// ---------------- launch (serial, single stream) ----------------
extern "C" void kernel_launch(void* const* d_in, const int* in_sizes, int n_in,
                              void* d_out, int out_size) {
    const float* x      = (const float*)d_in[0];
    const int*   labels = (const int*)  d_in[1];
    const float* cpe_w  = (const float*)d_in[2];
    const float* cpe_b  = (const float*)d_in[3];
    const float* fc1_w  = (const float*)d_in[4];
    const float* fc1_b  = (const float*)d_in[5];
    const float* nn_v_w = (const float*)d_in[6];
    const float* nn_v_b = (const float*)d_in[7];
    const float* nn_c_w = (const float*)d_in[8];
    const float* nn_c_b = (const float*)d_in[9];
    const float* fc2_w  = (const float*)d_in[10];
    const float* fc2_b  = (const float*)d_in[11];
    float* y = (float*)d_out;

    float *p_xa, *p_xf;
    __nv_bfloat16 *p_xth, *p_xtl, *p_xsh, *p_hnh, *p_Wvt, *p_W2t, *p_W1h, *p_W1l, *p_ABh;
    float *p_bcat;
    cudaGetSymbolAddress((void**)&p_xa,   g_xa);
    cudaGetSymbolAddress((void**)&p_xf,   g_xf);
    cudaGetSymbolAddress((void**)&p_bcat, g_bias_cat);
    cudaGetSymbolAddress((void**)&p_xth,  g_xt_hi);
    cudaGetSymbolAddress((void**)&p_xtl,  g_xt_lo);
    cudaGetSymbolAddress((void**)&p_xsh,  g_xsh);
    cudaGetSymbolAddress((void**)&p_hnh,  g_hnh);
    cudaGetSymbolAddress((void**)&p_Wvt,  g_Wvt);
    cudaGetSymbolAddress((void**)&p_W2t,  g_W2t);
    cudaGetSymbolAddress((void**)&p_W1h,  g_W1t_hi);
    cudaGetSymbolAddress((void**)&p_W1l,  g_W1t_lo);
    cudaGetSymbolAddress((void**)&p_ABh,  g_ABh);

    cudaFuncSetAttribute(k_hgemm3_db, cudaFuncAttributeMaxDynamicSharedMemorySize, 61440);
    cudaFuncSetAttribute(k_gram_ab,   cudaFuncAttributeMaxDynamicSharedMemorySize, 66048);
    cudaFuncSetAttribute(k_hgemm_db<64,2>, cudaFuncAttributeMaxDynamicSharedMemorySize, 34048);

    k_sortprep<<<8 + (NCAT * CH + 255) / 256, 256>>>(labels, nn_v_w, nn_c_w, fc2_w, fc1_w, nn_v_b, nn_c_b);
    k_dwconv<<<dim3(4, BATCH * CH), 256>>>(x, cpe_w, cpe_b);
    k_transpose_cn<<<dim3(NPIX / 32, CH / 32, BATCH), dim3(32, 8)>>>(p_xa);

    // fc1 split-bf16 (contiguous rows, unsorted out)
    k_hgemm3_db<<<dim3(CH / 64, BN / 128), 256, 61440>>>(p_xth, p_xtl, p_W1h, p_W1l, fc1_b, p_xf, BN, CH, CH);
    // gather into sorted order + norm (one pass)
    k_gather_norm<<<BN / 8, 256>>>();

    // merged: gram (768 blocks) + AB GEMM (1176 blocks) — independent work, one launch
    k_gram_ab<<<GRAM_BLOCKS + AB_BLOCKS, 256, 66048>>>(p_xsh, p_Wvt, p_bcat, p_ABh);

    k_sel<<<BATCH * KC, 256>>>();
    k_cenmlp<<<BATCH * KC, 256>>>();
    k_cmax<<<(BATCH * KC * CO + 255) / 256, 256>>>();

    k_aggregate<<<BN, CO / 2>>>();

    // fc2 fused: (25088,384)x(384,192) -> transpose + shortcut -> y
    k_hgemm_db<64,2><<<dim3(CH / 64, BN / 128), 256, 34048>>>(p_hnh, p_W2t, fc2_b, y, nullptr, x, BN, CO, CH);
}

// round 15
// speedup vs baseline: 1.7759x; 1.0993x over previous
#include <cuda_runtime.h>
#include <cuda_bf16.h>
#include <math_constants.h>
#include <cstdint>

#define BATCH 8
#define CH    192
#define HH    56
#define WW    56
#define NPIX  3136
#define KC    16
#define NBR   9
#define CO    384
#define NCAT  768
#define BN    (BATCH*NPIX)  // 25088
#define SMAX  384

// ---------------- scratch ----------------
__device__ __align__(128) float g_xa[BATCH*CH*NPIX];
__device__ __align__(128) __nv_bfloat16 g_xt_hi[BN*CH];
__device__ __align__(128) __nv_bfloat16 g_xt_lo[BN*CH];
__device__ __align__(128) float g_xf[BN*CH];            // fc1 out (UNSORTED rows)
__device__ __align__(128) __nv_bfloat16 g_xsh[BN*CH];   // sorted rows bf16
__device__ __align__(128) __nv_bfloat16 g_xe_hi[BN*CH]; // normalized sorted rows bf16
__device__ __align__(128) __nv_bfloat16 g_ABh[(size_t)BN*NCAT]; // [A | Bv] bf16 (sorted)
__device__ __align__(128) float g_S[(size_t)BATCH*KC*SMAX*SMAX];
__device__ __align__(128) __nv_bfloat16 g_hnh[BN*CO];   // aggregated, UNSORTED rows
__device__ int   g_order[BN];
__device__ int   g_ls[BN];
__device__ int   g_cstart[BATCH][KC+1];
__device__ int   g_nbr[BN*NBR];
__device__ __align__(128) float g_AcBc[BATCH*KC*NCAT];
__device__ __align__(128) float g_hc[BATCH*KC*CO];
__device__ __align__(128) float g_Wc2[CH*NCAT];
__device__ __align__(128) __nv_bfloat16 g_Wvt[NCAT*CH];
__device__ __align__(128) __nv_bfloat16 g_W2t[CH*CO];
__device__ __align__(128) __nv_bfloat16 g_W1t_hi[CH*CH];
__device__ __align__(128) __nv_bfloat16 g_W1t_lo[CH*CH];
__device__ __align__(128) float g_bias_cat[NCAT];
__device__ __align__(128) float g_bias_c2[NCAT];

__device__ __forceinline__ float gelu_f(float x) {
    float u = 0.7978845608028654f * (x + 0.044715f * x * x * x);
    float t;
    asm("tanh.approx.f32 %0, %1;" : "=f"(t) : "f"(u));
    return 0.5f * x * (1.0f + t);
}
__device__ __forceinline__ float gelu_max2(float mn, float mx) {
    return fmaxf(gelu_f(mn), gelu_f(mx));
}
__device__ __forceinline__ void split_bf16(float v, __nv_bfloat16& hi, __nv_bfloat16& lo) {
    hi = __float2bfloat16(v);
    lo = __float2bfloat16(v - __bfloat162float(hi));
}
__device__ __forceinline__ void cp16(void* dst, const void* src) {
    uint32_t d = (uint32_t)__cvta_generic_to_shared(dst);
    asm volatile("cp.async.ca.shared.global [%0], [%1], 16;\n" :: "r"(d), "l"(src));
}
__device__ __forceinline__ uint32_t smaddr(const void* p) {
    return (uint32_t)__cvta_generic_to_shared(p);
}
#define CP_COMMIT() asm volatile("cp.async.commit_group;\n")
#define CP_WAIT1()  asm volatile("cp.async.wait_group 1;\n")
#define CP_WAIT0()  asm volatile("cp.async.wait_group 0;\n")

#define MMA_BF16(acc, a0, a1, a2, a3, b0, b1) \
    asm volatile( \
        "mma.sync.aligned.m16n8k16.row.col.f32.bf16.bf16.f32 " \
        "{%0,%1,%2,%3}, {%4,%5,%6,%7}, {%8,%9}, {%0,%1,%2,%3};\n" \
        : "+f"(acc[0]), "+f"(acc[1]), "+f"(acc[2]), "+f"(acc[3]) \
        : "r"(a0), "r"(a1), "r"(a2), "r"(a3), "r"(b0), "r"(b1))

#define LDSM_X4(d0, d1, d2, d3, a) \
    asm volatile("ldmatrix.sync.aligned.m8n8.x4.shared.b16 {%0,%1,%2,%3}, [%4];" \
        : "=r"(d0), "=r"(d1), "=r"(d2), "=r"(d3) : "r"(a))

// ================= merged pre-pass: dwconv + sort + weight prep =================
#define CHUNK 13
#define DW_BLOCKS (4 * BATCH * CH)                       // 6144
#define SP_BLOCKS (8 + (NCAT * CH + 255) / 256)          // 8 + 576
#define PRE_SMEM  29184

__device__ void dwconv_body(int bid, const float* __restrict__ x,
                            const float* __restrict__ cw, const float* __restrict__ cb,
                            char* sm_) {
    float (*sh)[41] = (float(*)[41])sm_;                 // 38*41*4 = 6232
    float* wsh = (float*)(sm_ + 6240);                   // 49*4
    int bc = bid >> 2;
    int c  = bc % CH;
    int tile = bid & 3;
    int ty0 = (tile >> 1) * 32, tx0 = (tile & 1) * 32;
    if (threadIdx.x < 49) wsh[threadIdx.x] = cw[c * 49 + threadIdx.x];
    const float* src = x + (size_t)bc * NPIX;
    for (int l = threadIdx.x; l < 38 * 38; l += 256) {
        int r = l / 38, cc = l % 38;
        int h = ty0 + r - 3, w = tx0 + cc - 3;
        sh[r][cc] = (h >= 0 && h < HH && w >= 0 && w < WW) ? src[h * WW + w] : 0.f;
    }
    __syncthreads();
    int ty = threadIdx.x >> 3;
    int xg = threadIdx.x & 7;
    int h = ty0 + ty;
    int wbase = tx0 + xg * 4;
    if (h < HH) {
        float acc[4] = {0.f, 0.f, 0.f, 0.f};
#pragma unroll
        for (int kh = 0; kh < 7; kh++) {
            float rr[10];
#pragma unroll
            for (int q = 0; q < 10; q++) rr[q] = sh[ty + kh][xg * 4 + q];
#pragma unroll
            for (int kw = 0; kw < 7; kw++) {
                float wv = wsh[kh * 7 + kw];
                acc[0] += rr[kw] * wv;     acc[1] += rr[kw + 1] * wv;
                acc[2] += rr[kw + 2] * wv; acc[3] += rr[kw + 3] * wv;
            }
        }
        float bb = cb[c];
#pragma unroll
        for (int o = 0; o < 4; o++) {
            int w = wbase + o;
            if (w < WW)
                g_xa[(size_t)bc * NPIX + h * WW + w] = acc[o] + bb + sh[ty + 3][xg * 4 + o + 3];
        }
    }
}

__device__ void sort_body(int b, const int* __restrict__ labels, char* sm_) {
    int* slab = (int*)sm_;                               // 3136*4 = 12544
    int (*cnt)[257] = (int(*)[257])(sm_ + 12544);        // 16*257*4 = 16448
    int* start = (int*)(sm_ + 12544 + 16448);            // 17*4
    const int* lab = labels + b * NPIX;
    int t = threadIdx.x;
    for (int i = t; i < NPIX; i += 256) slab[i] = lab[i];
    __syncthreads();
    int lo = t * CHUNK;
    int hi = min(lo + CHUNK, NPIX);
    int local[KC];
#pragma unroll
    for (int k = 0; k < KC; k++) local[k] = 0;
    for (int i = lo; i < hi; i++) local[slab[i]]++;
#pragma unroll
    for (int k = 0; k < KC; k++) cnt[k][t + 1] = local[k];
    if (t < KC) cnt[t][0] = 0;
    __syncthreads();
    if (t < KC) {
        int s = 0;
        for (int j = 1; j <= 256; j++) { s += cnt[t][j]; cnt[t][j] = s; }
    }
    __syncthreads();
    if (t == 0) {
        int s = 0;
        for (int k = 0; k < KC; k++) { start[k] = s; s += cnt[k][256]; }
        start[KC] = s;
        for (int k = 0; k <= KC; k++) g_cstart[b][k] = start[k];
    }
    __syncthreads();
    int ofs[KC];
#pragma unroll
    for (int k = 0; k < KC; k++) ofs[k] = start[k] + cnt[k][t];
    for (int i = lo; i < hi; i++) {
        int l = slab[i];
        int p = ofs[l]++;
        g_order[b * NPIX + p] = i;
        g_ls[b * NPIX + p] = l;
    }
}

__device__ void prep_body(int pb,
                          const float* __restrict__ wv, const float* __restrict__ wc,
                          const float* __restrict__ w2, const float* __restrict__ w1,
                          const float* __restrict__ vb, const float* __restrict__ cbias) {
    int i = pb * 256 + threadIdx.x;
    if (i < NCAT * CH) {
        int n = i / CH, k = i % CH;
        float v;
        if (n < CO) v = wv[k * CO + n] - wv[(CH + k) * CO + n];
        else        v = wv[(CH + k) * CO + (n - CO)];
        g_Wvt[n * CH + k] = __float2bfloat16(v);
        int k2 = i / NCAT, n2 = i % NCAT;
        float vc;
        if (n2 < CO) vc = wc[k2 * CO + n2] - wc[(CH + k2) * CO + n2];
        else         vc = wc[(CH + k2) * CO + (n2 - CO)];
        g_Wc2[i] = vc;
    }
    if (i < CH * CO) {
        int n = i / CO, k = i % CO;
        g_W2t[n * CO + k] = __float2bfloat16(w2[k * CH + n]);
    }
    if (i < CH * CH) {
        int n = i / CH, k = i % CH;
        __nv_bfloat16 hi, lo;
        split_bf16(w1[k * CH + n], hi, lo);
        g_W1t_hi[n * CH + k] = hi;
        g_W1t_lo[n * CH + k] = lo;
    }
    if (i < NCAT) {
        g_bias_cat[i] = (i < CO) ? vb[i] : 0.f;
        g_bias_c2[i]  = (i < CO) ? cbias[i] : 0.f;
    }
}

__global__ void __launch_bounds__(256) k_pre(
        const float* __restrict__ x, const float* __restrict__ cw,
        const float* __restrict__ cb, const int* __restrict__ labels,
        const float* __restrict__ wv, const float* __restrict__ wc,
        const float* __restrict__ w2, const float* __restrict__ w1,
        const float* __restrict__ vb, const float* __restrict__ cbias) {
    extern __shared__ char sm_[];
    int bid = blockIdx.x;
    if (bid < DW_BLOCKS) {
        dwconv_body(bid, x, cw, cb, sm_);
    } else {
        int t = bid - DW_BLOCKS;
        if (t < 8) sort_body(t, labels, sm_);
        else       prep_body(t - 8, wv, wc, w2, w1, vb, cbias);
    }
}

// transpose (B,C,N)->(B,N,C), split bf16
__global__ void k_transpose_cn(const float* __restrict__ in) {
    int b = blockIdx.z;
    int n0 = blockIdx.x * 32, c0 = blockIdx.y * 32;
    __shared__ float t[32][33];
    const float* ip = in + (size_t)b * CH * NPIX;
#pragma unroll
    for (int q = 0; q < 4; q++) {
        int cc = c0 + threadIdx.y + q * 8;
        t[threadIdx.y + q * 8][threadIdx.x] = ip[(size_t)cc * NPIX + n0 + threadIdx.x];
    }
    __syncthreads();
#pragma unroll
    for (int q = 0; q < 4; q++) {
        int nn = n0 + threadIdx.y + q * 8;
        size_t o = ((size_t)b * NPIX + nn) * CH + c0 + threadIdx.x;
        __nv_bfloat16 hi, lo;
        split_bf16(t[threadIdx.x][threadIdx.y + q * 8], hi, lo);
        g_xt_hi[o] = hi;
        g_xt_lo[o] = lo;
    }
}

// ---------------- double-buffered bf16 tensor GEMM (fc2 fused epilogue) ----------------
template<int NT>
__global__ void __launch_bounds__(256) k_hgemm_fc2(
        const __nv_bfloat16* __restrict__ X, const __nv_bfloat16* __restrict__ Wt,
        const float* __restrict__ bias, float* __restrict__ Yf,
        const float* __restrict__ shortcut, int M, int K, int Nn) {
    extern __shared__ char sm_[];
    constexpr int ASZ = 128 * 40 * 2;
    constexpr int BSZ = NT * 40 * 2;
    constexpr int STG = ASZ + BSZ;
    int bm = blockIdx.y * 128, bn = blockIdx.x * NT;
    int tid = threadIdx.x, warp = tid >> 5, lane = tid & 31;
    int wm = warp & 3, wn = warp >> 2;
    int g = lane >> 2, tg = lane & 3;
    constexpr int NI = NT / 16;
    int arow = ((lane & 15) >> 3) * 8 + (lane & 7);
    int acol = (lane >> 4) * 8;
    int brow = (lane >> 4) * 8 + (lane & 7);
    int bcol = ((lane >> 3) & 1) * 8;
    float acc[2][NI][4];
#pragma unroll
    for (int im = 0; im < 2; im++)
#pragma unroll
        for (int in = 0; in < NI; in++)
#pragma unroll
            for (int q = 0; q < 4; q++) acc[im][in][q] = 0.f;

    int KT = K / 32;
#pragma unroll 1
    for (int kt = -1; kt < KT; kt++) {
        int lt = kt + 1;
        if (lt < KT) {
            int s = lt & 1;
            __nv_bfloat16 (*As)[40] = (__nv_bfloat16(*)[40])(sm_ + s * STG);
            __nv_bfloat16 (*Bs)[40] = (__nv_bfloat16(*)[40])(sm_ + s * STG + ASZ);
            int k0 = lt * 32;
#pragma unroll
            for (int c = 0; c < 2; c++) {
                int ch = tid + c * 256;
                int row = ch >> 2, part = ch & 3;
                cp16(&As[row][part * 8], X + (size_t)(bm + row) * K + k0 + part * 8);
            }
#pragma unroll
            for (int c = 0; c < NT / 64; c++) {
                int ch = tid + c * 256;
                int row = ch >> 2, part = ch & 3;
                cp16(&Bs[row][part * 8], Wt + (size_t)(bn + row) * K + k0 + part * 8);
            }
            CP_COMMIT();
        }
        if (kt < 0) continue;
        if (kt + 1 < KT) CP_WAIT1(); else CP_WAIT0();
        __syncthreads();
        int s = kt & 1;
        __nv_bfloat16 (*As)[40] = (__nv_bfloat16(*)[40])(sm_ + s * STG);
        __nv_bfloat16 (*Bs)[40] = (__nv_bfloat16(*)[40])(sm_ + s * STG + ASZ);
#pragma unroll
        for (int kk = 0; kk < 32; kk += 16) {
            uint32_t a[2][4], bf[NI][2];
#pragma unroll
            for (int im = 0; im < 2; im++) {
                uint32_t ad = smaddr(&As[wm * 32 + im * 16 + arow][kk + acol]);
                LDSM_X4(a[im][0], a[im][1], a[im][2], a[im][3], ad);
            }
#pragma unroll
            for (int i2 = 0; i2 < NI / 2; i2++) {
                uint32_t bd = smaddr(&Bs[wn * (NT / 2) + i2 * 16 + brow][kk + bcol]);
                LDSM_X4(bf[2 * i2][0], bf[2 * i2][1], bf[2 * i2 + 1][0], bf[2 * i2 + 1][1], bd);
            }
#pragma unroll
            for (int im = 0; im < 2; im++)
#pragma unroll
                for (int in = 0; in < NI; in++)
                    MMA_BF16(acc[im][in], a[im][0], a[im][1], a[im][2], a[im][3],
                             bf[in][0], bf[in][1]);
        }
        __syncthreads();
    }
    float* smf = (float*)sm_;            // [NT][132]
#pragma unroll
    for (int im = 0; im < 2; im++)
#pragma unroll
        for (int in = 0; in < NI; in++) {
            int r = wm * 32 + im * 16 + g;
            int cc = wn * (NT / 2) + in * 8 + tg * 2;
            float b0 = bias[bn + cc], b1 = bias[bn + cc + 1];
            smf[cc * 132 + r]           = acc[im][in][0] + b0;
            smf[(cc + 1) * 132 + r]     = acc[im][in][1] + b1;
            smf[cc * 132 + r + 8]       = acc[im][in][2] + b0;
            smf[(cc + 1) * 132 + r + 8] = acc[im][in][3] + b1;
        }
    __syncthreads();
    for (int cc = warp; cc < NT; cc += 8) {
        float4 v = *(float4*)&smf[cc * 132 + lane * 4];
        int p = bm + lane * 4;
        int b = p / NPIX;
        int n = p - b * NPIX;
        size_t o = ((size_t)b * CH + bn + cc) * NPIX + n;
        float4 xv = *(const float4*)(shortcut + o);
        v.x += xv.x; v.y += xv.y; v.z += xv.z; v.w += xv.w;
        *(float4*)(Yf + o) = v;
    }
}

// ---------------- double-buffered split-bf16 GEMM (fc1, ldmatrix fragments) ----------------
__global__ void __launch_bounds__(256) k_hgemm3_db(
        const __nv_bfloat16* __restrict__ Xhi, const __nv_bfloat16* __restrict__ Xlo,
        const __nv_bfloat16* __restrict__ Whi, const __nv_bfloat16* __restrict__ Wlo,
        const float* __restrict__ bias, float* __restrict__ Y,
        int M, int K, int Nn) {
    extern __shared__ char sm_[];
    constexpr int A1 = 128 * 40 * 2;
    constexpr int B1 = 64 * 40 * 2;
    constexpr int STG = 2 * A1 + 2 * B1;
    int bm = blockIdx.y * 128, bn = blockIdx.x * 64;
    int tid = threadIdx.x, warp = tid >> 5, lane = tid & 31;
    int wm = warp & 3, wn = warp >> 2;
    int g = lane >> 2, tg = lane & 3;
    int arow = ((lane & 15) >> 3) * 8 + (lane & 7);
    int acol = (lane >> 4) * 8;
    int brow = (lane >> 4) * 8 + (lane & 7);
    int bcol = ((lane >> 3) & 1) * 8;
    float acc[2][4][4];
#pragma unroll
    for (int im = 0; im < 2; im++)
#pragma unroll
        for (int in = 0; in < 4; in++)
#pragma unroll
            for (int q = 0; q < 4; q++) acc[im][in][q] = 0.f;

    int KT = K / 32;
#pragma unroll 1
    for (int kt = -1; kt < KT; kt++) {
        int lt = kt + 1;
        if (lt < KT) {
            int s = lt & 1;
            char* base = sm_ + s * STG;
            __nv_bfloat16 (*Ah)[40] = (__nv_bfloat16(*)[40])(base);
            __nv_bfloat16 (*Al)[40] = (__nv_bfloat16(*)[40])(base + A1);
            __nv_bfloat16 (*Bh)[40] = (__nv_bfloat16(*)[40])(base + 2 * A1);
            __nv_bfloat16 (*Bl)[40] = (__nv_bfloat16(*)[40])(base + 2 * A1 + B1);
            int k0 = lt * 32;
#pragma unroll
            for (int c = 0; c < 2; c++) {
                int ch = tid + c * 256;
                int row = ch >> 2, part = ch & 3;
                size_t ofs = (size_t)(bm + row) * K + k0 + part * 8;
                cp16(&Ah[row][part * 8], Xhi + ofs);
                cp16(&Al[row][part * 8], Xlo + ofs);
            }
            {
                int row = tid >> 2, part = tid & 3;
                size_t ofs = (size_t)(bn + row) * K + k0 + part * 8;
                cp16(&Bh[row][part * 8], Whi + ofs);
                cp16(&Bl[row][part * 8], Wlo + ofs);
            }
            CP_COMMIT();
        }
        if (kt < 0) continue;
        if (kt + 1 < KT) CP_WAIT1(); else CP_WAIT0();
        __syncthreads();
        int s = kt & 1;
        char* base = sm_ + s * STG;
        __nv_bfloat16 (*Ah)[40] = (__nv_bfloat16(*)[40])(base);
        __nv_bfloat16 (*Al)[40] = (__nv_bfloat16(*)[40])(base + A1);
        __nv_bfloat16 (*Bh)[40] = (__nv_bfloat16(*)[40])(base + 2 * A1);
        __nv_bfloat16 (*Bl)[40] = (__nv_bfloat16(*)[40])(base + 2 * A1 + B1);
#pragma unroll
        for (int kk = 0; kk < 32; kk += 16) {
            uint32_t ah[2][4], al[2][4], bh[4][2], bl[4][2];
#pragma unroll
            for (int im = 0; im < 2; im++) {
                uint32_t adh = smaddr(&Ah[wm * 32 + im * 16 + arow][kk + acol]);
                LDSM_X4(ah[im][0], ah[im][1], ah[im][2], ah[im][3], adh);
                uint32_t adl = smaddr(&Al[wm * 32 + im * 16 + arow][kk + acol]);
                LDSM_X4(al[im][0], al[im][1], al[im][2], al[im][3], adl);
            }
#pragma unroll
            for (int i2 = 0; i2 < 2; i2++) {
                uint32_t bdh = smaddr(&Bh[wn * 32 + i2 * 16 + brow][kk + bcol]);
                LDSM_X4(bh[2 * i2][0], bh[2 * i2][1], bh[2 * i2 + 1][0], bh[2 * i2 + 1][1], bdh);
                uint32_t bdl = smaddr(&Bl[wn * 32 + i2 * 16 + brow][kk + bcol]);
                LDSM_X4(bl[2 * i2][0], bl[2 * i2][1], bl[2 * i2 + 1][0], bl[2 * i2 + 1][1], bdl);
            }
#pragma unroll
            for (int im = 0; im < 2; im++)
#pragma unroll
                for (int in = 0; in < 4; in++) {
                    MMA_BF16(acc[im][in], ah[im][0], ah[im][1], ah[im][2], ah[im][3],
                             bh[in][0], bh[in][1]);
                    MMA_BF16(acc[im][in], ah[im][0], ah[im][1], ah[im][2], ah[im][3],
                             bl[in][0], bl[in][1]);
                    MMA_BF16(acc[im][in], al[im][0], al[im][1], al[im][2], al[im][3],
                             bh[in][0], bh[in][1]);
                }
        }
        __syncthreads();
    }
#pragma unroll
    for (int im = 0; im < 2; im++)
#pragma unroll
        for (int in = 0; in < 4; in++) {
            int row = bm + wm * 32 + im * 16 + g;
            int col = bn + wn * 32 + in * 8 + tg * 2;
            float b0 = bias[col], b1 = bias[col + 1];
            *(float2*)&Y[(size_t)row * Nn + col] =
                make_float2(acc[im][in][0] + b0, acc[im][in][1] + b1);
            *(float2*)&Y[(size_t)(row + 8) * Nn + col] =
                make_float2(acc[im][in][2] + b0, acc[im][in][3] + b1);
        }
}

// ---------------- gather + normalize (bf16 hi only) ----------------
__global__ void k_gather_norm() {
    int warp = threadIdx.x >> 5, lane = threadIdx.x & 31;
    int p = blockIdx.x * 8 + warp;
    if (p >= BN) return;
    int b = p / NPIX;
    int src = g_order[p];
    const float* in = g_xf + ((size_t)b * NPIX + src) * CH;
    float v[6];
    float ss = 0.f;
#pragma unroll
    for (int q = 0; q < 6; q++) { v[q] = in[lane + q * 32]; ss += v[q] * v[q]; }
#pragma unroll
    for (int off = 16; off; off >>= 1) ss += __shfl_xor_sync(0xffffffffu, ss, off);
    float inv = 1.f / fmaxf(sqrtf(ss), 1e-12f);
    size_t base = (size_t)p * CH;
#pragma unroll
    for (int q = 0; q < 6; q++) {
        int c = lane + q * 32;
        g_xsh[base + c] = __float2bfloat16(v[q]);
        g_xe_hi[base + c] = __float2bfloat16(v[q] * inv);
    }
}

// ---------------- gram body (single bf16 MMA, symmetric pairs, ldmatrix) ----------------
__device__ __forceinline__ void gram_body(int pi, int cl, char* sm_) {
    int b = cl / KC, k = cl % KC;
    int s0 = g_cstart[b][k], e0 = g_cstart[b][k + 1];
    int n = min(e0 - s0, SMAX);
    const int TI[6] = {0, 0, 0, 1, 1, 2};
    const int TJ[6] = {0, 1, 2, 1, 2, 2};
    int ti = TI[pi], tj = TJ[pi];
    if (ti * 128 >= n || tj * 128 >= n) return;
    int base = b * NPIX + s0;

    constexpr int A1 = 128 * 40 * 2;
    constexpr int STG = 2 * A1;
    int tid = threadIdx.x;
    int warp = tid >> 5, lane = tid & 31;
    int wm = warp & 3, wn = warp >> 2;
    int g = lane >> 2, tg = lane & 3;
    int arow = ((lane & 15) >> 3) * 8 + (lane & 7);
    int acol = (lane >> 4) * 8;
    int brow = (lane >> 4) * 8 + (lane & 7);
    int bcol = ((lane >> 3) & 1) * 8;
    float acc[2][8][4];
#pragma unroll
    for (int im = 0; im < 2; im++)
#pragma unroll
        for (int in = 0; in < 8; in++)
#pragma unroll
            for (int q = 0; q < 4; q++) acc[im][in][q] = 0.f;

    int KT = CH / 32;
#pragma unroll 1
    for (int kt = -1; kt < KT; kt++) {
        int lt = kt + 1;
        if (lt < KT) {
            int s = lt & 1;
            char* bb = sm_ + s * STG;
            __nv_bfloat16 (*Ah)[40] = (__nv_bfloat16(*)[40])(bb);
            __nv_bfloat16 (*Bh)[40] = (__nv_bfloat16(*)[40])(bb + A1);
            int k0 = lt * 32;
#pragma unroll
            for (int c = 0; c < 2; c++) {
                int ch = tid + c * 256;
                int row = ch >> 2, part = ch & 3;
                int ra = min(base + ti * 128 + row, BN - 1);
                int rb = min(base + tj * 128 + row, BN - 1);
                cp16(&Ah[row][part * 8], g_xe_hi + (size_t)ra * CH + k0 + part * 8);
                cp16(&Bh[row][part * 8], g_xe_hi + (size_t)rb * CH + k0 + part * 8);
            }
            CP_COMMIT();
        }
        if (kt < 0) continue;
        if (kt + 1 < KT) CP_WAIT1(); else CP_WAIT0();
        __syncthreads();
        int s = kt & 1;
        char* bb = sm_ + s * STG;
        __nv_bfloat16 (*Ah)[40] = (__nv_bfloat16(*)[40])(bb);
        __nv_bfloat16 (*Bh)[40] = (__nv_bfloat16(*)[40])(bb + A1);
#pragma unroll
        for (int kk = 0; kk < 32; kk += 16) {
            uint32_t ah[2][4], bh[8][2];
#pragma unroll
            for (int im = 0; im < 2; im++) {
                uint32_t adh = smaddr(&Ah[wm * 32 + im * 16 + arow][kk + acol]);
                LDSM_X4(ah[im][0], ah[im][1], ah[im][2], ah[im][3], adh);
            }
#pragma unroll
            for (int i2 = 0; i2 < 4; i2++) {
                uint32_t bdh = smaddr(&Bh[wn * 64 + i2 * 16 + brow][kk + bcol]);
                LDSM_X4(bh[2 * i2][0], bh[2 * i2][1], bh[2 * i2 + 1][0], bh[2 * i2 + 1][1], bdh);
            }
#pragma unroll
            for (int im = 0; im < 2; im++)
#pragma unroll
                for (int in = 0; in < 8; in++)
                    MMA_BF16(acc[im][in], ah[im][0], ah[im][1], ah[im][2], ah[im][3],
                             bh[in][0], bh[in][1]);
        }
        __syncthreads();
    }
    float* Sp = g_S + (size_t)cl * SMAX * SMAX;
    float* smf = (float*)sm_;
#pragma unroll
    for (int im = 0; im < 2; im++)
#pragma unroll
        for (int in = 0; in < 8; in++) {
            int i0 = ti * 128 + wm * 32 + im * 16 + g;
            int j  = tj * 128 + wn * 64 + in * 8 + tg * 2;
            *(float2*)&Sp[(size_t)i0 * SMAX + j] = make_float2(acc[im][in][0], acc[im][in][1]);
            *(float2*)&Sp[(size_t)(i0 + 8) * SMAX + j] = make_float2(acc[im][in][2], acc[im][in][3]);
            if (ti != tj) {
                int il = wm * 32 + im * 16 + g;
                int jl = wn * 64 + in * 8 + tg * 2;
                smf[jl * 129 + il]           = acc[im][in][0];
                smf[(jl + 1) * 129 + il]     = acc[im][in][1];
                smf[jl * 129 + il + 8]       = acc[im][in][2];
                smf[(jl + 1) * 129 + il + 8] = acc[im][in][3];
            }
        }
    if (ti != tj) {
        __syncthreads();
        for (int jj = warp; jj < 128; jj += 8) {
            float v0 = smf[jj * 129 + lane * 4 + 0];
            float v1 = smf[jj * 129 + lane * 4 + 1];
            float v2 = smf[jj * 129 + lane * 4 + 2];
            float v3 = smf[jj * 129 + lane * 4 + 3];
            *(float4*)&Sp[(size_t)(tj * 128 + jj) * SMAX + ti * 128 + lane * 4] =
                make_float4(v0, v1, v2, v3);
        }
    }
}

// ---------------- AB body (128-wide bf16 GEMM) ----------------
__device__ __forceinline__ void ab_body(int bxi, int byi,
        const __nv_bfloat16* __restrict__ X, const __nv_bfloat16* __restrict__ Wt,
        const float* __restrict__ bias, __nv_bfloat16* __restrict__ Ybf, char* sm_) {
    constexpr int NT = 128;
    constexpr int ASZ = 128 * 40 * 2;
    constexpr int BSZ = NT * 40 * 2;
    constexpr int STG = ASZ + BSZ;
    constexpr int K = CH, Nn = NCAT;
    int bm = byi * 128, bn = bxi * NT;
    int tid = threadIdx.x, warp = tid >> 5, lane = tid & 31;
    int wm = warp & 3, wn = warp >> 2;
    int g = lane >> 2, tg = lane & 3;
    constexpr int NI = NT / 16;
    int arow = ((lane & 15) >> 3) * 8 + (lane & 7);
    int acol = (lane >> 4) * 8;
    int brow = (lane >> 4) * 8 + (lane & 7);
    int bcol = ((lane >> 3) & 1) * 8;
    float acc[2][NI][4];
#pragma unroll
    for (int im = 0; im < 2; im++)
#pragma unroll
        for (int in = 0; in < NI; in++)
#pragma unroll
            for (int q = 0; q < 4; q++) acc[im][in][q] = 0.f;

    int KT = K / 32;
#pragma unroll 1
    for (int kt = -1; kt < KT; kt++) {
        int lt = kt + 1;
        if (lt < KT) {
            int s = lt & 1;
            __nv_bfloat16 (*As)[40] = (__nv_bfloat16(*)[40])(sm_ + s * STG);
            __nv_bfloat16 (*Bs)[40] = (__nv_bfloat16(*)[40])(sm_ + s * STG + ASZ);
            int k0 = lt * 32;
#pragma unroll
            for (int c = 0; c < 2; c++) {
                int ch = tid + c * 256;
                int row = ch >> 2, part = ch & 3;
                cp16(&As[row][part * 8], X + (size_t)(bm + row) * K + k0 + part * 8);
            }
#pragma unroll
            for (int c = 0; c < NT / 64; c++) {
                int ch = tid + c * 256;
                int row = ch >> 2, part = ch & 3;
                cp16(&Bs[row][part * 8], Wt + (size_t)(bn + row) * K + k0 + part * 8);
            }
            CP_COMMIT();
        }
        if (kt < 0) continue;
        if (kt + 1 < KT) CP_WAIT1(); else CP_WAIT0();
        __syncthreads();
        int s = kt & 1;
        __nv_bfloat16 (*As)[40] = (__nv_bfloat16(*)[40])(sm_ + s * STG);
        __nv_bfloat16 (*Bs)[40] = (__nv_bfloat16(*)[40])(sm_ + s * STG + ASZ);
#pragma unroll
        for (int kk = 0; kk < 32; kk += 16) {
            uint32_t a[2][4], bf[NI][2];
#pragma unroll
            for (int im = 0; im < 2; im++) {
                uint32_t ad = smaddr(&As[wm * 32 + im * 16 + arow][kk + acol]);
                LDSM_X4(a[im][0], a[im][1], a[im][2], a[im][3], ad);
            }
#pragma unroll
            for (int i2 = 0; i2 < NI / 2; i2++) {
                uint32_t bd = smaddr(&Bs[wn * (NT / 2) + i2 * 16 + brow][kk + bcol]);
                LDSM_X4(bf[2 * i2][0], bf[2 * i2][1], bf[2 * i2 + 1][0], bf[2 * i2 + 1][1], bd);
            }
#pragma unroll
            for (int im = 0; im < 2; im++)
#pragma unroll
                for (int in = 0; in < NI; in++)
                    MMA_BF16(acc[im][in], a[im][0], a[im][1], a[im][2], a[im][3],
                             bf[in][0], bf[in][1]);
        }
        __syncthreads();
    }
#pragma unroll
    for (int im = 0; im < 2; im++)
#pragma unroll
        for (int in = 0; in < NI; in++) {
            int row = bm + wm * 32 + im * 16 + g;
            int col = bn + wn * (NT / 2) + in * 8 + tg * 2;
            float b0 = bias[col], b1 = bias[col + 1];
            __nv_bfloat162 h0, h1;
            h0.x = __float2bfloat16(acc[im][in][0] + b0);
            h0.y = __float2bfloat16(acc[im][in][1] + b1);
            h1.x = __float2bfloat16(acc[im][in][2] + b0);
            h1.y = __float2bfloat16(acc[im][in][3] + b1);
            *(__nv_bfloat162*)&Ybf[(size_t)row * Nn + col] = h0;
            *(__nv_bfloat162*)&Ybf[(size_t)(row + 8) * Nn + col] = h1;
        }
}

// ---------------- merged gram + AB dispatch ----------------
#define GRAM_BLOCKS (6 * BATCH * KC)            // 768
#define AB_BLOCKS   ((NCAT / 128) * (BN / 128)) // 1176
__global__ void __launch_bounds__(256) k_gram_ab(
        const __nv_bfloat16* __restrict__ X, const __nv_bfloat16* __restrict__ Wt,
        const float* __restrict__ bias, __nv_bfloat16* __restrict__ Ybf) {
    extern __shared__ char sm_[];
    int bid = blockIdx.x;
    if (bid < GRAM_BLOCKS) {
        gram_body(bid % 6, bid / 6, sm_);
    } else {
        int t = bid - GRAM_BLOCKS;
        ab_body(t % (NCAT / 128), t / (NCAT / 128), X, Wt, bias, Ybf, sm_);
    }
}

// ---------------- sel body ----------------
__device__ void sel_body(int cl) {
    int b = cl / KC, k = cl % KC;
    int s = g_cstart[b][k], e = g_cstart[b][k + 1];
    int n = min(e - s, SMAX);
    int base = b * NPIX + s;
    int warp = threadIdx.x >> 5, lane = threadIdx.x & 31;
    int cnt = n < NBR ? n : NBR;
    const float* Sp = g_S + (size_t)cl * SMAX * SMAX;

    for (int i = warp; i < n; i += 8) {
        const float* row = Sp + (size_t)i * SMAX;
        float v[12];
#pragma unroll
        for (int q = 0; q < 12; q++) {
            int j = q * 32 + lane;
            v[q] = (j < n) ? row[j] : -CUDART_INF_F;
        }
        int lastbj = 0;
        for (int r = 0; r < cnt; r++) {
            float best = -CUDART_INF_F;
            int bj = SMAX * 32;
#pragma unroll
            for (int q = 0; q < 12; q++) {
                if (v[q] > best) { best = v[q]; bj = q * 32 + lane; }
            }
#pragma unroll
            for (int off = 16; off; off >>= 1) {
                float ov = __shfl_down_sync(0xffffffffu, best, off);
                int   oj = __shfl_down_sync(0xffffffffu, bj, off);
                if (ov > best || (ov == best && oj < bj)) { best = ov; bj = oj; }
            }
            bj = __shfl_sync(0xffffffffu, bj, 0);
            if (lane == (bj & 31)) v[bj >> 5] = -CUDART_INF_F;
            if (lane == 0) g_nbr[(size_t)(base + i) * NBR + r] = base + bj;
            lastbj = bj;
        }
        if (lane == 0)
            for (int r = cnt; r < NBR; r++)
                g_nbr[(size_t)(base + i) * NBR + r] = base + lastbj;
    }
}

// ---------------- cenmlp body ----------------
__device__ void cenmlp_body(int bk, char* sm_) {
    float* cen = (float*)sm_;
    int b = bk / KC, k = bk % KC;
    int s = g_cstart[b][k], e = g_cstart[b][k + 1];
    int t = threadIdx.x;
    if (t < CH) {
        float sum = 0.f;
        for (int p = s; p < e; p++)
            sum += __bfloat162float(g_xsh[((size_t)b * NPIX + p) * CH + t]);
        cen[t] = sum / (float)max(e - s, 1);
    }
    __syncthreads();
    for (int o = t; o < NCAT; o += 256) {
        float acc = g_bias_c2[o];
        for (int kk = 0; kk < CH; kk++)
            acc += cen[kk] * g_Wc2[kk * NCAT + o];
        g_AcBc[(size_t)bk * NCAT + o] = acc;
    }
}

// merged sel + cenmlp (independent: S vs xsh)
__global__ void __launch_bounds__(256) k_selcen() {
    extern __shared__ char sm_[];
    int bid = blockIdx.x;
    if (bid < BATCH * KC) sel_body(bid);
    else                  cenmlp_body(bid - BATCH * KC, sm_);
}

__global__ void k_cmax() {
    int idx = blockIdx.x * blockDim.x + threadIdx.x;
    if (idx >= BATCH * KC * CO) return;
    int c = idx % CO;
    int bk = idx / CO;
    int b = bk / KC;
    float a = g_AcBc[(size_t)bk * NCAT + c];
    float mn = CUDART_INF_F, mx = -CUDART_INF_F;
#pragma unroll
    for (int j = 0; j < KC; j++) {
        float xv = a + g_AcBc[(size_t)(b * KC + j) * NCAT + CO + c];
        mn = fminf(mn, xv);
        mx = fmaxf(mx, xv);
    }
    g_hc[idx] = gelu_max2(mn, mx);
}

// ---------------- aggregate: valley-extremes gelu-max over 9 neighbors ----------------
__global__ void k_aggregate() {
    int p = blockIdx.x;
    int b = p / NPIX;
    int lsk = g_ls[p];
    int dst = b * NPIX + g_order[p];
    __shared__ int nbrs[NBR];
    if (threadIdx.x < NBR) nbrs[threadIdx.x] = g_nbr[(size_t)p * NBR + threadIdx.x];
    __syncthreads();
    int c = threadIdx.x * 2;
    __nv_bfloat162 av = *(const __nv_bfloat162*)&g_ABh[(size_t)p * NCAT + c];
    float a0 = __bfloat162float(av.x), a1 = __bfloat162float(av.y);
    float2 hc2 = *(const float2*)&g_hc[((size_t)b * KC + lsk) * CO + c];
    float mn0 = CUDART_INF_F, mx0 = -CUDART_INF_F;
    float mn1 = CUDART_INF_F, mx1 = -CUDART_INF_F;
    int nb[NBR];
#pragma unroll
    for (int r = 0; r < NBR; r++) nb[r] = nbrs[r];
#pragma unroll
    for (int r = 0; r < NBR; r++) {
        __nv_bfloat162 bv = *(const __nv_bfloat162*)&g_ABh[(size_t)nb[r] * NCAT + CO + c];
        float x0 = __bfloat162float(bv.x);
        float x1 = __bfloat162float(bv.y);
        mn0 = fminf(mn0, x0); mx0 = fmaxf(mx0, x0);
        mn1 = fminf(mn1, x1); mx1 = fmaxf(mx1, x1);
    }
    float m0 = gelu_max2(a0 + mn0, a0 + mx0);
    float m1 = gelu_max2(a1 + mn1, a1 + mx1);
    __nv_bfloat162 out;
    out.x = __float2bfloat16(m0 + hc2.x);
    out.y = __float2bfloat16(m1 + hc2.y);
    *(__nv_bfloat162*)&g_hnh[(size_t)dst * CO + c] = out;
}

// ---------------- launch (serial, single stream) ----------------
extern "C" void kernel_launch(void* const* d_in, const int* in_sizes, int n_in,
                              void* d_out, int out_size) {
    const float* x      = (const float*)d_in[0];
    const int*   labels = (const int*)  d_in[1];
    const float* cpe_w  = (const float*)d_in[2];
    const float* cpe_b  = (const float*)d_in[3];
    const float* fc1_w  = (const float*)d_in[4];
    const float* fc1_b  = (const float*)d_in[5];
    const float* nn_v_w = (const float*)d_in[6];
    const float* nn_v_b = (const float*)d_in[7];
    const float* nn_c_w = (const float*)d_in[8];
    const float* nn_c_b = (const float*)d_in[9];
    const float* fc2_w  = (const float*)d_in[10];
    const float* fc2_b  = (const float*)d_in[11];
    float* y = (float*)d_out;

    float *p_xa, *p_xf;
    __nv_bfloat16 *p_xth, *p_xtl, *p_xsh, *p_hnh, *p_Wvt, *p_W2t, *p_W1h, *p_W1l, *p_ABh;
    float *p_bcat;
    cudaGetSymbolAddress((void**)&p_xa,   g_xa);
    cudaGetSymbolAddress((void**)&p_xf,   g_xf);
    cudaGetSymbolAddress((void**)&p_bcat, g_bias_cat);
    cudaGetSymbolAddress((void**)&p_xth,  g_xt_hi);
    cudaGetSymbolAddress((void**)&p_xtl,  g_xt_lo);
    cudaGetSymbolAddress((void**)&p_xsh,  g_xsh);
    cudaGetSymbolAddress((void**)&p_hnh,  g_hnh);
    cudaGetSymbolAddress((void**)&p_Wvt,  g_Wvt);
    cudaGetSymbolAddress((void**)&p_W2t,  g_W2t);
    cudaGetSymbolAddress((void**)&p_W1h,  g_W1t_hi);
    cudaGetSymbolAddress((void**)&p_W1l,  g_W1t_lo);
    cudaGetSymbolAddress((void**)&p_ABh,  g_ABh);

    cudaFuncSetAttribute(k_pre,        cudaFuncAttributeMaxDynamicSharedMemorySize, PRE_SMEM);
    cudaFuncSetAttribute(k_hgemm3_db,  cudaFuncAttributeMaxDynamicSharedMemorySize, 61440);
    cudaFuncSetAttribute(k_gram_ab,    cudaFuncAttributeMaxDynamicSharedMemorySize, 66048);
    cudaFuncSetAttribute(k_hgemm_fc2<64>, cudaFuncAttributeMaxDynamicSharedMemorySize, 34048);

    // merged: dwconv + label sort + weight prep (all independent)
    k_pre<<<DW_BLOCKS + SP_BLOCKS, 256, PRE_SMEM>>>(x, cpe_w, cpe_b, labels,
                                                    nn_v_w, nn_c_w, fc2_w, fc1_w, nn_v_b, nn_c_b);
    k_transpose_cn<<<dim3(NPIX / 32, CH / 32, BATCH), dim3(32, 8)>>>(p_xa);

    // fc1 split-bf16 (contiguous rows, unsorted out)
    k_hgemm3_db<<<dim3(CH / 64, BN / 128), 256, 61440>>>(p_xth, p_xtl, p_W1h, p_W1l, fc1_b, p_xf, BN, CH, CH);
    // gather into sorted order + norm (one pass)
    k_gather_norm<<<BN / 8, 256>>>();

    // merged: gram (768 blocks) + AB GEMM (1176 blocks)
    k_gram_ab<<<GRAM_BLOCKS + AB_BLOCKS, 256, 66048>>>(p_xsh, p_Wvt, p_bcat, p_ABh);

    // merged: sel (128) + centroid-MLP (128)
    k_selcen<<<2 * BATCH * KC, 256, CH * 4>>>();
    k_cmax<<<(BATCH * KC * CO + 255) / 256, 256>>>();

    k_aggregate<<<BN, CO / 2>>>();

    // fc2 fused: (25088,384)x(384,192) -> transpose + shortcut -> y
    k_hgemm_fc2<64><<<dim3(CH / 64, BN / 128), 256, 34048>>>(p_hnh, p_W2t, fc2_b, y, x, BN, CO, CH);
}

// round 16
// speedup vs baseline: 1.8012x; 1.0143x over previous
#include <cuda_runtime.h>
#include <cuda_bf16.h>
#include <math_constants.h>
#include <cstdint>

#define BATCH 8
#define CH    192
#define HH    56
#define WW    56
#define NPIX  3136
#define KC    16
#define NBR   9
#define CO    384
#define NCAT  768
#define BN    (BATCH*NPIX)  // 25088
#define SMAX  384

// ---------------- scratch ----------------
__device__ __align__(128) float g_xa[BATCH*CH*NPIX];
__device__ __align__(128) __nv_bfloat16 g_xt_hi[BN*CH];
__device__ __align__(128) __nv_bfloat16 g_xt_lo[BN*CH];
__device__ __align__(128) float g_xf[BN*CH];            // fc1 out (UNSORTED rows)
__device__ __align__(128) __nv_bfloat16 g_xsh[BN*CH];   // sorted rows bf16
__device__ __align__(128) __nv_bfloat16 g_xe_hi[BN*CH]; // normalized sorted rows bf16
__device__ __align__(128) __nv_bfloat16 g_ABh[(size_t)BN*NCAT]; // [A | Bv] bf16 (sorted)
__device__ __align__(128) float g_S[(size_t)BATCH*KC*SMAX*SMAX];
__device__ __align__(128) __nv_bfloat16 g_hnh[BN*CO];   // aggregated, UNSORTED rows
__device__ int   g_order[BN];
__device__ int   g_ls[BN];
__device__ int   g_cstart[BATCH][KC+1];
__device__ int   g_nbr[BN*NBR];
__device__ __align__(128) float g_AcBc[BATCH*KC*NCAT];
__device__ __align__(128) float g_hc[BATCH*KC*CO];
__device__ __align__(128) float g_Wc2[CH*NCAT];
__device__ __align__(128) __nv_bfloat16 g_Wvt[NCAT*CH];
__device__ __align__(128) __nv_bfloat16 g_W2t[CH*CO];
__device__ __align__(128) __nv_bfloat16 g_W1t_hi[CH*CH];
__device__ __align__(128) __nv_bfloat16 g_W1t_lo[CH*CH];
__device__ __align__(128) float g_bias_cat[NCAT];
__device__ __align__(128) float g_bias_c2[NCAT];

__device__ __forceinline__ float gelu_f(float x) {
    float u = 0.7978845608028654f * (x + 0.044715f * x * x * x);
    float t;
    asm("tanh.approx.f32 %0, %1;" : "=f"(t) : "f"(u));
    return 0.5f * x * (1.0f + t);
}
__device__ __forceinline__ float gelu_max2(float mn, float mx) {
    return fmaxf(gelu_f(mn), gelu_f(mx));
}
__device__ __forceinline__ void split_bf16(float v, __nv_bfloat16& hi, __nv_bfloat16& lo) {
    hi = __float2bfloat16(v);
    lo = __float2bfloat16(v - __bfloat162float(hi));
}
__device__ __forceinline__ void cp16(void* dst, const void* src) {
    uint32_t d = (uint32_t)__cvta_generic_to_shared(dst);
    asm volatile("cp.async.ca.shared.global [%0], [%1], 16;\n" :: "r"(d), "l"(src));
}
__device__ __forceinline__ uint32_t smaddr(const void* p) {
    return (uint32_t)__cvta_generic_to_shared(p);
}
#define CP_COMMIT() asm volatile("cp.async.commit_group;\n")
#define CP_WAIT1()  asm volatile("cp.async.wait_group 1;\n")
#define CP_WAIT0()  asm volatile("cp.async.wait_group 0;\n")

#define MMA_BF16(acc, a0, a1, a2, a3, b0, b1) \
    asm volatile( \
        "mma.sync.aligned.m16n8k16.row.col.f32.bf16.bf16.f32 " \
        "{%0,%1,%2,%3}, {%4,%5,%6,%7}, {%8,%9}, {%0,%1,%2,%3};\n" \
        : "+f"(acc[0]), "+f"(acc[1]), "+f"(acc[2]), "+f"(acc[3]) \
        : "r"(a0), "r"(a1), "r"(a2), "r"(a3), "r"(b0), "r"(b1))

#define LDSM_X4(d0, d1, d2, d3, a) \
    asm volatile("ldmatrix.sync.aligned.m8n8.x4.shared.b16 {%0,%1,%2,%3}, [%4];" \
        : "=r"(d0), "=r"(d1), "=r"(d2), "=r"(d3) : "r"(a))

// ================= merged pre-pass: dwconv + sort + weight prep =================
#define CHUNK 13
#define DW_BLOCKS (4 * BATCH * CH)                       // 6144
#define SP_BLOCKS (8 + (NCAT * CH + 255) / 256)          // 8 + 576
#define PRE_SMEM  29184

__device__ void dwconv_body(int bid, const float* __restrict__ x,
                            const float* __restrict__ cw, const float* __restrict__ cb,
                            char* sm_) {
    float (*sh)[41] = (float(*)[41])sm_;
    float* wsh = (float*)(sm_ + 6240);
    int bc = bid >> 2;
    int c  = bc % CH;
    int tile = bid & 3;
    int ty0 = (tile >> 1) * 32, tx0 = (tile & 1) * 32;
    if (threadIdx.x < 49) wsh[threadIdx.x] = cw[c * 49 + threadIdx.x];
    const float* src = x + (size_t)bc * NPIX;
    for (int l = threadIdx.x; l < 38 * 38; l += 256) {
        int r = l / 38, cc = l % 38;
        int h = ty0 + r - 3, w = tx0 + cc - 3;
        sh[r][cc] = (h >= 0 && h < HH && w >= 0 && w < WW) ? src[h * WW + w] : 0.f;
    }
    __syncthreads();
    int ty = threadIdx.x >> 3;
    int xg = threadIdx.x & 7;
    int h = ty0 + ty;
    int wbase = tx0 + xg * 4;
    if (h < HH) {
        float acc[4] = {0.f, 0.f, 0.f, 0.f};
#pragma unroll
        for (int kh = 0; kh < 7; kh++) {
            float rr[10];
#pragma unroll
            for (int q = 0; q < 10; q++) rr[q] = sh[ty + kh][xg * 4 + q];
#pragma unroll
            for (int kw = 0; kw < 7; kw++) {
                float wv = wsh[kh * 7 + kw];
                acc[0] += rr[kw] * wv;     acc[1] += rr[kw + 1] * wv;
                acc[2] += rr[kw + 2] * wv; acc[3] += rr[kw + 3] * wv;
            }
        }
        float bb = cb[c];
#pragma unroll
        for (int o = 0; o < 4; o++) {
            int w = wbase + o;
            if (w < WW)
                g_xa[(size_t)bc * NPIX + h * WW + w] = acc[o] + bb + sh[ty + 3][xg * 4 + o + 3];
        }
    }
}

__device__ void sort_body(int b, const int* __restrict__ labels, char* sm_) {
    int* slab = (int*)sm_;
    int (*cnt)[257] = (int(*)[257])(sm_ + 12544);
    int* start = (int*)(sm_ + 12544 + 16448);
    const int* lab = labels + b * NPIX;
    int t = threadIdx.x;
    for (int i = t; i < NPIX; i += 256) slab[i] = lab[i];
    __syncthreads();
    int lo = t * CHUNK;
    int hi = min(lo + CHUNK, NPIX);
    int local[KC];
#pragma unroll
    for (int k = 0; k < KC; k++) local[k] = 0;
    for (int i = lo; i < hi; i++) local[slab[i]]++;
#pragma unroll
    for (int k = 0; k < KC; k++) cnt[k][t + 1] = local[k];
    if (t < KC) cnt[t][0] = 0;
    __syncthreads();
    if (t < KC) {
        int s = 0;
        for (int j = 1; j <= 256; j++) { s += cnt[t][j]; cnt[t][j] = s; }
    }
    __syncthreads();
    if (t == 0) {
        int s = 0;
        for (int k = 0; k < KC; k++) { start[k] = s; s += cnt[k][256]; }
        start[KC] = s;
        for (int k = 0; k <= KC; k++) g_cstart[b][k] = start[k];
    }
    __syncthreads();
    int ofs[KC];
#pragma unroll
    for (int k = 0; k < KC; k++) ofs[k] = start[k] + cnt[k][t];
    for (int i = lo; i < hi; i++) {
        int l = slab[i];
        int p = ofs[l]++;
        g_order[b * NPIX + p] = i;
        g_ls[b * NPIX + p] = l;
    }
}

__device__ void prep_body(int pb,
                          const float* __restrict__ wv, const float* __restrict__ wc,
                          const float* __restrict__ w2, const float* __restrict__ w1,
                          const float* __restrict__ vb, const float* __restrict__ cbias) {
    int i = pb * 256 + threadIdx.x;
    if (i < NCAT * CH) {
        int n = i / CH, k = i % CH;
        float v;
        if (n < CO) v = wv[k * CO + n] - wv[(CH + k) * CO + n];
        else        v = wv[(CH + k) * CO + (n - CO)];
        g_Wvt[n * CH + k] = __float2bfloat16(v);
        int k2 = i / NCAT, n2 = i % NCAT;
        float vc;
        if (n2 < CO) vc = wc[k2 * CO + n2] - wc[(CH + k2) * CO + n2];
        else         vc = wc[(CH + k2) * CO + (n2 - CO)];
        g_Wc2[i] = vc;
    }
    if (i < CH * CO) {
        int n = i / CO, k = i % CO;
        g_W2t[n * CO + k] = __float2bfloat16(w2[k * CH + n]);
    }
    if (i < CH * CH) {
        int n = i / CH, k = i % CH;
        __nv_bfloat16 hi, lo;
        split_bf16(w1[k * CH + n], hi, lo);
        g_W1t_hi[n * CH + k] = hi;
        g_W1t_lo[n * CH + k] = lo;
    }
    if (i < NCAT) {
        g_bias_cat[i] = (i < CO) ? vb[i] : 0.f;
        g_bias_c2[i]  = (i < CO) ? cbias[i] : 0.f;
    }
}

__global__ void __launch_bounds__(256) k_pre(
        const float* __restrict__ x, const float* __restrict__ cw,
        const float* __restrict__ cb, const int* __restrict__ labels,
        const float* __restrict__ wv, const float* __restrict__ wc,
        const float* __restrict__ w2, const float* __restrict__ w1,
        const float* __restrict__ vb, const float* __restrict__ cbias) {
    extern __shared__ char sm_[];
    int bid = blockIdx.x;
    if (bid < DW_BLOCKS) {
        dwconv_body(bid, x, cw, cb, sm_);
    } else {
        int t = bid - DW_BLOCKS;
        if (t < 8) sort_body(t, labels, sm_);
        else       prep_body(t - 8, wv, wc, w2, w1, vb, cbias);
    }
}

// transpose (B,C,N)->(B,N,C), split bf16
__global__ void k_transpose_cn(const float* __restrict__ in) {
    int b = blockIdx.z;
    int n0 = blockIdx.x * 32, c0 = blockIdx.y * 32;
    __shared__ float t[32][33];
    const float* ip = in + (size_t)b * CH * NPIX;
#pragma unroll
    for (int q = 0; q < 4; q++) {
        int cc = c0 + threadIdx.y + q * 8;
        t[threadIdx.y + q * 8][threadIdx.x] = ip[(size_t)cc * NPIX + n0 + threadIdx.x];
    }
    __syncthreads();
#pragma unroll
    for (int q = 0; q < 4; q++) {
        int nn = n0 + threadIdx.y + q * 8;
        size_t o = ((size_t)b * NPIX + nn) * CH + c0 + threadIdx.x;
        __nv_bfloat16 hi, lo;
        split_bf16(t[threadIdx.x][threadIdx.y + q * 8], hi, lo);
        g_xt_hi[o] = hi;
        g_xt_lo[o] = lo;
    }
}

// ---------------- fc2: bf16 tensor GEMM, compile-time K=CO, fully unrolled ----------------
template<int NT>
__global__ void __launch_bounds__(256) k_hgemm_fc2(
        const __nv_bfloat16* __restrict__ X, const __nv_bfloat16* __restrict__ Wt,
        const float* __restrict__ bias, float* __restrict__ Yf,
        const float* __restrict__ shortcut) {
    extern __shared__ char sm_[];
    constexpr int K = CO;        // 384
    constexpr int Nn = CH;       // 192
    constexpr int ASZ = 128 * 40 * 2;
    constexpr int BSZ = NT * 40 * 2;
    constexpr int STG = ASZ + BSZ;
    constexpr int KT = K / 32;   // 12
    int bm = blockIdx.y * 128, bn = blockIdx.x * NT;
    int tid = threadIdx.x, warp = tid >> 5, lane = tid & 31;
    int wm = warp & 3, wn = warp >> 2;
    int g = lane >> 2, tg = lane & 3;
    constexpr int NI = NT / 16;
    int arow = ((lane & 15) >> 3) * 8 + (lane & 7);
    int acol = (lane >> 4) * 8;
    int brow = (lane >> 4) * 8 + (lane & 7);
    int bcol = ((lane >> 3) & 1) * 8;
    float acc[2][NI][4];
#pragma unroll
    for (int im = 0; im < 2; im++)
#pragma unroll
        for (int in = 0; in < NI; in++)
#pragma unroll
            for (int q = 0; q < 4; q++) acc[im][in][q] = 0.f;

#pragma unroll
    for (int kt = -1; kt < KT; kt++) {
        int lt = kt + 1;
        if (lt < KT) {
            int s = lt & 1;
            __nv_bfloat16 (*As)[40] = (__nv_bfloat16(*)[40])(sm_ + s * STG);
            __nv_bfloat16 (*Bs)[40] = (__nv_bfloat16(*)[40])(sm_ + s * STG + ASZ);
            int k0 = lt * 32;
#pragma unroll
            for (int c = 0; c < 2; c++) {
                int ch = tid + c * 256;
                int row = ch >> 2, part = ch & 3;
                cp16(&As[row][part * 8], X + (size_t)(bm + row) * K + k0 + part * 8);
            }
#pragma unroll
            for (int c = 0; c < NT / 64; c++) {
                int ch = tid + c * 256;
                int row = ch >> 2, part = ch & 3;
                cp16(&Bs[row][part * 8], Wt + (size_t)(bn + row) * K + k0 + part * 8);
            }
            CP_COMMIT();
        }
        if (kt < 0) continue;
        if (kt + 1 < KT) CP_WAIT1(); else CP_WAIT0();
        __syncthreads();
        int s = kt & 1;
        __nv_bfloat16 (*As)[40] = (__nv_bfloat16(*)[40])(sm_ + s * STG);
        __nv_bfloat16 (*Bs)[40] = (__nv_bfloat16(*)[40])(sm_ + s * STG + ASZ);
#pragma unroll
        for (int kk = 0; kk < 32; kk += 16) {
            uint32_t a[2][4], bf[NI][2];
#pragma unroll
            for (int im = 0; im < 2; im++) {
                uint32_t ad = smaddr(&As[wm * 32 + im * 16 + arow][kk + acol]);
                LDSM_X4(a[im][0], a[im][1], a[im][2], a[im][3], ad);
            }
#pragma unroll
            for (int i2 = 0; i2 < NI / 2; i2++) {
                uint32_t bd = smaddr(&Bs[wn * (NT / 2) + i2 * 16 + brow][kk + bcol]);
                LDSM_X4(bf[2 * i2][0], bf[2 * i2][1], bf[2 * i2 + 1][0], bf[2 * i2 + 1][1], bd);
            }
#pragma unroll
            for (int im = 0; im < 2; im++)
#pragma unroll
                for (int in = 0; in < NI; in++)
                    MMA_BF16(acc[im][in], a[im][0], a[im][1], a[im][2], a[im][3],
                             bf[in][0], bf[in][1]);
        }
        __syncthreads();
    }
    float* smf = (float*)sm_;            // [NT][132]
#pragma unroll
    for (int im = 0; im < 2; im++)
#pragma unroll
        for (int in = 0; in < NI; in++) {
            int r = wm * 32 + im * 16 + g;
            int cc = wn * (NT / 2) + in * 8 + tg * 2;
            float b0 = bias[bn + cc], b1 = bias[bn + cc + 1];
            smf[cc * 132 + r]           = acc[im][in][0] + b0;
            smf[(cc + 1) * 132 + r]     = acc[im][in][1] + b1;
            smf[cc * 132 + r + 8]       = acc[im][in][2] + b0;
            smf[(cc + 1) * 132 + r + 8] = acc[im][in][3] + b1;
        }
    __syncthreads();
    for (int cc = warp; cc < NT; cc += 8) {
        float4 v = *(float4*)&smf[cc * 132 + lane * 4];
        int p = bm + lane * 4;
        int b = p / NPIX;
        int n = p - b * NPIX;
        size_t o = ((size_t)b * CH + bn + cc) * NPIX + n;
        float4 xv = *(const float4*)(shortcut + o);
        v.x += xv.x; v.y += xv.y; v.z += xv.z; v.w += xv.w;
        *(float4*)(Yf + o) = v;
    }
}

// ---------------- fc1: split-bf16 GEMM, compile-time K=CH, fully unrolled ----------------
__global__ void __launch_bounds__(256) k_hgemm3_db(
        const __nv_bfloat16* __restrict__ Xhi, const __nv_bfloat16* __restrict__ Xlo,
        const __nv_bfloat16* __restrict__ Whi, const __nv_bfloat16* __restrict__ Wlo,
        const float* __restrict__ bias, float* __restrict__ Y) {
    extern __shared__ char sm_[];
    constexpr int K = CH;        // 192
    constexpr int Nn = CH;       // 192
    constexpr int A1 = 128 * 40 * 2;
    constexpr int B1 = 64 * 40 * 2;
    constexpr int STG = 2 * A1 + 2 * B1;
    constexpr int KT = K / 32;   // 6
    int bm = blockIdx.y * 128, bn = blockIdx.x * 64;
    int tid = threadIdx.x, warp = tid >> 5, lane = tid & 31;
    int wm = warp & 3, wn = warp >> 2;
    int g = lane >> 2, tg = lane & 3;
    int arow = ((lane & 15) >> 3) * 8 + (lane & 7);
    int acol = (lane >> 4) * 8;
    int brow = (lane >> 4) * 8 + (lane & 7);
    int bcol = ((lane >> 3) & 1) * 8;
    float acc[2][4][4];
#pragma unroll
    for (int im = 0; im < 2; im++)
#pragma unroll
        for (int in = 0; in < 4; in++)
#pragma unroll
            for (int q = 0; q < 4; q++) acc[im][in][q] = 0.f;

#pragma unroll
    for (int kt = -1; kt < KT; kt++) {
        int lt = kt + 1;
        if (lt < KT) {
            int s = lt & 1;
            char* base = sm_ + s * STG;
            __nv_bfloat16 (*Ah)[40] = (__nv_bfloat16(*)[40])(base);
            __nv_bfloat16 (*Al)[40] = (__nv_bfloat16(*)[40])(base + A1);
            __nv_bfloat16 (*Bh)[40] = (__nv_bfloat16(*)[40])(base + 2 * A1);
            __nv_bfloat16 (*Bl)[40] = (__nv_bfloat16(*)[40])(base + 2 * A1 + B1);
            int k0 = lt * 32;
#pragma unroll
            for (int c = 0; c < 2; c++) {
                int ch = tid + c * 256;
                int row = ch >> 2, part = ch & 3;
                size_t ofs = (size_t)(bm + row) * K + k0 + part * 8;
                cp16(&Ah[row][part * 8], Xhi + ofs);
                cp16(&Al[row][part * 8], Xlo + ofs);
            }
            {
                int row = tid >> 2, part = tid & 3;
                size_t ofs = (size_t)(bn + row) * K + k0 + part * 8;
                cp16(&Bh[row][part * 8], Whi + ofs);
                cp16(&Bl[row][part * 8], Wlo + ofs);
            }
            CP_COMMIT();
        }
        if (kt < 0) continue;
        if (kt + 1 < KT) CP_WAIT1(); else CP_WAIT0();
        __syncthreads();
        int s = kt & 1;
        char* base = sm_ + s * STG;
        __nv_bfloat16 (*Ah)[40] = (__nv_bfloat16(*)[40])(base);
        __nv_bfloat16 (*Al)[40] = (__nv_bfloat16(*)[40])(base + A1);
        __nv_bfloat16 (*Bh)[40] = (__nv_bfloat16(*)[40])(base + 2 * A1);
        __nv_bfloat16 (*Bl)[40] = (__nv_bfloat16(*)[40])(base + 2 * A1 + B1);
#pragma unroll
        for (int kk = 0; kk < 32; kk += 16) {
            uint32_t ah[2][4], al[2][4], bh[4][2], bl[4][2];
#pragma unroll
            for (int im = 0; im < 2; im++) {
                uint32_t adh = smaddr(&Ah[wm * 32 + im * 16 + arow][kk + acol]);
                LDSM_X4(ah[im][0], ah[im][1], ah[im][2], ah[im][3], adh);
                uint32_t adl = smaddr(&Al[wm * 32 + im * 16 + arow][kk + acol]);
                LDSM_X4(al[im][0], al[im][1], al[im][2], al[im][3], adl);
            }
#pragma unroll
            for (int i2 = 0; i2 < 2; i2++) {
                uint32_t bdh = smaddr(&Bh[wn * 32 + i2 * 16 + brow][kk + bcol]);
                LDSM_X4(bh[2 * i2][0], bh[2 * i2][1], bh[2 * i2 + 1][0], bh[2 * i2 + 1][1], bdh);
                uint32_t bdl = smaddr(&Bl[wn * 32 + i2 * 16 + brow][kk + bcol]);
                LDSM_X4(bl[2 * i2][0], bl[2 * i2][1], bl[2 * i2 + 1][0], bl[2 * i2 + 1][1], bdl);
            }
#pragma unroll
            for (int im = 0; im < 2; im++)
#pragma unroll
                for (int in = 0; in < 4; in++) {
                    MMA_BF16(acc[im][in], ah[im][0], ah[im][1], ah[im][2], ah[im][3],
                             bh[in][0], bh[in][1]);
                    MMA_BF16(acc[im][in], ah[im][0], ah[im][1], ah[im][2], ah[im][3],
                             bl[in][0], bl[in][1]);
                    MMA_BF16(acc[im][in], al[im][0], al[im][1], al[im][2], al[im][3],
                             bh[in][0], bh[in][1]);
                }
        }
        __syncthreads();
    }
#pragma unroll
    for (int im = 0; im < 2; im++)
#pragma unroll
        for (int in = 0; in < 4; in++) {
            int row = bm + wm * 32 + im * 16 + g;
            int col = bn + wn * 32 + in * 8 + tg * 2;
            float b0 = bias[col], b1 = bias[col + 1];
            *(float2*)&Y[(size_t)row * Nn + col] =
                make_float2(acc[im][in][0] + b0, acc[im][in][1] + b1);
            *(float2*)&Y[(size_t)(row + 8) * Nn + col] =
                make_float2(acc[im][in][2] + b0, acc[im][in][3] + b1);
        }
}

// ---------------- gather + normalize (bf16 hi only) ----------------
__global__ void k_gather_norm() {
    int warp = threadIdx.x >> 5, lane = threadIdx.x & 31;
    int p = blockIdx.x * 8 + warp;
    if (p >= BN) return;
    int b = p / NPIX;
    int src = g_order[p];
    const float* in = g_xf + ((size_t)b * NPIX + src) * CH;
    float v[6];
    float ss = 0.f;
#pragma unroll
    for (int q = 0; q < 6; q++) { v[q] = in[lane + q * 32]; ss += v[q] * v[q]; }
#pragma unroll
    for (int off = 16; off; off >>= 1) ss += __shfl_xor_sync(0xffffffffu, ss, off);
    float inv = 1.f / fmaxf(sqrtf(ss), 1e-12f);
    size_t base = (size_t)p * CH;
#pragma unroll
    for (int q = 0; q < 6; q++) {
        int c = lane + q * 32;
        g_xsh[base + c] = __float2bfloat16(v[q]);
        g_xe_hi[base + c] = __float2bfloat16(v[q] * inv);
    }
}

// ---------------- gram body (single bf16 MMA, fully unrolled pipeline) ----------------
__device__ __forceinline__ void gram_body(int pi, int cl, char* sm_) {
    int b = cl / KC, k = cl % KC;
    int s0 = g_cstart[b][k], e0 = g_cstart[b][k + 1];
    int n = min(e0 - s0, SMAX);
    const int TI[6] = {0, 0, 0, 1, 1, 2};
    const int TJ[6] = {0, 1, 2, 1, 2, 2};
    int ti = TI[pi], tj = TJ[pi];
    if (ti * 128 >= n || tj * 128 >= n) return;
    int base = b * NPIX + s0;

    constexpr int A1 = 128 * 40 * 2;
    constexpr int STG = 2 * A1;
    constexpr int KT = CH / 32;   // 6
    int tid = threadIdx.x;
    int warp = tid >> 5, lane = tid & 31;
    int wm = warp & 3, wn = warp >> 2;
    int g = lane >> 2, tg = lane & 3;
    int arow = ((lane & 15) >> 3) * 8 + (lane & 7);
    int acol = (lane >> 4) * 8;
    int brow = (lane >> 4) * 8 + (lane & 7);
    int bcol = ((lane >> 3) & 1) * 8;
    float acc[2][8][4];
#pragma unroll
    for (int im = 0; im < 2; im++)
#pragma unroll
        for (int in = 0; in < 8; in++)
#pragma unroll
            for (int q = 0; q < 4; q++) acc[im][in][q] = 0.f;

#pragma unroll
    for (int kt = -1; kt < KT; kt++) {
        int lt = kt + 1;
        if (lt < KT) {
            int s = lt & 1;
            char* bb = sm_ + s * STG;
            __nv_bfloat16 (*Ah)[40] = (__nv_bfloat16(*)[40])(bb);
            __nv_bfloat16 (*Bh)[40] = (__nv_bfloat16(*)[40])(bb + A1);
            int k0 = lt * 32;
#pragma unroll
            for (int c = 0; c < 2; c++) {
                int ch = tid + c * 256;
                int row = ch >> 2, part = ch & 3;
                int ra = min(base + ti * 128 + row, BN - 1);
                int rb = min(base + tj * 128 + row, BN - 1);
                cp16(&Ah[row][part * 8], g_xe_hi + (size_t)ra * CH + k0 + part * 8);
                cp16(&Bh[row][part * 8], g_xe_hi + (size_t)rb * CH + k0 + part * 8);
            }
            CP_COMMIT();
        }
        if (kt < 0) continue;
        if (kt + 1 < KT) CP_WAIT1(); else CP_WAIT0();
        __syncthreads();
        int s = kt & 1;
        char* bb = sm_ + s * STG;
        __nv_bfloat16 (*Ah)[40] = (__nv_bfloat16(*)[40])(bb);
        __nv_bfloat16 (*Bh)[40] = (__nv_bfloat16(*)[40])(bb + A1);
#pragma unroll
        for (int kk = 0; kk < 32; kk += 16) {
            uint32_t ah[2][4], bh[8][2];
#pragma unroll
            for (int im = 0; im < 2; im++) {
                uint32_t adh = smaddr(&Ah[wm * 32 + im * 16 + arow][kk + acol]);
                LDSM_X4(ah[im][0], ah[im][1], ah[im][2], ah[im][3], adh);
            }
#pragma unroll
            for (int i2 = 0; i2 < 4; i2++) {
                uint32_t bdh = smaddr(&Bh[wn * 64 + i2 * 16 + brow][kk + bcol]);
                LDSM_X4(bh[2 * i2][0], bh[2 * i2][1], bh[2 * i2 + 1][0], bh[2 * i2 + 1][1], bdh);
            }
#pragma unroll
            for (int im = 0; im < 2; im++)
#pragma unroll
                for (int in = 0; in < 8; in++)
                    MMA_BF16(acc[im][in], ah[im][0], ah[im][1], ah[im][2], ah[im][3],
                             bh[in][0], bh[in][1]);
        }
        __syncthreads();
    }
    float* Sp = g_S + (size_t)cl * SMAX * SMAX;
    float* smf = (float*)sm_;
#pragma unroll
    for (int im = 0; im < 2; im++)
#pragma unroll
        for (int in = 0; in < 8; in++) {
            int i0 = ti * 128 + wm * 32 + im * 16 + g;
            int j  = tj * 128 + wn * 64 + in * 8 + tg * 2;
            *(float2*)&Sp[(size_t)i0 * SMAX + j] = make_float2(acc[im][in][0], acc[im][in][1]);
            *(float2*)&Sp[(size_t)(i0 + 8) * SMAX + j] = make_float2(acc[im][in][2], acc[im][in][3]);
            if (ti != tj) {
                int il = wm * 32 + im * 16 + g;
                int jl = wn * 64 + in * 8 + tg * 2;
                smf[jl * 129 + il]           = acc[im][in][0];
                smf[(jl + 1) * 129 + il]     = acc[im][in][1];
                smf[jl * 129 + il + 8]       = acc[im][in][2];
                smf[(jl + 1) * 129 + il + 8] = acc[im][in][3];
            }
        }
    if (ti != tj) {
        __syncthreads();
        for (int jj = warp; jj < 128; jj += 8) {
            float v0 = smf[jj * 129 + lane * 4 + 0];
            float v1 = smf[jj * 129 + lane * 4 + 1];
            float v2 = smf[jj * 129 + lane * 4 + 2];
            float v3 = smf[jj * 129 + lane * 4 + 3];
            *(float4*)&Sp[(size_t)(tj * 128 + jj) * SMAX + ti * 128 + lane * 4] =
                make_float4(v0, v1, v2, v3);
        }
    }
}

// ---------------- AB body (128-wide bf16 GEMM, fully unrolled pipeline) ----------------
__device__ __forceinline__ void ab_body(int bxi, int byi,
        const __nv_bfloat16* __restrict__ X, const __nv_bfloat16* __restrict__ Wt,
        const float* __restrict__ bias, __nv_bfloat16* __restrict__ Ybf, char* sm_) {
    constexpr int NT = 128;
    constexpr int ASZ = 128 * 40 * 2;
    constexpr int BSZ = NT * 40 * 2;
    constexpr int STG = ASZ + BSZ;
    constexpr int K = CH, Nn = NCAT;
    constexpr int KT = K / 32;   // 6
    int bm = byi * 128, bn = bxi * NT;
    int tid = threadIdx.x, warp = tid >> 5, lane = tid & 31;
    int wm = warp & 3, wn = warp >> 2;
    int g = lane >> 2, tg = lane & 3;
    constexpr int NI = NT / 16;
    int arow = ((lane & 15) >> 3) * 8 + (lane & 7);
    int acol = (lane >> 4) * 8;
    int brow = (lane >> 4) * 8 + (lane & 7);
    int bcol = ((lane >> 3) & 1) * 8;
    float acc[2][NI][4];
#pragma unroll
    for (int im = 0; im < 2; im++)
#pragma unroll
        for (int in = 0; in < NI; in++)
#pragma unroll
            for (int q = 0; q < 4; q++) acc[im][in][q] = 0.f;

#pragma unroll
    for (int kt = -1; kt < KT; kt++) {
        int lt = kt + 1;
        if (lt < KT) {
            int s = lt & 1;
            __nv_bfloat16 (*As)[40] = (__nv_bfloat16(*)[40])(sm_ + s * STG);
            __nv_bfloat16 (*Bs)[40] = (__nv_bfloat16(*)[40])(sm_ + s * STG + ASZ);
            int k0 = lt * 32;
#pragma unroll
            for (int c = 0; c < 2; c++) {
                int ch = tid + c * 256;
                int row = ch >> 2, part = ch & 3;
                cp16(&As[row][part * 8], X + (size_t)(bm + row) * K + k0 + part * 8);
            }
#pragma unroll
            for (int c = 0; c < NT / 64; c++) {
                int ch = tid + c * 256;
                int row = ch >> 2, part = ch & 3;
                cp16(&Bs[row][part * 8], Wt + (size_t)(bn + row) * K + k0 + part * 8);
            }
            CP_COMMIT();
        }
        if (kt < 0) continue;
        if (kt + 1 < KT) CP_WAIT1(); else CP_WAIT0();
        __syncthreads();
        int s = kt & 1;
        __nv_bfloat16 (*As)[40] = (__nv_bfloat16(*)[40])(sm_ + s * STG);
        __nv_bfloat16 (*Bs)[40] = (__nv_bfloat16(*)[40])(sm_ + s * STG + ASZ);
#pragma unroll
        for (int kk = 0; kk < 32; kk += 16) {
            uint32_t a[2][4], bf[NI][2];
#pragma unroll
            for (int im = 0; im < 2; im++) {
                uint32_t ad = smaddr(&As[wm * 32 + im * 16 + arow][kk + acol]);
                LDSM_X4(a[im][0], a[im][1], a[im][2], a[im][3], ad);
            }
#pragma unroll
            for (int i2 = 0; i2 < NI / 2; i2++) {
                uint32_t bd = smaddr(&Bs[wn * (NT / 2) + i2 * 16 + brow][kk + bcol]);
                LDSM_X4(bf[2 * i2][0], bf[2 * i2][1], bf[2 * i2 + 1][0], bf[2 * i2 + 1][1], bd);
            }
#pragma unroll
            for (int im = 0; im < 2; im++)
#pragma unroll
                for (int in = 0; in < NI; in++)
                    MMA_BF16(acc[im][in], a[im][0], a[im][1], a[im][2], a[im][3],
                             bf[in][0], bf[in][1]);
        }
        __syncthreads();
    }
#pragma unroll
    for (int im = 0; im < 2; im++)
#pragma unroll
        for (int in = 0; in < NI; in++) {
            int row = bm + wm * 32 + im * 16 + g;
            int col = bn + wn * (NT / 2) + in * 8 + tg * 2;
            float b0 = bias[col], b1 = bias[col + 1];
            __nv_bfloat162 h0, h1;
            h0.x = __float2bfloat16(acc[im][in][0] + b0);
            h0.y = __float2bfloat16(acc[im][in][1] + b1);
            h1.x = __float2bfloat16(acc[im][in][2] + b0);
            h1.y = __float2bfloat16(acc[im][in][3] + b1);
            *(__nv_bfloat162*)&Ybf[(size_t)row * Nn + col] = h0;
            *(__nv_bfloat162*)&Ybf[(size_t)(row + 8) * Nn + col] = h1;
        }
}

// ---------------- merged gram + AB dispatch ----------------
#define GRAM_BLOCKS (6 * BATCH * KC)            // 768
#define AB_BLOCKS   ((NCAT / 128) * (BN / 128)) // 1176
__global__ void __launch_bounds__(256) k_gram_ab(
        const __nv_bfloat16* __restrict__ X, const __nv_bfloat16* __restrict__ Wt,
        const float* __restrict__ bias, __nv_bfloat16* __restrict__ Ybf) {
    extern __shared__ char sm_[];
    int bid = blockIdx.x;
    if (bid < GRAM_BLOCKS) {
        gram_body(bid % 6, bid / 6, sm_);
    } else {
        int t = bid - GRAM_BLOCKS;
        ab_body(t % (NCAT / 128), t / (NCAT / 128), X, Wt, bias, Ybf, sm_);
    }
}

// ---------------- sel body ----------------
__device__ void sel_body(int cl) {
    int b = cl / KC, k = cl % KC;
    int s = g_cstart[b][k], e = g_cstart[b][k + 1];
    int n = min(e - s, SMAX);
    int base = b * NPIX + s;
    int warp = threadIdx.x >> 5, lane = threadIdx.x & 31;
    int cnt = n < NBR ? n : NBR;
    const float* Sp = g_S + (size_t)cl * SMAX * SMAX;

    for (int i = warp; i < n; i += 8) {
        const float* row = Sp + (size_t)i * SMAX;
        float v[12];
#pragma unroll
        for (int q = 0; q < 12; q++) {
            int j = q * 32 + lane;
            v[q] = (j < n) ? row[j] : -CUDART_INF_F;
        }
        int lastbj = 0;
        for (int r = 0; r < cnt; r++) {
            float best = -CUDART_INF_F;
            int bj = SMAX * 32;
#pragma unroll
            for (int q = 0; q < 12; q++) {
                if (v[q] > best) { best = v[q]; bj = q * 32 + lane; }
            }
#pragma unroll
            for (int off = 16; off; off >>= 1) {
                float ov = __shfl_down_sync(0xffffffffu, best, off);
                int   oj = __shfl_down_sync(0xffffffffu, bj, off);
                if (ov > best || (ov == best && oj < bj)) { best = ov; bj = oj; }
            }
            bj = __shfl_sync(0xffffffffu, bj, 0);
            if (lane == (bj & 31)) v[bj >> 5] = -CUDART_INF_F;
            if (lane == 0) g_nbr[(size_t)(base + i) * NBR + r] = base + bj;
            lastbj = bj;
        }
        if (lane == 0)
            for (int r = cnt; r < NBR; r++)
                g_nbr[(size_t)(base + i) * NBR + r] = base + lastbj;
    }
}

// ---------------- cenmlp body ----------------
__device__ void cenmlp_body(int bk, char* sm_) {
    float* cen = (float*)sm_;
    int b = bk / KC, k = bk % KC;
    int s = g_cstart[b][k], e = g_cstart[b][k + 1];
    int t = threadIdx.x;
    if (t < CH) {
        float sum = 0.f;
        for (int p = s; p < e; p++)
            sum += __bfloat162float(g_xsh[((size_t)b * NPIX + p) * CH + t]);
        cen[t] = sum / (float)max(e - s, 1);
    }
    __syncthreads();
    for (int o = t; o < NCAT; o += 256) {
        float acc = g_bias_c2[o];
        for (int kk = 0; kk < CH; kk++)
            acc += cen[kk] * g_Wc2[kk * NCAT + o];
        g_AcBc[(size_t)bk * NCAT + o] = acc;
    }
}

// merged sel + cenmlp (independent: S vs xsh)
__global__ void __launch_bounds__(256) k_selcen() {
    extern __shared__ char sm_[];
    int bid = blockIdx.x;
    if (bid < BATCH * KC) sel_body(bid);
    else                  cenmlp_body(bid - BATCH * KC, sm_);
}

__global__ void k_cmax() {
    int idx = blockIdx.x * blockDim.x + threadIdx.x;
    if (idx >= BATCH * KC * CO) return;
    int c = idx % CO;
    int bk = idx / CO;
    int b = bk / KC;
    float a = g_AcBc[(size_t)bk * NCAT + c];
    float mn = CUDART_INF_F, mx = -CUDART_INF_F;
#pragma unroll
    for (int j = 0; j < KC; j++) {
        float xv = a + g_AcBc[(size_t)(b * KC + j) * NCAT + CO + c];
        mn = fminf(mn, xv);
        mx = fmaxf(mx, xv);
    }
    g_hc[idx] = gelu_max2(mn, mx);
}

// ---------------- aggregate: valley-extremes gelu-max over 9 neighbors ----------------
__global__ void k_aggregate() {
    int p = blockIdx.x;
    int b = p / NPIX;
    int lsk = g_ls[p];
    int dst = b * NPIX + g_order[p];
    __shared__ int nbrs[NBR];
    if (threadIdx.x < NBR) nbrs[threadIdx.x] = g_nbr[(size_t)p * NBR + threadIdx.x];
    __syncthreads();
    int c = threadIdx.x * 2;
    __nv_bfloat162 av = *(const __nv_bfloat162*)&g_ABh[(size_t)p * NCAT + c];
    float a0 = __bfloat162float(av.x), a1 = __bfloat162float(av.y);
    float2 hc2 = *(const float2*)&g_hc[((size_t)b * KC + lsk) * CO + c];
    float mn0 = CUDART_INF_F, mx0 = -CUDART_INF_F;
    float mn1 = CUDART_INF_F, mx1 = -CUDART_INF_F;
    int nb[NBR];
#pragma unroll
    for (int r = 0; r < NBR; r++) nb[r] = nbrs[r];
#pragma unroll
    for (int r = 0; r < NBR; r++) {
        __nv_bfloat162 bv = *(const __nv_bfloat162*)&g_ABh[(size_t)nb[r] * NCAT + CO + c];
        float x0 = __bfloat162float(bv.x);
        float x1 = __bfloat162float(bv.y);
        mn0 = fminf(mn0, x0); mx0 = fmaxf(mx0, x0);
        mn1 = fminf(mn1, x1); mx1 = fmaxf(mx1, x1);
    }
    float m0 = gelu_max2(a0 + mn0, a0 + mx0);
    float m1 = gelu_max2(a1 + mn1, a1 + mx1);
    __nv_bfloat162 out;
    out.x = __float2bfloat16(m0 + hc2.x);
    out.y = __float2bfloat16(m1 + hc2.y);
    *(__nv_bfloat162*)&g_hnh[(size_t)dst * CO + c] = out;
}

// ---------------- launch (serial, single stream) ----------------
extern "C" void kernel_launch(void* const* d_in, const int* in_sizes, int n_in,
                              void* d_out, int out_size) {
    const float* x      = (const float*)d_in[0];
    const int*   labels = (const int*)  d_in[1];
    const float* cpe_w  = (const float*)d_in[2];
    const float* cpe_b  = (const float*)d_in[3];
    const float* fc1_w  = (const float*)d_in[4];
    const float* fc1_b  = (const float*)d_in[5];
    const float* nn_v_w = (const float*)d_in[6];
    const float* nn_v_b = (const float*)d_in[7];
    const float* nn_c_w = (const float*)d_in[8];
    const float* nn_c_b = (const float*)d_in[9];
    const float* fc2_w  = (const float*)d_in[10];
    const float* fc2_b  = (const float*)d_in[11];
    float* y = (float*)d_out;

    float *p_xa, *p_xf;
    __nv_bfloat16 *p_xth, *p_xtl, *p_xsh, *p_hnh, *p_Wvt, *p_W2t, *p_W1h, *p_W1l, *p_ABh;
    float *p_bcat;
    cudaGetSymbolAddress((void**)&p_xa,   g_xa);
    cudaGetSymbolAddress((void**)&p_xf,   g_xf);
    cudaGetSymbolAddress((void**)&p_bcat, g_bias_cat);
    cudaGetSymbolAddress((void**)&p_xth,  g_xt_hi);
    cudaGetSymbolAddress((void**)&p_xtl,  g_xt_lo);
    cudaGetSymbolAddress((void**)&p_xsh,  g_xsh);
    cudaGetSymbolAddress((void**)&p_hnh,  g_hnh);
    cudaGetSymbolAddress((void**)&p_Wvt,  g_Wvt);
    cudaGetSymbolAddress((void**)&p_W2t,  g_W2t);
    cudaGetSymbolAddress((void**)&p_W1h,  g_W1t_hi);
    cudaGetSymbolAddress((void**)&p_W1l,  g_W1t_lo);
    cudaGetSymbolAddress((void**)&p_ABh,  g_ABh);

    cudaFuncSetAttribute(k_pre,        cudaFuncAttributeMaxDynamicSharedMemorySize, PRE_SMEM);
    cudaFuncSetAttribute(k_hgemm3_db,  cudaFuncAttributeMaxDynamicSharedMemorySize, 61440);
    cudaFuncSetAttribute(k_gram_ab,    cudaFuncAttributeMaxDynamicSharedMemorySize, 66048);
    cudaFuncSetAttribute(k_hgemm_fc2<64>, cudaFuncAttributeMaxDynamicSharedMemorySize, 34048);

    // merged: dwconv + label sort + weight prep (all independent)
    k_pre<<<DW_BLOCKS + SP_BLOCKS, 256, PRE_SMEM>>>(x, cpe_w, cpe_b, labels,
                                                    nn_v_w, nn_c_w, fc2_w, fc1_w, nn_v_b, nn_c_b);
    k_transpose_cn<<<dim3(NPIX / 32, CH / 32, BATCH), dim3(32, 8)>>>(p_xa);

    // fc1 split-bf16 (contiguous rows, unsorted out)
    k_hgemm3_db<<<dim3(CH / 64, BN / 128), 256, 61440>>>(p_xth, p_xtl, p_W1h, p_W1l, fc1_b, p_xf);
    // gather into sorted order + norm (one pass)
    k_gather_norm<<<BN / 8, 256>>>();

    // merged: gram (768 blocks) + AB GEMM (1176 blocks)
    k_gram_ab<<<GRAM_BLOCKS + AB_BLOCKS, 256, 66048>>>(p_xsh, p_Wvt, p_bcat, p_ABh);

    // merged: sel (128) + centroid-MLP (128)
    k_selcen<<<2 * BATCH * KC, 256, CH * 4>>>();
    k_cmax<<<(BATCH * KC * CO + 255) / 256, 256>>>();

    k_aggregate<<<BN, CO / 2>>>();

    // fc2 fused: (25088,384)x(384,192) -> transpose + shortcut -> y
    k_hgemm_fc2<64><<<dim3(CH / 64, BN / 128), 256, 34048>>>(p_hnh, p_W2t, fc2_b, y, x);
}